// round 2
// baseline (speedup 1.0000x reference)
#include <cuda_runtime.h>
#include <cuda_bf16.h>

// Problem constants
//   B=16, N=32, D=512, H=4, SB=256, S=N*N=1024, DS=128
// Inputs (metadata order):
//   0 edges (16,1024,512) f32
//   1 bb_semantics_embedding (16,256,512) f32
//   2 global_attn_matrix (16,32,32) bool-ish
//   3 cross_attn_mask (16,1024,256) bool-ish
//   4..11  g_Wq,g_bq,g_Wk,g_bk,g_Wv,g_bv,g_Wo,g_bo
//   12..19 c_*
//   20 ff_W1(2048,512) 21 ff_b1 22 ff_W2(512,2048) 23 ff_b2
// Output: edges (16,1024,512) f32

// ---------------- static scratch (no allocations allowed) ----------------
__device__ float g_X [8388608];    // inorm output (B,S,D)
__device__ float g_Q [8388608];    // Q (B,S,D)
__device__ float g_K [8388608];    // K (B,S,D) or (B,SB,D)
__device__ float g_V [8388608];    // V
__device__ float g_AO[8388608];    // attention output pre-O-proj (B,S,D)
__device__ float g_S [67108864];   // scores (B,H,S,S) / cross scores / FFN hidden
__device__ unsigned char g_m8g[16384];    // global mask, flattened g (B,S)
__device__ unsigned char g_m8c[4194304];  // cross mask (B,S,SB)
__device__ int g_mtype[2];

// ---------------- mask dtype detection + conversion ----------------
// 0 = uint8 bool, 1 = int32, 2 = float32, 3 = bfloat16
__device__ int classify_bytes(const unsigned char* p) {
    bool big = false, bf16sig = false;
    int ones = 0;
    for (int i = 0; i < 256; i++) {
        unsigned char v = p[i];
        if (v > 1) big = true;
        if (v == 1) ones++;
        if (v == 0x3F && (i & 3) == 1) bf16sig = true;  // bf16 1.0 high byte at odd pos
    }
    if (big) return bf16sig ? 3 : 2;
    return (ones > 96) ? 0 : 1;   // p=0.7: bool ~179 ones, int32 ~45 ones in 256B
}

__global__ void detect_kernel(const unsigned char* gm, const unsigned char* cm) {
    if (threadIdx.x == 0) {
        g_mtype[0] = classify_bytes(gm);
        g_mtype[1] = classify_bytes(cm);
    }
}

__global__ void convert_mask_kernel(const void* src, unsigned char* dst, int n, int which) {
    int i = blockIdx.x * blockDim.x + threadIdx.x;
    if (i >= n) return;
    int t = g_mtype[which];
    unsigned char v;
    if (t == 0)      v = ((const unsigned char*)src)[i] != 0;
    else if (t == 1) v = ((const int*)src)[i] != 0;
    else if (t == 3) v = ((const unsigned short*)src)[i] != 0;
    else             v = ((const float*)src)[i] != 0.0f;
    dst[i] = v;
}

// ---------------- instance norm over D=512, one block per token ----------------
__global__ void inorm_kernel(const float* __restrict__ x, float* __restrict__ y) {
    const size_t base = (size_t)blockIdx.x * 512;
    const int tid = threadIdx.x;   // 128 threads
    float v[4];
    float s = 0.f, s2 = 0.f;
#pragma unroll
    for (int i = 0; i < 4; i++) {
        float a = x[base + tid + i * 128];
        v[i] = a; s += a; s2 += a * a;
    }
#pragma unroll
    for (int o = 16; o > 0; o >>= 1) {
        s  += __shfl_xor_sync(0xffffffffu, s,  o);
        s2 += __shfl_xor_sync(0xffffffffu, s2, o);
    }
    __shared__ float sh[8];
    int w = tid >> 5;
    if ((tid & 31) == 0) { sh[w] = s; sh[4 + w] = s2; }
    __syncthreads();
    s  = sh[0] + sh[1] + sh[2] + sh[3];
    s2 = sh[4] + sh[5] + sh[6] + sh[7];
    float mean = s * (1.f / 512.f);
    float var  = s2 * (1.f / 512.f) - mean * mean;
    float inv  = rsqrtf(var + 1e-5f);
#pragma unroll
    for (int i = 0; i < 4; i++)
        y[base + tid + i * 128] = (v[i] - mean) * inv;
}

// ---------------- generic SGEMM-NT: C = [res +] A(MxK) * W(NxK)^T + bias [, relu] ----
// Tiles 128x128x8, 256 threads, 8x8 per thread. M,N multiples of 128, K of 8.
template<int RELU, int HASRES>
__global__ void __launch_bounds__(256) gemm_nt_kernel(
    const float* __restrict__ A, int lda,
    const float* __restrict__ W, int ldw,
    const float* __restrict__ bias,
    const float* __restrict__ res,
    float* __restrict__ C, int ldc, int K)
{
    __shared__ float As[8][128];
    __shared__ float Bs[8][128];
    const int m0 = blockIdx.y * 128, n0 = blockIdx.x * 128;
    const int tid = threadIdx.x;
    const int tx = tid & 15, ty = tid >> 4;
    const int lrow = tid >> 1, lkq = (tid & 1) * 4;
    const float* Ap = A + (size_t)(m0 + lrow) * lda + lkq;
    const float* Wp = W + (size_t)(n0 + lrow) * ldw + lkq;
    float acc[8][8] = {};
    for (int k0 = 0; k0 < K; k0 += 8) {
        float4 av = *(const float4*)(Ap + k0);
        float4 wv = *(const float4*)(Wp + k0);
        __syncthreads();
        As[lkq + 0][lrow] = av.x; As[lkq + 1][lrow] = av.y;
        As[lkq + 2][lrow] = av.z; As[lkq + 3][lrow] = av.w;
        Bs[lkq + 0][lrow] = wv.x; Bs[lkq + 1][lrow] = wv.y;
        Bs[lkq + 2][lrow] = wv.z; Bs[lkq + 3][lrow] = wv.w;
        __syncthreads();
#pragma unroll
        for (int kk = 0; kk < 8; kk++) {
            float4 a0 = *(const float4*)&As[kk][ty * 8];
            float4 a1 = *(const float4*)&As[kk][ty * 8 + 4];
            float4 b0 = *(const float4*)&Bs[kk][tx * 8];
            float4 b1 = *(const float4*)&Bs[kk][tx * 8 + 4];
            float a[8] = {a0.x, a0.y, a0.z, a0.w, a1.x, a1.y, a1.z, a1.w};
            float b[8] = {b0.x, b0.y, b0.z, b0.w, b1.x, b1.y, b1.z, b1.w};
#pragma unroll
            for (int i = 0; i < 8; i++)
#pragma unroll
                for (int j = 0; j < 8; j++)
                    acc[i][j] += a[i] * b[j];
        }
    }
#pragma unroll
    for (int i = 0; i < 8; i++) {
        size_t row = (size_t)(m0 + ty * 8 + i);
#pragma unroll
        for (int j = 0; j < 8; j++) {
            int n = n0 + tx * 8 + j;
            float val = acc[i][j] + bias[n];
            if (HASRES) val += res[row * ldc + n];
            if (RELU)   val = fmaxf(val, 0.f);
            C[row * ldc + n] = val;
        }
    }
}

// ---------------- batched attention scores: S = mask ? (Qh Kh^T)/sqrt(128) : -1e9 ----
// grid: (Lk/128, 1024/128, B*H). MODE 0: global (outer product of g), MODE 1: cross.
template<int MODE>
__global__ void __launch_bounds__(256) attn_scores_kernel(
    const float* __restrict__ Q, const float* __restrict__ Kmat,
    const unsigned char* __restrict__ mask,
    float* __restrict__ Sout, int Lk, int kbstride)
{
    __shared__ float As[8][128];
    __shared__ float Bs[8][128];
    const int b = blockIdx.z >> 2, h = blockIdx.z & 3;
    const int m0 = blockIdx.y * 128, n0 = blockIdx.x * 128;
    const int tid = threadIdx.x;
    const int tx = tid & 15, ty = tid >> 4;
    const int lrow = tid >> 1, lkq = (tid & 1) * 4;
    const float* Qp = Q + (size_t)b * 524288 + (size_t)(m0 + lrow) * 512 + h * 128 + lkq;
    const float* Kp = Kmat + (size_t)b * kbstride + (size_t)(n0 + lrow) * 512 + h * 128 + lkq;
    float acc[8][8] = {};
    for (int k0 = 0; k0 < 128; k0 += 8) {
        float4 av = *(const float4*)(Qp + k0);
        float4 wv = *(const float4*)(Kp + k0);
        __syncthreads();
        As[lkq + 0][lrow] = av.x; As[lkq + 1][lrow] = av.y;
        As[lkq + 2][lrow] = av.z; As[lkq + 3][lrow] = av.w;
        Bs[lkq + 0][lrow] = wv.x; Bs[lkq + 1][lrow] = wv.y;
        Bs[lkq + 2][lrow] = wv.z; Bs[lkq + 3][lrow] = wv.w;
        __syncthreads();
#pragma unroll
        for (int kk = 0; kk < 8; kk++) {
            float4 a0 = *(const float4*)&As[kk][ty * 8];
            float4 a1 = *(const float4*)&As[kk][ty * 8 + 4];
            float4 b0 = *(const float4*)&Bs[kk][tx * 8];
            float4 b1 = *(const float4*)&Bs[kk][tx * 8 + 4];
            float a[8] = {a0.x, a0.y, a0.z, a0.w, a1.x, a1.y, a1.z, a1.w};
            float bb[8] = {b0.x, b0.y, b0.z, b0.w, b1.x, b1.y, b1.z, b1.w};
#pragma unroll
            for (int i = 0; i < 8; i++)
#pragma unroll
                for (int j = 0; j < 8; j++)
                    acc[i][j] += a[i] * bb[j];
        }
    }
    const float scale = 0.08838834764831845f;   // 1/sqrt(128)
    float* Sb = Sout + (size_t)blockIdx.z * 1024 * Lk;
#pragma unroll
    for (int i = 0; i < 8; i++) {
        int q = m0 + ty * 8 + i;
        unsigned char qok = (MODE == 0) ? mask[b * 1024 + q] : (unsigned char)1;
#pragma unroll
        for (int j = 0; j < 8; j++) {
            int kc = n0 + tx * 8 + j;
            bool ok;
            if (MODE == 0) ok = qok && mask[b * 1024 + kc];
            else           ok = mask[((size_t)(b * 1024 + q)) * 256 + kc] != 0;
            Sb[(size_t)q * Lk + kc] = ok ? acc[i][j] * scale : -1e9f;
        }
    }
}

// ---------------- row softmax, one block (128 thr) per row; PT = Lk/128 ----------
template<int PT>
__global__ void softmax_kernel(float* __restrict__ Sc) {
    float* p = Sc + (size_t)blockIdx.x * (PT * 128);
    const int tid = threadIdx.x;
    float v[PT];
    float mx = -3.4e38f;
#pragma unroll
    for (int i = 0; i < PT; i++) { v[i] = p[tid + i * 128]; mx = fmaxf(mx, v[i]); }
#pragma unroll
    for (int o = 16; o > 0; o >>= 1) mx = fmaxf(mx, __shfl_xor_sync(0xffffffffu, mx, o));
    __shared__ float shm[4], shs[4];
    if ((tid & 31) == 0) shm[tid >> 5] = mx;
    __syncthreads();
    mx = fmaxf(fmaxf(shm[0], shm[1]), fmaxf(shm[2], shm[3]));
    float s = 0.f;
#pragma unroll
    for (int i = 0; i < PT; i++) { v[i] = __expf(v[i] - mx); s += v[i]; }
#pragma unroll
    for (int o = 16; o > 0; o >>= 1) s += __shfl_xor_sync(0xffffffffu, s, o);
    if ((tid & 31) == 0) shs[tid >> 5] = s;
    __syncthreads();
    s = shs[0] + shs[1] + shs[2] + shs[3];
    float inv = 1.f / s;
#pragma unroll
    for (int i = 0; i < PT; i++) p[tid + i * 128] = v[i] * inv;
}

// ---------------- batched AV: O[b, q, h*128+n] = sum_k P[bh,q,k] * V[b,k,h*128+n] ----
// grid: (1, 1024/128, B*H). BN = 128 (full head dim).
__global__ void __launch_bounds__(256) attn_av_kernel(
    const float* __restrict__ P, const float* __restrict__ Vmat,
    float* __restrict__ O, int Lk, int vbstride)
{
    __shared__ float As[8][128];
    __shared__ float Bs[8][128];
    const int b = blockIdx.z >> 2, h = blockIdx.z & 3;
    const int m0 = blockIdx.y * 128;
    const int tid = threadIdx.x;
    const int tx = tid & 15, ty = tid >> 4;
    const int lrow = tid >> 1, lkq = (tid & 1) * 4;
    const int lkk = tid >> 5, lnq = (tid & 31) * 4;
    const float* Pp = P + ((size_t)blockIdx.z * 1024 + m0 + lrow) * Lk + lkq;
    const float* Vp = Vmat + (size_t)b * vbstride + h * 128 + (size_t)lkk * 512 + lnq;
    float acc[8][8] = {};
    for (int k0 = 0; k0 < Lk; k0 += 8) {
        float4 av = *(const float4*)(Pp + k0);
        float4 vv = *(const float4*)(Vp + (size_t)k0 * 512);
        __syncthreads();
        As[lkq + 0][lrow] = av.x; As[lkq + 1][lrow] = av.y;
        As[lkq + 2][lrow] = av.z; As[lkq + 3][lrow] = av.w;
        *(float4*)&Bs[lkk][lnq] = vv;
        __syncthreads();
#pragma unroll
        for (int kk = 0; kk < 8; kk++) {
            float4 a0 = *(const float4*)&As[kk][ty * 8];
            float4 a1 = *(const float4*)&As[kk][ty * 8 + 4];
            float4 b0 = *(const float4*)&Bs[kk][tx * 8];
            float4 b1 = *(const float4*)&Bs[kk][tx * 8 + 4];
            float a[8] = {a0.x, a0.y, a0.z, a0.w, a1.x, a1.y, a1.z, a1.w};
            float bb[8] = {b0.x, b0.y, b0.z, b0.w, b1.x, b1.y, b1.z, b1.w};
#pragma unroll
            for (int i = 0; i < 8; i++)
#pragma unroll
                for (int j = 0; j < 8; j++)
                    acc[i][j] += a[i] * bb[j];
        }
    }
#pragma unroll
    for (int i = 0; i < 8; i++)
#pragma unroll
        for (int j = 0; j < 8; j++)
            O[(size_t)b * 524288 + (size_t)(m0 + ty * 8 + i) * 512 + h * 128 + tx * 8 + j]
                = acc[i][j];
}

// ---------------- launch ----------------
extern "C" void kernel_launch(void* const* d_in, const int* in_sizes, int n_in,
                              void* d_out, int out_size) {
    const float* edges = (const float*)d_in[0];
    const float* bbse  = (const float*)d_in[1];
    const void*  gm    = d_in[2];
    const void*  cm    = d_in[3];
    const float* gWq = (const float*)d_in[4];  const float* gbq = (const float*)d_in[5];
    const float* gWk = (const float*)d_in[6];  const float* gbk = (const float*)d_in[7];
    const float* gWv = (const float*)d_in[8];  const float* gbv = (const float*)d_in[9];
    const float* gWo = (const float*)d_in[10]; const float* gbo = (const float*)d_in[11];
    const float* cWq = (const float*)d_in[12]; const float* cbq = (const float*)d_in[13];
    const float* cWk = (const float*)d_in[14]; const float* cbk = (const float*)d_in[15];
    const float* cWv = (const float*)d_in[16]; const float* cbv = (const float*)d_in[17];
    const float* cWo = (const float*)d_in[18]; const float* cbo = (const float*)d_in[19];
    const float* fW1 = (const float*)d_in[20]; const float* fb1 = (const float*)d_in[21];
    const float* fW2 = (const float*)d_in[22]; const float* fb2 = (const float*)d_in[23];
    float* out = (float*)d_out;

    float *X, *Q, *Kb, *V, *AO, *Sc;
    unsigned char *m8g, *m8c;
    cudaGetSymbolAddress((void**)&X,  g_X);
    cudaGetSymbolAddress((void**)&Q,  g_Q);
    cudaGetSymbolAddress((void**)&Kb, g_K);
    cudaGetSymbolAddress((void**)&V,  g_V);
    cudaGetSymbolAddress((void**)&AO, g_AO);
    cudaGetSymbolAddress((void**)&Sc, g_S);
    cudaGetSymbolAddress((void**)&m8g, g_m8g);
    cudaGetSymbolAddress((void**)&m8c, g_m8c);

    // masks -> canonical uint8
    detect_kernel<<<1, 32>>>((const unsigned char*)gm, (const unsigned char*)cm);
    convert_mask_kernel<<<64, 256>>>(gm, m8g, 16384, 0);
    convert_mask_kernel<<<16384, 256>>>(cm, m8c, 4194304, 1);

    const int M = 16384;  // B*S tokens

    // ---- 1. global edge-edge self-attention ----
    inorm_kernel<<<M, 128>>>(edges, X);
    gemm_nt_kernel<0, 0><<<dim3(4, 128), 256>>>(X, 512, gWq, 512, gbq, nullptr, Q,  512, 512);
    gemm_nt_kernel<0, 0><<<dim3(4, 128), 256>>>(X, 512, gWk, 512, gbk, nullptr, Kb, 512, 512);
    gemm_nt_kernel<0, 0><<<dim3(4, 128), 256>>>(X, 512, gWv, 512, gbv, nullptr, V,  512, 512);
    attn_scores_kernel<0><<<dim3(8, 8, 64), 256>>>(Q, Kb, m8g, Sc, 1024, 524288);
    softmax_kernel<8><<<65536, 128>>>(Sc);
    attn_av_kernel<<<dim3(1, 8, 64), 256>>>(Sc, V, AO, 1024, 524288);
    gemm_nt_kernel<0, 1><<<dim3(4, 128), 256>>>(AO, 512, gWo, 512, gbo, edges, out, 512, 512);

    // ---- 2. cross-attention from bb semantics ----
    inorm_kernel<<<M, 128>>>(out, X);
    gemm_nt_kernel<0, 0><<<dim3(4, 128), 256>>>(X,    512, cWq, 512, cbq, nullptr, Q,  512, 512);
    gemm_nt_kernel<0, 0><<<dim3(4, 32),  256>>>(bbse, 512, cWk, 512, cbk, nullptr, Kb, 512, 512);
    gemm_nt_kernel<0, 0><<<dim3(4, 32),  256>>>(bbse, 512, cWv, 512, cbv, nullptr, V,  512, 512);
    attn_scores_kernel<1><<<dim3(2, 8, 64), 256>>>(Q, Kb, m8c, Sc, 256, 131072);
    softmax_kernel<2><<<65536, 128>>>(Sc);
    attn_av_kernel<<<dim3(1, 8, 64), 256>>>(Sc, V, AO, 256, 131072);
    gemm_nt_kernel<0, 1><<<dim3(4, 128), 256>>>(AO, 512, cWo, 512, cbo, out, out, 512, 512);

    // ---- 3. FFN ----
    inorm_kernel<<<M, 128>>>(out, X);
    gemm_nt_kernel<1, 0><<<dim3(16, 128), 256>>>(X,  512,  fW1, 512,  fb1, nullptr, Sc,  2048, 512);
    gemm_nt_kernel<0, 1><<<dim3(4, 128),  256>>>(Sc, 2048, fW2, 2048, fb2, out,     out, 512,  2048);
}

// round 3
// speedup vs baseline: 1.0006x; 1.0006x over previous
#include <cuda_runtime.h>
#include <cuda_bf16.h>

// Problem constants
//   B=16, N=32, D=512, H=4, SB=256, S=N*N=1024, DS=128
// Inputs (metadata order):
//   0 edges (16,1024,512) f32
//   1 bb_semantics_embedding (16,256,512) f32
//   2 global_attn_matrix (16,32,32) bool-ish
//   3 cross_attn_mask (16,1024,256) bool-ish
//   4..11  g_Wq,g_bq,g_Wk,g_bk,g_Wv,g_bv,g_Wo,g_bo
//   12..19 c_*
//   20 ff_W1(2048,512) 21 ff_b1 22 ff_W2(512,2048) 23 ff_b2
// Output: edges (16,1024,512) f32

// ---------------- static scratch (no allocations allowed) ----------------
__device__ float g_X [8388608];    // inorm output (B,S,D)
__device__ float g_Q [8388608];    // Q (B,S,D)
__device__ float g_K [8388608];    // K (B,S,D) or (B,SB,D)
__device__ float g_V [8388608];    // V
__device__ float g_AO[8388608];    // attention output pre-O-proj (B,S,D)
__device__ float g_S [67108864];   // scores (B,H,S,S) / cross scores / FFN hidden
__device__ unsigned char g_m8g[16384];    // global mask, flattened g (B,S)
__device__ unsigned char g_m8c[4194304];  // cross mask (B,S,SB)
__device__ int g_mtype[2];

// ---------------- mask dtype detection + conversion ----------------
// 0 = uint8 bool, 1 = int32, 2 = float32, 3 = bfloat16
__device__ int classify_bytes(const unsigned char* p) {
    bool big = false, bf16sig = false;
    int ones = 0;
    for (int i = 0; i < 256; i++) {
        unsigned char v = p[i];
        if (v > 1) big = true;
        if (v == 1) ones++;
        if (v == 0x3F && (i & 3) == 1) bf16sig = true;  // bf16 1.0 high byte at odd pos
    }
    if (big) return bf16sig ? 3 : 2;
    return (ones > 96) ? 0 : 1;   // p=0.7: bool ~179 ones, int32 ~45 ones in 256B
}

__global__ void detect_kernel(const unsigned char* gm, const unsigned char* cm) {
    if (threadIdx.x == 0) {
        g_mtype[0] = classify_bytes(gm);
        g_mtype[1] = classify_bytes(cm);
    }
}

__global__ void convert_mask_kernel(const void* src, unsigned char* dst, int n, int which) {
    int i = blockIdx.x * blockDim.x + threadIdx.x;
    if (i >= n) return;
    int t = g_mtype[which];
    unsigned char v;
    if (t == 0)      v = ((const unsigned char*)src)[i] != 0;
    else if (t == 1) v = ((const int*)src)[i] != 0;
    else if (t == 3) v = ((const unsigned short*)src)[i] != 0;
    else             v = ((const float*)src)[i] != 0.0f;
    dst[i] = v;
}

// ---------------- instance norm over D=512, one block per token ----------------
__global__ void inorm_kernel(const float* __restrict__ x, float* __restrict__ y) {
    const size_t base = (size_t)blockIdx.x * 512;
    const int tid = threadIdx.x;   // 128 threads
    float v[4];
    float s = 0.f, s2 = 0.f;
#pragma unroll
    for (int i = 0; i < 4; i++) {
        float a = x[base + tid + i * 128];
        v[i] = a; s += a; s2 += a * a;
    }
#pragma unroll
    for (int o = 16; o > 0; o >>= 1) {
        s  += __shfl_xor_sync(0xffffffffu, s,  o);
        s2 += __shfl_xor_sync(0xffffffffu, s2, o);
    }
    __shared__ float sh[8];
    int w = tid >> 5;
    if ((tid & 31) == 0) { sh[w] = s; sh[4 + w] = s2; }
    __syncthreads();
    s  = sh[0] + sh[1] + sh[2] + sh[3];
    s2 = sh[4] + sh[5] + sh[6] + sh[7];
    float mean = s * (1.f / 512.f);
    float var  = s2 * (1.f / 512.f) - mean * mean;
    float inv  = rsqrtf(var + 1e-5f);
#pragma unroll
    for (int i = 0; i < 4; i++)
        y[base + tid + i * 128] = (v[i] - mean) * inv;
}

// ---------------- generic SGEMM-NT: C = [res +] A(MxK) * W(NxK)^T + bias [, relu] ----
// Tiles 128x128x8, 256 threads, 8x8 per thread. M,N multiples of 128, K of 8.
template<int RELU, int HASRES>
__global__ void __launch_bounds__(256) gemm_nt_kernel(
    const float* __restrict__ A, int lda,
    const float* __restrict__ W, int ldw,
    const float* __restrict__ bias,
    const float* __restrict__ res,
    float* __restrict__ C, int ldc, int K)
{
    __shared__ float As[8][128];
    __shared__ float Bs[8][128];
    const int m0 = blockIdx.y * 128, n0 = blockIdx.x * 128;
    const int tid = threadIdx.x;
    const int tx = tid & 15, ty = tid >> 4;
    const int lrow = tid >> 1, lkq = (tid & 1) * 4;
    const float* Ap = A + (size_t)(m0 + lrow) * lda + lkq;
    const float* Wp = W + (size_t)(n0 + lrow) * ldw + lkq;
    float acc[8][8] = {};
    for (int k0 = 0; k0 < K; k0 += 8) {
        float4 av = *(const float4*)(Ap + k0);
        float4 wv = *(const float4*)(Wp + k0);
        __syncthreads();
        As[lkq + 0][lrow] = av.x; As[lkq + 1][lrow] = av.y;
        As[lkq + 2][lrow] = av.z; As[lkq + 3][lrow] = av.w;
        Bs[lkq + 0][lrow] = wv.x; Bs[lkq + 1][lrow] = wv.y;
        Bs[lkq + 2][lrow] = wv.z; Bs[lkq + 3][lrow] = wv.w;
        __syncthreads();
#pragma unroll
        for (int kk = 0; kk < 8; kk++) {
            float4 a0 = *(const float4*)&As[kk][ty * 8];
            float4 a1 = *(const float4*)&As[kk][ty * 8 + 4];
            float4 b0 = *(const float4*)&Bs[kk][tx * 8];
            float4 b1 = *(const float4*)&Bs[kk][tx * 8 + 4];
            float a[8] = {a0.x, a0.y, a0.z, a0.w, a1.x, a1.y, a1.z, a1.w};
            float b[8] = {b0.x, b0.y, b0.z, b0.w, b1.x, b1.y, b1.z, b1.w};
#pragma unroll
            for (int i = 0; i < 8; i++)
#pragma unroll
                for (int j = 0; j < 8; j++)
                    acc[i][j] += a[i] * b[j];
        }
    }
#pragma unroll
    for (int i = 0; i < 8; i++) {
        size_t row = (size_t)(m0 + ty * 8 + i);
#pragma unroll
        for (int j = 0; j < 8; j++) {
            int n = n0 + tx * 8 + j;
            float val = acc[i][j] + bias[n];
            if (HASRES) val += res[row * ldc + n];
            if (RELU)   val = fmaxf(val, 0.f);
            C[row * ldc + n] = val;
        }
    }
}

// ---------------- batched attention scores: S = mask ? (Qh Kh^T)/sqrt(128) : -1e9 ----
// grid: (Lk/128, 1024/128, B*H). MODE 0: global (outer product of g), MODE 1: cross.
template<int MODE>
__global__ void __launch_bounds__(256) attn_scores_kernel(
    const float* __restrict__ Q, const float* __restrict__ Kmat,
    const unsigned char* __restrict__ mask,
    float* __restrict__ Sout, int Lk, int kbstride)
{
    __shared__ float As[8][128];
    __shared__ float Bs[8][128];
    const int b = blockIdx.z >> 2, h = blockIdx.z & 3;
    const int m0 = blockIdx.y * 128, n0 = blockIdx.x * 128;
    const int tid = threadIdx.x;
    const int tx = tid & 15, ty = tid >> 4;
    const int lrow = tid >> 1, lkq = (tid & 1) * 4;
    const float* Qp = Q + (size_t)b * 524288 + (size_t)(m0 + lrow) * 512 + h * 128 + lkq;
    const float* Kp = Kmat + (size_t)b * kbstride + (size_t)(n0 + lrow) * 512 + h * 128 + lkq;
    float acc[8][8] = {};
    for (int k0 = 0; k0 < 128; k0 += 8) {
        float4 av = *(const float4*)(Qp + k0);
        float4 wv = *(const float4*)(Kp + k0);
        __syncthreads();
        As[lkq + 0][lrow] = av.x; As[lkq + 1][lrow] = av.y;
        As[lkq + 2][lrow] = av.z; As[lkq + 3][lrow] = av.w;
        Bs[lkq + 0][lrow] = wv.x; Bs[lkq + 1][lrow] = wv.y;
        Bs[lkq + 2][lrow] = wv.z; Bs[lkq + 3][lrow] = wv.w;
        __syncthreads();
#pragma unroll
        for (int kk = 0; kk < 8; kk++) {
            float4 a0 = *(const float4*)&As[kk][ty * 8];
            float4 a1 = *(const float4*)&As[kk][ty * 8 + 4];
            float4 b0 = *(const float4*)&Bs[kk][tx * 8];
            float4 b1 = *(const float4*)&Bs[kk][tx * 8 + 4];
            float a[8] = {a0.x, a0.y, a0.z, a0.w, a1.x, a1.y, a1.z, a1.w};
            float bb[8] = {b0.x, b0.y, b0.z, b0.w, b1.x, b1.y, b1.z, b1.w};
#pragma unroll
            for (int i = 0; i < 8; i++)
#pragma unroll
                for (int j = 0; j < 8; j++)
                    acc[i][j] += a[i] * bb[j];
        }
    }
    const float scale = 0.08838834764831845f;   // 1/sqrt(128)
    float* Sb = Sout + (size_t)blockIdx.z * 1024 * Lk;
#pragma unroll
    for (int i = 0; i < 8; i++) {
        int q = m0 + ty * 8 + i;
        unsigned char qok = (MODE == 0) ? mask[b * 1024 + q] : (unsigned char)1;
#pragma unroll
        for (int j = 0; j < 8; j++) {
            int kc = n0 + tx * 8 + j;
            bool ok;
            if (MODE == 0) ok = qok && mask[b * 1024 + kc];
            else           ok = mask[((size_t)(b * 1024 + q)) * 256 + kc] != 0;
            Sb[(size_t)q * Lk + kc] = ok ? acc[i][j] * scale : -1e9f;
        }
    }
}

// ---------------- row softmax, one block (128 thr) per row; PT = Lk/128 ----------
template<int PT>
__global__ void softmax_kernel(float* __restrict__ Sc) {
    float* p = Sc + (size_t)blockIdx.x * (PT * 128);
    const int tid = threadIdx.x;
    float v[PT];
    float mx = -3.4e38f;
#pragma unroll
    for (int i = 0; i < PT; i++) { v[i] = p[tid + i * 128]; mx = fmaxf(mx, v[i]); }
#pragma unroll
    for (int o = 16; o > 0; o >>= 1) mx = fmaxf(mx, __shfl_xor_sync(0xffffffffu, mx, o));
    __shared__ float shm[4], shs[4];
    if ((tid & 31) == 0) shm[tid >> 5] = mx;
    __syncthreads();
    mx = fmaxf(fmaxf(shm[0], shm[1]), fmaxf(shm[2], shm[3]));
    float s = 0.f;
#pragma unroll
    for (int i = 0; i < PT; i++) { v[i] = __expf(v[i] - mx); s += v[i]; }
#pragma unroll
    for (int o = 16; o > 0; o >>= 1) s += __shfl_xor_sync(0xffffffffu, s, o);
    if ((tid & 31) == 0) shs[tid >> 5] = s;
    __syncthreads();
    s = shs[0] + shs[1] + shs[2] + shs[3];
    float inv = 1.f / s;
#pragma unroll
    for (int i = 0; i < PT; i++) p[tid + i * 128] = v[i] * inv;
}

// ---------------- batched AV: O[b, q, h*128+n] = sum_k P[bh,q,k] * V[b,k,h*128+n] ----
// grid: (1, 1024/128, B*H). BN = 128 (full head dim).
__global__ void __launch_bounds__(256) attn_av_kernel(
    const float* __restrict__ P, const float* __restrict__ Vmat,
    float* __restrict__ O, int Lk, int vbstride)
{
    __shared__ float As[8][128];
    __shared__ float Bs[8][128];
    const int b = blockIdx.z >> 2, h = blockIdx.z & 3;
    const int m0 = blockIdx.y * 128;
    const int tid = threadIdx.x;
    const int tx = tid & 15, ty = tid >> 4;
    const int lrow = tid >> 1, lkq = (tid & 1) * 4;
    const int lkk = tid >> 5, lnq = (tid & 31) * 4;
    const float* Pp = P + ((size_t)blockIdx.z * 1024 + m0 + lrow) * Lk + lkq;
    const float* Vp = Vmat + (size_t)b * vbstride + h * 128 + (size_t)lkk * 512 + lnq;
    float acc[8][8] = {};
    for (int k0 = 0; k0 < Lk; k0 += 8) {
        float4 av = *(const float4*)(Pp + k0);
        float4 vv = *(const float4*)(Vp + (size_t)k0 * 512);
        __syncthreads();
        As[lkq + 0][lrow] = av.x; As[lkq + 1][lrow] = av.y;
        As[lkq + 2][lrow] = av.z; As[lkq + 3][lrow] = av.w;
        *(float4*)&Bs[lkk][lnq] = vv;
        __syncthreads();
#pragma unroll
        for (int kk = 0; kk < 8; kk++) {
            float4 a0 = *(const float4*)&As[kk][ty * 8];
            float4 a1 = *(const float4*)&As[kk][ty * 8 + 4];
            float4 b0 = *(const float4*)&Bs[kk][tx * 8];
            float4 b1 = *(const float4*)&Bs[kk][tx * 8 + 4];
            float a[8] = {a0.x, a0.y, a0.z, a0.w, a1.x, a1.y, a1.z, a1.w};
            float bb[8] = {b0.x, b0.y, b0.z, b0.w, b1.x, b1.y, b1.z, b1.w};
#pragma unroll
            for (int i = 0; i < 8; i++)
#pragma unroll
                for (int j = 0; j < 8; j++)
                    acc[i][j] += a[i] * bb[j];
        }
    }
#pragma unroll
    for (int i = 0; i < 8; i++)
#pragma unroll
        for (int j = 0; j < 8; j++)
            O[(size_t)b * 524288 + (size_t)(m0 + ty * 8 + i) * 512 + h * 128 + tx * 8 + j]
                = acc[i][j];
}

// ---------------- launch ----------------
extern "C" void kernel_launch(void* const* d_in, const int* in_sizes, int n_in,
                              void* d_out, int out_size) {
    const float* edges = (const float*)d_in[0];
    const float* bbse  = (const float*)d_in[1];
    const void*  gm    = d_in[2];
    const void*  cm    = d_in[3];
    const float* gWq = (const float*)d_in[4];  const float* gbq = (const float*)d_in[5];
    const float* gWk = (const float*)d_in[6];  const float* gbk = (const float*)d_in[7];
    const float* gWv = (const float*)d_in[8];  const float* gbv = (const float*)d_in[9];
    const float* gWo = (const float*)d_in[10]; const float* gbo = (const float*)d_in[11];
    const float* cWq = (const float*)d_in[12]; const float* cbq = (const float*)d_in[13];
    const float* cWk = (const float*)d_in[14]; const float* cbk = (const float*)d_in[15];
    const float* cWv = (const float*)d_in[16]; const float* cbv = (const float*)d_in[17];
    const float* cWo = (const float*)d_in[18]; const float* cbo = (const float*)d_in[19];
    const float* fW1 = (const float*)d_in[20]; const float* fb1 = (const float*)d_in[21];
    const float* fW2 = (const float*)d_in[22]; const float* fb2 = (const float*)d_in[23];
    float* out = (float*)d_out;

    float *X, *Q, *Kb, *V, *AO, *Sc;
    unsigned char *m8g, *m8c;
    cudaGetSymbolAddress((void**)&X,  g_X);
    cudaGetSymbolAddress((void**)&Q,  g_Q);
    cudaGetSymbolAddress((void**)&Kb, g_K);
    cudaGetSymbolAddress((void**)&V,  g_V);
    cudaGetSymbolAddress((void**)&AO, g_AO);
    cudaGetSymbolAddress((void**)&Sc, g_S);
    cudaGetSymbolAddress((void**)&m8g, g_m8g);
    cudaGetSymbolAddress((void**)&m8c, g_m8c);

    // masks -> canonical uint8
    detect_kernel<<<1, 32>>>((const unsigned char*)gm, (const unsigned char*)cm);
    convert_mask_kernel<<<64, 256>>>(gm, m8g, 16384, 0);
    convert_mask_kernel<<<16384, 256>>>(cm, m8c, 4194304, 1);

    const int M = 16384;  // B*S tokens

    // ---- 1. global edge-edge self-attention ----
    inorm_kernel<<<M, 128>>>(edges, X);
    gemm_nt_kernel<0, 0><<<dim3(4, 128), 256>>>(X, 512, gWq, 512, gbq, nullptr, Q,  512, 512);
    gemm_nt_kernel<0, 0><<<dim3(4, 128), 256>>>(X, 512, gWk, 512, gbk, nullptr, Kb, 512, 512);
    gemm_nt_kernel<0, 0><<<dim3(4, 128), 256>>>(X, 512, gWv, 512, gbv, nullptr, V,  512, 512);
    attn_scores_kernel<0><<<dim3(8, 8, 64), 256>>>(Q, Kb, m8g, Sc, 1024, 524288);
    softmax_kernel<8><<<65536, 128>>>(Sc);
    attn_av_kernel<<<dim3(1, 8, 64), 256>>>(Sc, V, AO, 1024, 524288);
    gemm_nt_kernel<0, 1><<<dim3(4, 128), 256>>>(AO, 512, gWo, 512, gbo, edges, out, 512, 512);

    // ---- 2. cross-attention from bb semantics ----
    inorm_kernel<<<M, 128>>>(out, X);
    gemm_nt_kernel<0, 0><<<dim3(4, 128), 256>>>(X,    512, cWq, 512, cbq, nullptr, Q,  512, 512);
    gemm_nt_kernel<0, 0><<<dim3(4, 32),  256>>>(bbse, 512, cWk, 512, cbk, nullptr, Kb, 512, 512);
    gemm_nt_kernel<0, 0><<<dim3(4, 32),  256>>>(bbse, 512, cWv, 512, cbv, nullptr, V,  512, 512);
    attn_scores_kernel<1><<<dim3(2, 8, 64), 256>>>(Q, Kb, m8c, Sc, 256, 131072);
    softmax_kernel<2><<<65536, 128>>>(Sc);
    attn_av_kernel<<<dim3(1, 8, 64), 256>>>(Sc, V, AO, 256, 131072);
    gemm_nt_kernel<0, 1><<<dim3(4, 128), 256>>>(AO, 512, cWo, 512, cbo, out, out, 512, 512);

    // ---- 3. FFN ----
    inorm_kernel<<<M, 128>>>(out, X);
    gemm_nt_kernel<1, 0><<<dim3(16, 128), 256>>>(X,  512,  fW1, 512,  fb1, nullptr, Sc,  2048, 512);
    gemm_nt_kernel<0, 1><<<dim3(4, 128),  256>>>(Sc, 2048, fW2, 2048, fb2, out,     out, 512,  2048);
}

// round 4
// speedup vs baseline: 1.0026x; 1.0021x over previous
#include <cuda_runtime.h>
#include <cuda_bf16.h>

// Problem constants
//   B=16, N=32, D=512, H=4, SB=256, S=N*N=1024, DS=128
// Inputs (metadata order):
//   0 edges (16,1024,512) f32
//   1 bb_semantics_embedding (16,256,512) f32
//   2 global_attn_matrix (16,32,32) bool-ish
//   3 cross_attn_mask (16,1024,256) bool-ish
//   4..11  g_Wq,g_bq,g_Wk,g_bk,g_Wv,g_bv,g_Wo,g_bo
//   12..19 c_*
//   20 ff_W1(2048,512) 21 ff_b1 22 ff_W2(512,2048) 23 ff_b2
// Output: edges (16,1024,512) f32

// ---------------- static scratch (no allocations allowed) ----------------
__device__ float g_X [8388608];    // inorm output (B,S,D)
__device__ float g_Q [8388608];    // Q (B,S,D)
__device__ float g_K [8388608];    // K (B,S,D) or (B,SB,D)
__device__ float g_V [8388608];    // V
__device__ float g_AO[8388608];    // attention output pre-O-proj (B,S,D)
__device__ float g_S [67108864];   // scores (B,H,S,S) / cross scores / FFN hidden
__device__ unsigned char g_m8g[16384];    // global mask, flattened g (B,S)
__device__ unsigned char g_m8c[4194304];  // cross mask (B,S,SB)
__device__ int g_mtype[2];

// ---------------- mask dtype detection + conversion ----------------
// 0 = uint8 bool, 1 = int32, 2 = float32, 3 = bfloat16
__device__ int classify_bytes(const unsigned char* p) {
    bool big = false, bf16sig = false;
    int ones = 0;
    for (int i = 0; i < 256; i++) {
        unsigned char v = p[i];
        if (v > 1) big = true;
        if (v == 1) ones++;
        if (v == 0x3F && (i & 3) == 1) bf16sig = true;  // bf16 1.0 high byte at odd pos
    }
    if (big) return bf16sig ? 3 : 2;
    return (ones > 96) ? 0 : 1;   // p=0.7: bool ~179 ones, int32 ~45 ones in 256B
}

__global__ void detect_kernel(const unsigned char* gm, const unsigned char* cm) {
    if (threadIdx.x == 0) {
        g_mtype[0] = classify_bytes(gm);
        g_mtype[1] = classify_bytes(cm);
    }
}

__global__ void convert_mask_kernel(const void* src, unsigned char* dst, int n, int which) {
    int i = blockIdx.x * blockDim.x + threadIdx.x;
    if (i >= n) return;
    int t = g_mtype[which];
    unsigned char v;
    if (t == 0)      v = ((const unsigned char*)src)[i] != 0;
    else if (t == 1) v = ((const int*)src)[i] != 0;
    else if (t == 3) v = ((const unsigned short*)src)[i] != 0;
    else             v = ((const float*)src)[i] != 0.0f;
    dst[i] = v;
}

// ---------------- instance norm over D=512, one block per token ----------------
__global__ void inorm_kernel(const float* __restrict__ x, float* __restrict__ y) {
    const size_t base = (size_t)blockIdx.x * 512;
    const int tid = threadIdx.x;   // 128 threads
    float v[4];
    float s = 0.f, s2 = 0.f;
#pragma unroll
    for (int i = 0; i < 4; i++) {
        float a = x[base + tid + i * 128];
        v[i] = a; s += a; s2 += a * a;
    }
#pragma unroll
    for (int o = 16; o > 0; o >>= 1) {
        s  += __shfl_xor_sync(0xffffffffu, s,  o);
        s2 += __shfl_xor_sync(0xffffffffu, s2, o);
    }
    __shared__ float sh[8];
    int w = tid >> 5;
    if ((tid & 31) == 0) { sh[w] = s; sh[4 + w] = s2; }
    __syncthreads();
    s  = sh[0] + sh[1] + sh[2] + sh[3];
    s2 = sh[4] + sh[5] + sh[6] + sh[7];
    float mean = s * (1.f / 512.f);
    float var  = s2 * (1.f / 512.f) - mean * mean;
    float inv  = rsqrtf(var + 1e-5f);
#pragma unroll
    for (int i = 0; i < 4; i++)
        y[base + tid + i * 128] = (v[i] - mean) * inv;
}

// ---------------- generic SGEMM-NT: C = [res +] A(MxK) * W(NxK)^T + bias [, relu] ----
// Tiles 128x128x8, 256 threads, 8x8 per thread. M,N multiples of 128, K of 8.
template<int RELU, int HASRES>
__global__ void __launch_bounds__(256) gemm_nt_kernel(
    const float* __restrict__ A, int lda,
    const float* __restrict__ W, int ldw,
    const float* __restrict__ bias,
    const float* __restrict__ res,
    float* __restrict__ C, int ldc, int K)
{
    __shared__ float As[8][128];
    __shared__ float Bs[8][128];
    const int m0 = blockIdx.y * 128, n0 = blockIdx.x * 128;
    const int tid = threadIdx.x;
    const int tx = tid & 15, ty = tid >> 4;
    const int lrow = tid >> 1, lkq = (tid & 1) * 4;
    const float* Ap = A + (size_t)(m0 + lrow) * lda + lkq;
    const float* Wp = W + (size_t)(n0 + lrow) * ldw + lkq;
    float acc[8][8] = {};
    for (int k0 = 0; k0 < K; k0 += 8) {
        float4 av = *(const float4*)(Ap + k0);
        float4 wv = *(const float4*)(Wp + k0);
        __syncthreads();
        As[lkq + 0][lrow] = av.x; As[lkq + 1][lrow] = av.y;
        As[lkq + 2][lrow] = av.z; As[lkq + 3][lrow] = av.w;
        Bs[lkq + 0][lrow] = wv.x; Bs[lkq + 1][lrow] = wv.y;
        Bs[lkq + 2][lrow] = wv.z; Bs[lkq + 3][lrow] = wv.w;
        __syncthreads();
#pragma unroll
        for (int kk = 0; kk < 8; kk++) {
            float4 a0 = *(const float4*)&As[kk][ty * 8];
            float4 a1 = *(const float4*)&As[kk][ty * 8 + 4];
            float4 b0 = *(const float4*)&Bs[kk][tx * 8];
            float4 b1 = *(const float4*)&Bs[kk][tx * 8 + 4];
            float a[8] = {a0.x, a0.y, a0.z, a0.w, a1.x, a1.y, a1.z, a1.w};
            float b[8] = {b0.x, b0.y, b0.z, b0.w, b1.x, b1.y, b1.z, b1.w};
#pragma unroll
            for (int i = 0; i < 8; i++)
#pragma unroll
                for (int j = 0; j < 8; j++)
                    acc[i][j] += a[i] * b[j];
        }
    }
#pragma unroll
    for (int i = 0; i < 8; i++) {
        size_t row = (size_t)(m0 + ty * 8 + i);
#pragma unroll
        for (int j = 0; j < 8; j++) {
            int n = n0 + tx * 8 + j;
            float val = acc[i][j] + bias[n];
            if (HASRES) val += res[row * ldc + n];
            if (RELU)   val = fmaxf(val, 0.f);
            C[row * ldc + n] = val;
        }
    }
}

// ---------------- batched attention scores: S = mask ? (Qh Kh^T)/sqrt(128) : -1e9 ----
// grid: (Lk/128, 1024/128, B*H). MODE 0: global (outer product of g), MODE 1: cross.
template<int MODE>
__global__ void __launch_bounds__(256) attn_scores_kernel(
    const float* __restrict__ Q, const float* __restrict__ Kmat,
    const unsigned char* __restrict__ mask,
    float* __restrict__ Sout, int Lk, int kbstride)
{
    __shared__ float As[8][128];
    __shared__ float Bs[8][128];
    const int b = blockIdx.z >> 2, h = blockIdx.z & 3;
    const int m0 = blockIdx.y * 128, n0 = blockIdx.x * 128;
    const int tid = threadIdx.x;
    const int tx = tid & 15, ty = tid >> 4;
    const int lrow = tid >> 1, lkq = (tid & 1) * 4;
    const float* Qp = Q + (size_t)b * 524288 + (size_t)(m0 + lrow) * 512 + h * 128 + lkq;
    const float* Kp = Kmat + (size_t)b * kbstride + (size_t)(n0 + lrow) * 512 + h * 128 + lkq;
    float acc[8][8] = {};
    for (int k0 = 0; k0 < 128; k0 += 8) {
        float4 av = *(const float4*)(Qp + k0);
        float4 wv = *(const float4*)(Kp + k0);
        __syncthreads();
        As[lkq + 0][lrow] = av.x; As[lkq + 1][lrow] = av.y;
        As[lkq + 2][lrow] = av.z; As[lkq + 3][lrow] = av.w;
        Bs[lkq + 0][lrow] = wv.x; Bs[lkq + 1][lrow] = wv.y;
        Bs[lkq + 2][lrow] = wv.z; Bs[lkq + 3][lrow] = wv.w;
        __syncthreads();
#pragma unroll
        for (int kk = 0; kk < 8; kk++) {
            float4 a0 = *(const float4*)&As[kk][ty * 8];
            float4 a1 = *(const float4*)&As[kk][ty * 8 + 4];
            float4 b0 = *(const float4*)&Bs[kk][tx * 8];
            float4 b1 = *(const float4*)&Bs[kk][tx * 8 + 4];
            float a[8] = {a0.x, a0.y, a0.z, a0.w, a1.x, a1.y, a1.z, a1.w};
            float bb[8] = {b0.x, b0.y, b0.z, b0.w, b1.x, b1.y, b1.z, b1.w};
#pragma unroll
            for (int i = 0; i < 8; i++)
#pragma unroll
                for (int j = 0; j < 8; j++)
                    acc[i][j] += a[i] * bb[j];
        }
    }
    const float scale = 0.08838834764831845f;   // 1/sqrt(128)
    float* Sb = Sout + (size_t)blockIdx.z * 1024 * Lk;
#pragma unroll
    for (int i = 0; i < 8; i++) {
        int q = m0 + ty * 8 + i;
        unsigned char qok = (MODE == 0) ? mask[b * 1024 + q] : (unsigned char)1;
#pragma unroll
        for (int j = 0; j < 8; j++) {
            int kc = n0 + tx * 8 + j;
            bool ok;
            if (MODE == 0) ok = qok && mask[b * 1024 + kc];
            else           ok = mask[((size_t)(b * 1024 + q)) * 256 + kc] != 0;
            Sb[(size_t)q * Lk + kc] = ok ? acc[i][j] * scale : -1e9f;
        }
    }
}

// ---------------- row softmax, one block (128 thr) per row; PT = Lk/128 ----------
template<int PT>
__global__ void softmax_kernel(float* __restrict__ Sc) {
    float* p = Sc + (size_t)blockIdx.x * (PT * 128);
    const int tid = threadIdx.x;
    float v[PT];
    float mx = -3.4e38f;
#pragma unroll
    for (int i = 0; i < PT; i++) { v[i] = p[tid + i * 128]; mx = fmaxf(mx, v[i]); }
#pragma unroll
    for (int o = 16; o > 0; o >>= 1) mx = fmaxf(mx, __shfl_xor_sync(0xffffffffu, mx, o));
    __shared__ float shm[4], shs[4];
    if ((tid & 31) == 0) shm[tid >> 5] = mx;
    __syncthreads();
    mx = fmaxf(fmaxf(shm[0], shm[1]), fmaxf(shm[2], shm[3]));
    float s = 0.f;
#pragma unroll
    for (int i = 0; i < PT; i++) { v[i] = __expf(v[i] - mx); s += v[i]; }
#pragma unroll
    for (int o = 16; o > 0; o >>= 1) s += __shfl_xor_sync(0xffffffffu, s, o);
    if ((tid & 31) == 0) shs[tid >> 5] = s;
    __syncthreads();
    s = shs[0] + shs[1] + shs[2] + shs[3];
    float inv = 1.f / s;
#pragma unroll
    for (int i = 0; i < PT; i++) p[tid + i * 128] = v[i] * inv;
}

// ---------------- batched AV: O[b, q, h*128+n] = sum_k P[bh,q,k] * V[b,k,h*128+n] ----
// grid: (1, 1024/128, B*H). BN = 128 (full head dim).
__global__ void __launch_bounds__(256) attn_av_kernel(
    const float* __restrict__ P, const float* __restrict__ Vmat,
    float* __restrict__ O, int Lk, int vbstride)
{
    __shared__ float As[8][128];
    __shared__ float Bs[8][128];
    const int b = blockIdx.z >> 2, h = blockIdx.z & 3;
    const int m0 = blockIdx.y * 128;
    const int tid = threadIdx.x;
    const int tx = tid & 15, ty = tid >> 4;
    const int lrow = tid >> 1, lkq = (tid & 1) * 4;
    const int lkk = tid >> 5, lnq = (tid & 31) * 4;
    const float* Pp = P + ((size_t)blockIdx.z * 1024 + m0 + lrow) * Lk + lkq;
    const float* Vp = Vmat + (size_t)b * vbstride + h * 128 + (size_t)lkk * 512 + lnq;
    float acc[8][8] = {};
    for (int k0 = 0; k0 < Lk; k0 += 8) {
        float4 av = *(const float4*)(Pp + k0);
        float4 vv = *(const float4*)(Vp + (size_t)k0 * 512);
        __syncthreads();
        As[lkq + 0][lrow] = av.x; As[lkq + 1][lrow] = av.y;
        As[lkq + 2][lrow] = av.z; As[lkq + 3][lrow] = av.w;
        *(float4*)&Bs[lkk][lnq] = vv;
        __syncthreads();
#pragma unroll
        for (int kk = 0; kk < 8; kk++) {
            float4 a0 = *(const float4*)&As[kk][ty * 8];
            float4 a1 = *(const float4*)&As[kk][ty * 8 + 4];
            float4 b0 = *(const float4*)&Bs[kk][tx * 8];
            float4 b1 = *(const float4*)&Bs[kk][tx * 8 + 4];
            float a[8] = {a0.x, a0.y, a0.z, a0.w, a1.x, a1.y, a1.z, a1.w};
            float bb[8] = {b0.x, b0.y, b0.z, b0.w, b1.x, b1.y, b1.z, b1.w};
#pragma unroll
            for (int i = 0; i < 8; i++)
#pragma unroll
                for (int j = 0; j < 8; j++)
                    acc[i][j] += a[i] * bb[j];
        }
    }
#pragma unroll
    for (int i = 0; i < 8; i++)
#pragma unroll
        for (int j = 0; j < 8; j++)
            O[(size_t)b * 524288 + (size_t)(m0 + ty * 8 + i) * 512 + h * 128 + tx * 8 + j]
                = acc[i][j];
}

// ---------------- launch ----------------
extern "C" void kernel_launch(void* const* d_in, const int* in_sizes, int n_in,
                              void* d_out, int out_size) {
    const float* edges = (const float*)d_in[0];
    const float* bbse  = (const float*)d_in[1];
    const void*  gm    = d_in[2];
    const void*  cm    = d_in[3];
    const float* gWq = (const float*)d_in[4];  const float* gbq = (const float*)d_in[5];
    const float* gWk = (const float*)d_in[6];  const float* gbk = (const float*)d_in[7];
    const float* gWv = (const float*)d_in[8];  const float* gbv = (const float*)d_in[9];
    const float* gWo = (const float*)d_in[10]; const float* gbo = (const float*)d_in[11];
    const float* cWq = (const float*)d_in[12]; const float* cbq = (const float*)d_in[13];
    const float* cWk = (const float*)d_in[14]; const float* cbk = (const float*)d_in[15];
    const float* cWv = (const float*)d_in[16]; const float* cbv = (const float*)d_in[17];
    const float* cWo = (const float*)d_in[18]; const float* cbo = (const float*)d_in[19];
    const float* fW1 = (const float*)d_in[20]; const float* fb1 = (const float*)d_in[21];
    const float* fW2 = (const float*)d_in[22]; const float* fb2 = (const float*)d_in[23];
    float* out = (float*)d_out;

    float *X, *Q, *Kb, *V, *AO, *Sc;
    unsigned char *m8g, *m8c;
    cudaGetSymbolAddress((void**)&X,  g_X);
    cudaGetSymbolAddress((void**)&Q,  g_Q);
    cudaGetSymbolAddress((void**)&Kb, g_K);
    cudaGetSymbolAddress((void**)&V,  g_V);
    cudaGetSymbolAddress((void**)&AO, g_AO);
    cudaGetSymbolAddress((void**)&Sc, g_S);
    cudaGetSymbolAddress((void**)&m8g, g_m8g);
    cudaGetSymbolAddress((void**)&m8c, g_m8c);

    // masks -> canonical uint8
    detect_kernel<<<1, 32>>>((const unsigned char*)gm, (const unsigned char*)cm);
    convert_mask_kernel<<<64, 256>>>(gm, m8g, 16384, 0);
    convert_mask_kernel<<<16384, 256>>>(cm, m8c, 4194304, 1);

    const int M = 16384;  // B*S tokens

    // ---- 1. global edge-edge self-attention ----
    inorm_kernel<<<M, 128>>>(edges, X);
    gemm_nt_kernel<0, 0><<<dim3(4, 128), 256>>>(X, 512, gWq, 512, gbq, nullptr, Q,  512, 512);
    gemm_nt_kernel<0, 0><<<dim3(4, 128), 256>>>(X, 512, gWk, 512, gbk, nullptr, Kb, 512, 512);
    gemm_nt_kernel<0, 0><<<dim3(4, 128), 256>>>(X, 512, gWv, 512, gbv, nullptr, V,  512, 512);
    attn_scores_kernel<0><<<dim3(8, 8, 64), 256>>>(Q, Kb, m8g, Sc, 1024, 524288);
    softmax_kernel<8><<<65536, 128>>>(Sc);
    attn_av_kernel<<<dim3(1, 8, 64), 256>>>(Sc, V, AO, 1024, 524288);
    gemm_nt_kernel<0, 1><<<dim3(4, 128), 256>>>(AO, 512, gWo, 512, gbo, edges, out, 512, 512);

    // ---- 2. cross-attention from bb semantics ----
    inorm_kernel<<<M, 128>>>(out, X);
    gemm_nt_kernel<0, 0><<<dim3(4, 128), 256>>>(X,    512, cWq, 512, cbq, nullptr, Q,  512, 512);
    gemm_nt_kernel<0, 0><<<dim3(4, 32),  256>>>(bbse, 512, cWk, 512, cbk, nullptr, Kb, 512, 512);
    gemm_nt_kernel<0, 0><<<dim3(4, 32),  256>>>(bbse, 512, cWv, 512, cbv, nullptr, V,  512, 512);
    attn_scores_kernel<1><<<dim3(2, 8, 64), 256>>>(Q, Kb, m8c, Sc, 256, 131072);
    softmax_kernel<2><<<65536, 128>>>(Sc);
    attn_av_kernel<<<dim3(1, 8, 64), 256>>>(Sc, V, AO, 256, 131072);
    gemm_nt_kernel<0, 1><<<dim3(4, 128), 256>>>(AO, 512, cWo, 512, cbo, out, out, 512, 512);

    // ---- 3. FFN ----
    inorm_kernel<<<M, 128>>>(out, X);
    gemm_nt_kernel<1, 0><<<dim3(16, 128), 256>>>(X,  512,  fW1, 512,  fb1, nullptr, Sc,  2048, 512);
    gemm_nt_kernel<0, 1><<<dim3(4, 128),  256>>>(Sc, 2048, fW2, 2048, fb2, out,     out, 512,  2048);
}

// round 5
// speedup vs baseline: 2.2819x; 2.2759x over previous
#include <cuda_runtime.h>
#include <cuda_bf16.h>

// Problem constants
//   B=16, N=32, D=512, H=4, SB=256, S=N*N=1024, DS=128
// Output: edges (16,1024,512) f32

// ---------------- static scratch (no allocations allowed) ----------------
__device__ float g_X [8388608];    // inorm output (B,S,D)
__device__ float g_Q [8388608];    // Q (B,S,D)
__device__ float g_K [8388608];    // K (B,S,D) or (B,SB,D)
__device__ float g_V [8388608];    // V
__device__ float g_AO[8388608];    // attention output pre-O-proj (B,S,D)
__device__ float g_S [67108864];   // scores (B,H,S,S) / cross scores / FFN hidden
__device__ unsigned char g_m8g[16384];    // global mask, flattened g (B,S)
__device__ unsigned char g_m8c[4194304];  // cross mask (B,S,SB)
__device__ int g_mtype[2];

// ---------------- mask dtype detection + conversion ----------------
// 0 = uint8 bool, 1 = int32, 2 = float32, 3 = bfloat16
__device__ int classify_bytes(const unsigned char* p) {
    bool big = false, bf16sig = false;
    int ones = 0;
    for (int i = 0; i < 256; i++) {
        unsigned char v = p[i];
        if (v > 1) big = true;
        if (v == 1) ones++;
        if (v == 0x3F && (i & 3) == 1) bf16sig = true;
    }
    if (big) return bf16sig ? 3 : 2;
    return (ones > 96) ? 0 : 1;
}

__global__ void detect_kernel(const unsigned char* gm, const unsigned char* cm) {
    if (threadIdx.x == 0) {
        g_mtype[0] = classify_bytes(gm);
        g_mtype[1] = classify_bytes(cm);
    }
}

__global__ void convert_mask_kernel(const void* src, unsigned char* dst, int n, int which) {
    int i = blockIdx.x * blockDim.x + threadIdx.x;
    if (i >= n) return;
    int t = g_mtype[which];
    unsigned char v;
    if (t == 0)      v = ((const unsigned char*)src)[i] != 0;
    else if (t == 1) v = ((const int*)src)[i] != 0;
    else if (t == 3) v = ((const unsigned short*)src)[i] != 0;
    else             v = ((const float*)src)[i] != 0.0f;
    dst[i] = v;
}

// ---------------- instance norm over D=512, one block per token ----------------
__global__ void inorm_kernel(const float* __restrict__ x, float* __restrict__ y) {
    const size_t base = (size_t)blockIdx.x * 512;
    const int tid = threadIdx.x;   // 128 threads
    float v[4];
    float s = 0.f, s2 = 0.f;
#pragma unroll
    for (int i = 0; i < 4; i++) {
        float a = x[base + tid + i * 128];
        v[i] = a; s += a; s2 += a * a;
    }
#pragma unroll
    for (int o = 16; o > 0; o >>= 1) {
        s  += __shfl_xor_sync(0xffffffffu, s,  o);
        s2 += __shfl_xor_sync(0xffffffffu, s2, o);
    }
    __shared__ float sh[8];
    int w = tid >> 5;
    if ((tid & 31) == 0) { sh[w] = s; sh[4 + w] = s2; }
    __syncthreads();
    s  = sh[0] + sh[1] + sh[2] + sh[3];
    s2 = sh[4] + sh[5] + sh[6] + sh[7];
    float mean = s * (1.f / 512.f);
    float var  = s2 * (1.f / 512.f) - mean * mean;
    float inv  = rsqrtf(var + 1e-5f);
#pragma unroll
    for (int i = 0; i < 4; i++)
        y[base + tid + i * 128] = (v[i] - mean) * inv;
}

// ---------------- tf32 mma helpers ----------------
__device__ __forceinline__ unsigned f2t(float x) {
    unsigned u;
    asm("cvt.rna.tf32.f32 %0, %1;" : "=r"(u) : "f"(x));
    return u;
}

__device__ __forceinline__ void mma8(float* c, const unsigned* a, const unsigned* b) {
    asm volatile(
        "mma.sync.aligned.m16n8k8.row.col.f32.tf32.tf32.f32 "
        "{%0,%1,%2,%3}, {%4,%5,%6,%7}, {%8,%9}, {%0,%1,%2,%3};"
        : "+f"(c[0]), "+f"(c[1]), "+f"(c[2]), "+f"(c[3])
        : "r"(a[0]), "r"(a[1]), "r"(a[2]), "r"(a[3]), "r"(b[0]), "r"(b[1]));
}

// ================= TF32 GEMM-NT: C = [res +] A(MxK) * W(NxK)^T + bias [, relu] ====
// Block 128x128x16, 256 thr = 8 warps (2m x 4n), warp tile 64x32.
// Smem tiles row-major [row][16 k + pad 4] -> conflict-free fragment loads.
template<int RELU, int HASRES>
__global__ void __launch_bounds__(256) gemm_tf32_nt(
    const float* __restrict__ A, int lda,
    const float* __restrict__ W, int ldw,
    const float* __restrict__ bias,
    const float* __restrict__ res,
    float* __restrict__ C, int ldc, int K)
{
    __shared__ __align__(16) unsigned As[2][128][20];
    __shared__ __align__(16) unsigned Bs[2][128][20];
    const int tid = threadIdx.x, lane = tid & 31, wid = tid >> 5;
    const int wm = (wid & 1) * 64, wn = (wid >> 1) * 32;
    const int m0 = blockIdx.y * 128, n0 = blockIdx.x * 128;
    const int r = tid >> 1, kq = (tid & 1) * 8;
    const float* Ap = A + (size_t)(m0 + r) * lda + kq;
    const float* Wp = W + (size_t)(n0 + r) * ldw + kq;

    float4 pa0 = *(const float4*)Ap, pa1 = *(const float4*)(Ap + 4);
    float4 pb0 = *(const float4*)Wp, pb1 = *(const float4*)(Wp + 4);
    *(uint4*)&As[0][r][kq]     = make_uint4(f2t(pa0.x), f2t(pa0.y), f2t(pa0.z), f2t(pa0.w));
    *(uint4*)&As[0][r][kq + 4] = make_uint4(f2t(pa1.x), f2t(pa1.y), f2t(pa1.z), f2t(pa1.w));
    *(uint4*)&Bs[0][r][kq]     = make_uint4(f2t(pb0.x), f2t(pb0.y), f2t(pb0.z), f2t(pb0.w));
    *(uint4*)&Bs[0][r][kq + 4] = make_uint4(f2t(pb1.x), f2t(pb1.y), f2t(pb1.z), f2t(pb1.w));

    float acc[4][4][4] = {};
    const int nt = K >> 4;
    int cur = 0;
    for (int kt = 0; kt < nt; kt++) {
        __syncthreads();
        if (kt + 1 < nt) {
            const float* A2 = Ap + (kt + 1) * 16;
            const float* W2 = Wp + (kt + 1) * 16;
            pa0 = *(const float4*)A2; pa1 = *(const float4*)(A2 + 4);
            pb0 = *(const float4*)W2; pb1 = *(const float4*)(W2 + 4);
        }
#pragma unroll
        for (int ks = 0; ks < 16; ks += 8) {
            unsigned af[4][4], bf[4][2];
            const int k = ks + (lane & 3);
#pragma unroll
            for (int mi = 0; mi < 4; mi++) {
                int m = wm + mi * 16 + (lane >> 2);
                af[mi][0] = As[cur][m][k];
                af[mi][1] = As[cur][m + 8][k];
                af[mi][2] = As[cur][m][k + 4];
                af[mi][3] = As[cur][m + 8][k + 4];
            }
#pragma unroll
            for (int ni = 0; ni < 4; ni++) {
                int n = wn + ni * 8 + (lane >> 2);
                bf[ni][0] = Bs[cur][n][k];
                bf[ni][1] = Bs[cur][n][k + 4];
            }
#pragma unroll
            for (int mi = 0; mi < 4; mi++)
#pragma unroll
                for (int ni = 0; ni < 4; ni++)
                    mma8(acc[mi][ni], af[mi], bf[ni]);
        }
        if (kt + 1 < nt) {
            int nx = cur ^ 1;
            *(uint4*)&As[nx][r][kq]     = make_uint4(f2t(pa0.x), f2t(pa0.y), f2t(pa0.z), f2t(pa0.w));
            *(uint4*)&As[nx][r][kq + 4] = make_uint4(f2t(pa1.x), f2t(pa1.y), f2t(pa1.z), f2t(pa1.w));
            *(uint4*)&Bs[nx][r][kq]     = make_uint4(f2t(pb0.x), f2t(pb0.y), f2t(pb0.z), f2t(pb0.w));
            *(uint4*)&Bs[nx][r][kq + 4] = make_uint4(f2t(pb1.x), f2t(pb1.y), f2t(pb1.z), f2t(pb1.w));
        }
        cur ^= 1;
    }

#pragma unroll
    for (int mi = 0; mi < 4; mi++)
#pragma unroll
        for (int ni = 0; ni < 4; ni++) {
            int row = m0 + wm + mi * 16 + (lane >> 2);
            int col = n0 + wn + ni * 8 + 2 * (lane & 3);
            float b0v = bias[col], b1v = bias[col + 1];
            float v0 = acc[mi][ni][0] + b0v, v1 = acc[mi][ni][1] + b1v;
            float v2 = acc[mi][ni][2] + b0v, v3 = acc[mi][ni][3] + b1v;
            if (HASRES) {
                float2 r0 = *(const float2*)&res[(size_t)row * ldc + col];
                float2 r1 = *(const float2*)&res[(size_t)(row + 8) * ldc + col];
                v0 += r0.x; v1 += r0.y; v2 += r1.x; v3 += r1.y;
            }
            if (RELU) {
                v0 = fmaxf(v0, 0.f); v1 = fmaxf(v1, 0.f);
                v2 = fmaxf(v2, 0.f); v3 = fmaxf(v3, 0.f);
            }
            float2 o0 = {v0, v1}, o1 = {v2, v3};
            *(float2*)&C[(size_t)row * ldc + col]       = o0;
            *(float2*)&C[(size_t)(row + 8) * ldc + col] = o1;
        }
}

// ================= TF32 attention scores: S = mask ? (Qh Kh^T)/sqrt(128) : -1e9 ====
// grid: (Lk/128, 8, B*H). MODE 0: global (outer product), MODE 1: cross.
template<int MODE>
__global__ void __launch_bounds__(256) scores_tf32(
    const float* __restrict__ Q, const float* __restrict__ Km,
    const unsigned char* __restrict__ mask,
    float* __restrict__ Sout, int Lk, int kbstride)
{
    __shared__ __align__(16) unsigned As[2][128][20];
    __shared__ __align__(16) unsigned Bs[2][128][20];
    const int tid = threadIdx.x, lane = tid & 31, wid = tid >> 5;
    const int wm = (wid & 1) * 64, wn = (wid >> 1) * 32;
    const int b = blockIdx.z >> 2, h = blockIdx.z & 3;
    const int m0 = blockIdx.y * 128, n0 = blockIdx.x * 128;
    const int r = tid >> 1, kq = (tid & 1) * 8;
    const float* Ap = Q  + (size_t)b * 524288  + (size_t)(m0 + r) * 512 + h * 128 + kq;
    const float* Wp = Km + (size_t)b * kbstride + (size_t)(n0 + r) * 512 + h * 128 + kq;

    float4 pa0 = *(const float4*)Ap, pa1 = *(const float4*)(Ap + 4);
    float4 pb0 = *(const float4*)Wp, pb1 = *(const float4*)(Wp + 4);
    *(uint4*)&As[0][r][kq]     = make_uint4(f2t(pa0.x), f2t(pa0.y), f2t(pa0.z), f2t(pa0.w));
    *(uint4*)&As[0][r][kq + 4] = make_uint4(f2t(pa1.x), f2t(pa1.y), f2t(pa1.z), f2t(pa1.w));
    *(uint4*)&Bs[0][r][kq]     = make_uint4(f2t(pb0.x), f2t(pb0.y), f2t(pb0.z), f2t(pb0.w));
    *(uint4*)&Bs[0][r][kq + 4] = make_uint4(f2t(pb1.x), f2t(pb1.y), f2t(pb1.z), f2t(pb1.w));

    float acc[4][4][4] = {};
    int cur = 0;
    for (int kt = 0; kt < 8; kt++) {
        __syncthreads();
        if (kt + 1 < 8) {
            const float* A2 = Ap + (kt + 1) * 16;
            const float* W2 = Wp + (kt + 1) * 16;
            pa0 = *(const float4*)A2; pa1 = *(const float4*)(A2 + 4);
            pb0 = *(const float4*)W2; pb1 = *(const float4*)(W2 + 4);
        }
#pragma unroll
        for (int ks = 0; ks < 16; ks += 8) {
            unsigned af[4][4], bf[4][2];
            const int k = ks + (lane & 3);
#pragma unroll
            for (int mi = 0; mi < 4; mi++) {
                int m = wm + mi * 16 + (lane >> 2);
                af[mi][0] = As[cur][m][k];
                af[mi][1] = As[cur][m + 8][k];
                af[mi][2] = As[cur][m][k + 4];
                af[mi][3] = As[cur][m + 8][k + 4];
            }
#pragma unroll
            for (int ni = 0; ni < 4; ni++) {
                int n = wn + ni * 8 + (lane >> 2);
                bf[ni][0] = Bs[cur][n][k];
                bf[ni][1] = Bs[cur][n][k + 4];
            }
#pragma unroll
            for (int mi = 0; mi < 4; mi++)
#pragma unroll
                for (int ni = 0; ni < 4; ni++)
                    mma8(acc[mi][ni], af[mi], bf[ni]);
        }
        if (kt + 1 < 8) {
            int nx = cur ^ 1;
            *(uint4*)&As[nx][r][kq]     = make_uint4(f2t(pa0.x), f2t(pa0.y), f2t(pa0.z), f2t(pa0.w));
            *(uint4*)&As[nx][r][kq + 4] = make_uint4(f2t(pa1.x), f2t(pa1.y), f2t(pa1.z), f2t(pa1.w));
            *(uint4*)&Bs[nx][r][kq]     = make_uint4(f2t(pb0.x), f2t(pb0.y), f2t(pb0.z), f2t(pb0.w));
            *(uint4*)&Bs[nx][r][kq + 4] = make_uint4(f2t(pb1.x), f2t(pb1.y), f2t(pb1.z), f2t(pb1.w));
        }
        cur ^= 1;
    }

    const float scale = 0.08838834764831845f;   // 1/sqrt(128)
    float* Sb = Sout + (size_t)blockIdx.z * 1024 * Lk;
#pragma unroll
    for (int mi = 0; mi < 4; mi++)
#pragma unroll
        for (int ni = 0; ni < 4; ni++) {
            int q0 = m0 + wm + mi * 16 + (lane >> 2);
            int col = n0 + wn + ni * 8 + 2 * (lane & 3);
            bool ok00, ok01, ok10, ok11;
            if (MODE == 0) {
                bool qa = mask[b * 1024 + q0] != 0;
                bool qb = mask[b * 1024 + q0 + 8] != 0;
                bool ka = mask[b * 1024 + col] != 0;
                bool kb = mask[b * 1024 + col + 1] != 0;
                ok00 = qa && ka; ok01 = qa && kb; ok10 = qb && ka; ok11 = qb && kb;
            } else {
                const unsigned char* mrow0 = mask + ((size_t)(b * 1024 + q0)) * 256;
                const unsigned char* mrow1 = mrow0 + 8 * 256;
                ok00 = mrow0[col] != 0; ok01 = mrow0[col + 1] != 0;
                ok10 = mrow1[col] != 0; ok11 = mrow1[col + 1] != 0;
            }
            float2 o0 = {ok00 ? acc[mi][ni][0] * scale : -1e9f,
                         ok01 ? acc[mi][ni][1] * scale : -1e9f};
            float2 o1 = {ok10 ? acc[mi][ni][2] * scale : -1e9f,
                         ok11 ? acc[mi][ni][3] * scale : -1e9f};
            *(float2*)&Sb[(size_t)q0 * Lk + col]       = o0;
            *(float2*)&Sb[(size_t)(q0 + 8) * Lk + col] = o1;
        }
}

// ---------------- row softmax, one block (128 thr) per row; PT = Lk/128 ----------
template<int PT>
__global__ void softmax_kernel(float* __restrict__ Sc) {
    float* p = Sc + (size_t)blockIdx.x * (PT * 128);
    const int tid = threadIdx.x;
    float v[PT];
    float mx = -3.4e38f;
#pragma unroll
    for (int i = 0; i < PT; i++) { v[i] = p[tid + i * 128]; mx = fmaxf(mx, v[i]); }
#pragma unroll
    for (int o = 16; o > 0; o >>= 1) mx = fmaxf(mx, __shfl_xor_sync(0xffffffffu, mx, o));
    __shared__ float shm[4], shs[4];
    if ((tid & 31) == 0) shm[tid >> 5] = mx;
    __syncthreads();
    mx = fmaxf(fmaxf(shm[0], shm[1]), fmaxf(shm[2], shm[3]));
    float s = 0.f;
#pragma unroll
    for (int i = 0; i < PT; i++) { v[i] = __expf(v[i] - mx); s += v[i]; }
#pragma unroll
    for (int o = 16; o > 0; o >>= 1) s += __shfl_xor_sync(0xffffffffu, s, o);
    if ((tid & 31) == 0) shs[tid >> 5] = s;
    __syncthreads();
    s = shs[0] + shs[1] + shs[2] + shs[3];
    float inv = 1.f / s;
#pragma unroll
    for (int i = 0; i < PT; i++) p[tid + i * 128] = v[i] * inv;
}

// ================= TF32 AV: O[b,q,h*128+n] = sum_k P[bh,q,k] * V[b,k,h*128+n] ====
// grid: (8, B*H). Block tile 128(m) x 128(n=full head) x 16.
__global__ void __launch_bounds__(256) av_tf32(
    const float* __restrict__ P, const float* __restrict__ V,
    float* __restrict__ O, int Lk, int vbstride)
{
    __shared__ __align__(16) unsigned As[2][128][20];
    __shared__ __align__(16) unsigned Bs[2][16][132];
    const int tid = threadIdx.x, lane = tid & 31, wid = tid >> 5;
    const int wm = (wid & 1) * 64, wn = (wid >> 1) * 32;
    const int b = blockIdx.y >> 2, h = blockIdx.y & 3;
    const int m0 = blockIdx.x * 128;
    const int r = tid >> 1, kq = (tid & 1) * 8;
    const int kr = tid >> 4, nq = (tid & 15) * 8;
    const float* Ap = P + ((size_t)blockIdx.y * 1024 + m0 + r) * Lk + kq;
    const float* Vp = V + (size_t)b * vbstride + h * 128 + (size_t)kr * 512 + nq;

    float4 pa0 = *(const float4*)Ap, pa1 = *(const float4*)(Ap + 4);
    float4 pb0 = *(const float4*)Vp, pb1 = *(const float4*)(Vp + 4);
    *(uint4*)&As[0][r][kq]      = make_uint4(f2t(pa0.x), f2t(pa0.y), f2t(pa0.z), f2t(pa0.w));
    *(uint4*)&As[0][r][kq + 4]  = make_uint4(f2t(pa1.x), f2t(pa1.y), f2t(pa1.z), f2t(pa1.w));
    *(uint4*)&Bs[0][kr][nq]     = make_uint4(f2t(pb0.x), f2t(pb0.y), f2t(pb0.z), f2t(pb0.w));
    *(uint4*)&Bs[0][kr][nq + 4] = make_uint4(f2t(pb1.x), f2t(pb1.y), f2t(pb1.z), f2t(pb1.w));

    float acc[4][4][4] = {};
    const int nt = Lk >> 4;
    int cur = 0;
    for (int kt = 0; kt < nt; kt++) {
        __syncthreads();
        if (kt + 1 < nt) {
            const float* A2 = Ap + (kt + 1) * 16;
            const float* V2 = Vp + (size_t)(kt + 1) * 16 * 512;
            pa0 = *(const float4*)A2; pa1 = *(const float4*)(A2 + 4);
            pb0 = *(const float4*)V2; pb1 = *(const float4*)(V2 + 4);
        }
#pragma unroll
        for (int ks = 0; ks < 16; ks += 8) {
            unsigned af[4][4], bf[4][2];
            const int k = ks + (lane & 3);
#pragma unroll
            for (int mi = 0; mi < 4; mi++) {
                int m = wm + mi * 16 + (lane >> 2);
                af[mi][0] = As[cur][m][k];
                af[mi][1] = As[cur][m + 8][k];
                af[mi][2] = As[cur][m][k + 4];
                af[mi][3] = As[cur][m + 8][k + 4];
            }
#pragma unroll
            for (int ni = 0; ni < 4; ni++) {
                int n = wn + ni * 8 + (lane >> 2);
                bf[ni][0] = Bs[cur][k][n];
                bf[ni][1] = Bs[cur][k + 4][n];
            }
#pragma unroll
            for (int mi = 0; mi < 4; mi++)
#pragma unroll
                for (int ni = 0; ni < 4; ni++)
                    mma8(acc[mi][ni], af[mi], bf[ni]);
        }
        if (kt + 1 < nt) {
            int nx = cur ^ 1;
            *(uint4*)&As[nx][r][kq]      = make_uint4(f2t(pa0.x), f2t(pa0.y), f2t(pa0.z), f2t(pa0.w));
            *(uint4*)&As[nx][r][kq + 4]  = make_uint4(f2t(pa1.x), f2t(pa1.y), f2t(pa1.z), f2t(pa1.w));
            *(uint4*)&Bs[nx][kr][nq]     = make_uint4(f2t(pb0.x), f2t(pb0.y), f2t(pb0.z), f2t(pb0.w));
            *(uint4*)&Bs[nx][kr][nq + 4] = make_uint4(f2t(pb1.x), f2t(pb1.y), f2t(pb1.z), f2t(pb1.w));
        }
        cur ^= 1;
    }

#pragma unroll
    for (int mi = 0; mi < 4; mi++)
#pragma unroll
        for (int ni = 0; ni < 4; ni++) {
            int row = m0 + wm + mi * 16 + (lane >> 2);
            int col = h * 128 + wn + ni * 8 + 2 * (lane & 3);
            float2 o0 = {acc[mi][ni][0], acc[mi][ni][1]};
            float2 o1 = {acc[mi][ni][2], acc[mi][ni][3]};
            *(float2*)&O[(size_t)b * 524288 + (size_t)row * 512 + col]       = o0;
            *(float2*)&O[(size_t)b * 524288 + (size_t)(row + 8) * 512 + col] = o1;
        }
}

// ---------------- launch ----------------
extern "C" void kernel_launch(void* const* d_in, const int* in_sizes, int n_in,
                              void* d_out, int out_size) {
    const float* edges = (const float*)d_in[0];
    const float* bbse  = (const float*)d_in[1];
    const void*  gm    = d_in[2];
    const void*  cm    = d_in[3];
    const float* gWq = (const float*)d_in[4];  const float* gbq = (const float*)d_in[5];
    const float* gWk = (const float*)d_in[6];  const float* gbk = (const float*)d_in[7];
    const float* gWv = (const float*)d_in[8];  const float* gbv = (const float*)d_in[9];
    const float* gWo = (const float*)d_in[10]; const float* gbo = (const float*)d_in[11];
    const float* cWq = (const float*)d_in[12]; const float* cbq = (const float*)d_in[13];
    const float* cWk = (const float*)d_in[14]; const float* cbk = (const float*)d_in[15];
    const float* cWv = (const float*)d_in[16]; const float* cbv = (const float*)d_in[17];
    const float* cWo = (const float*)d_in[18]; const float* cbo = (const float*)d_in[19];
    const float* fW1 = (const float*)d_in[20]; const float* fb1 = (const float*)d_in[21];
    const float* fW2 = (const float*)d_in[22]; const float* fb2 = (const float*)d_in[23];
    float* out = (float*)d_out;

    float *X, *Q, *Kb, *V, *AO, *Sc;
    unsigned char *m8g, *m8c;
    cudaGetSymbolAddress((void**)&X,  g_X);
    cudaGetSymbolAddress((void**)&Q,  g_Q);
    cudaGetSymbolAddress((void**)&Kb, g_K);
    cudaGetSymbolAddress((void**)&V,  g_V);
    cudaGetSymbolAddress((void**)&AO, g_AO);
    cudaGetSymbolAddress((void**)&Sc, g_S);
    cudaGetSymbolAddress((void**)&m8g, g_m8g);
    cudaGetSymbolAddress((void**)&m8c, g_m8c);

    // masks -> canonical uint8
    detect_kernel<<<1, 32>>>((const unsigned char*)gm, (const unsigned char*)cm);
    convert_mask_kernel<<<64, 256>>>(gm, m8g, 16384, 0);
    convert_mask_kernel<<<16384, 256>>>(cm, m8c, 4194304, 1);

    const int M = 16384;  // B*S tokens

    // ---- 1. global edge-edge self-attention ----
    inorm_kernel<<<M, 128>>>(edges, X);
    gemm_tf32_nt<0, 0><<<dim3(4, 128), 256>>>(X, 512, gWq, 512, gbq, nullptr, Q,  512, 512);
    gemm_tf32_nt<0, 0><<<dim3(4, 128), 256>>>(X, 512, gWk, 512, gbk, nullptr, Kb, 512, 512);
    gemm_tf32_nt<0, 0><<<dim3(4, 128), 256>>>(X, 512, gWv, 512, gbv, nullptr, V,  512, 512);
    scores_tf32<0><<<dim3(8, 8, 64), 256>>>(Q, Kb, m8g, Sc, 1024, 524288);
    softmax_kernel<8><<<65536, 128>>>(Sc);
    av_tf32<<<dim3(8, 64), 256>>>(Sc, V, AO, 1024, 524288);
    gemm_tf32_nt<0, 1><<<dim3(4, 128), 256>>>(AO, 512, gWo, 512, gbo, edges, out, 512, 512);

    // ---- 2. cross-attention from bb semantics ----
    inorm_kernel<<<M, 128>>>(out, X);
    gemm_tf32_nt<0, 0><<<dim3(4, 128), 256>>>(X,    512, cWq, 512, cbq, nullptr, Q,  512, 512);
    gemm_tf32_nt<0, 0><<<dim3(4, 32),  256>>>(bbse, 512, cWk, 512, cbk, nullptr, Kb, 512, 512);
    gemm_tf32_nt<0, 0><<<dim3(4, 32),  256>>>(bbse, 512, cWv, 512, cbv, nullptr, V,  512, 512);
    scores_tf32<1><<<dim3(2, 8, 64), 256>>>(Q, Kb, m8c, Sc, 256, 131072);
    softmax_kernel<2><<<65536, 128>>>(Sc);
    av_tf32<<<dim3(8, 64), 256>>>(Sc, V, AO, 256, 131072);
    gemm_tf32_nt<0, 1><<<dim3(4, 128), 256>>>(AO, 512, cWo, 512, cbo, out, out, 512, 512);

    // ---- 3. FFN ----
    inorm_kernel<<<M, 128>>>(out, X);
    gemm_tf32_nt<1, 0><<<dim3(16, 128), 256>>>(X,  512,  fW1, 512,  fb1, nullptr, Sc,  2048, 512);
    gemm_tf32_nt<0, 1><<<dim3(4, 128),  256>>>(Sc, 2048, fW2, 2048, fb2, out,     out, 512,  2048);
}

// round 7
// speedup vs baseline: 3.4207x; 1.4990x over previous
#include <cuda_runtime.h>
#include <cuda_bf16.h>

// Problem constants
//   B=16, N=32, D=512, H=4, SB=256, S=N*N=1024, DS=128
// Output: edges (16,1024,512) f32

// ---------------- static scratch (no allocations allowed) ----------------
__device__ float g_X [8388608];    // inorm output (B,S,D)
__device__ float g_Q [8388608];    // Q (B,S,D)
__device__ float g_K [8388608];    // K (B,S,D) or (B,SB,D)
__device__ float g_V [8388608];    // V
__device__ float g_AO[8388608];    // attention output pre-O-proj (B,S,D)
__device__ float g_S [67108864];   // scores (B,H,S,S) / cross scores / FFN hidden
__device__ unsigned char g_m8g[16384];    // global mask, flattened g (B,S)
__device__ unsigned char g_m8c[4194304];  // cross mask (B,S,SB)
__device__ int g_mtype[2];

// ---------------- cp.async / ldmatrix helpers ----------------
#define CPA(dst, src) asm volatile("cp.async.cg.shared.global [%0], [%1], 16;" :: "r"(dst), "l"(src))
#define CPC()         asm volatile("cp.async.commit_group;")
#define CPW(n)        asm volatile("cp.async.wait_group %0;" :: "n"(n))
#define LDM4(r0, r1, r2, r3, addr) \
    asm volatile("ldmatrix.sync.aligned.m8n8.x4.shared.b16 {%0,%1,%2,%3}, [%4];" \
        : "=r"(r0), "=r"(r1), "=r"(r2), "=r"(r3) : "r"(addr))

__device__ __forceinline__ void mma8(float* c, const unsigned* a, const unsigned* b) {
    asm volatile(
        "mma.sync.aligned.m16n8k8.row.col.f32.tf32.tf32.f32 "
        "{%0,%1,%2,%3}, {%4,%5,%6,%7}, {%8,%9}, {%0,%1,%2,%3};"
        : "+f"(c[0]), "+f"(c[1]), "+f"(c[2]), "+f"(c[3])
        : "r"(a[0]), "r"(a[1]), "r"(a[2]), "r"(a[3]), "r"(b[0]), "r"(b[1]));
}

// ---------------- mask dtype detection + conversion ----------------
// 0 = uint8 bool, 1 = int32, 2 = float32, 3 = bfloat16
__device__ int classify_bytes(const unsigned char* p) {
    bool big = false, bf16sig = false;
    int ones = 0;
    for (int i = 0; i < 256; i++) {
        unsigned char v = p[i];
        if (v > 1) big = true;
        if (v == 1) ones++;
        if (v == 0x3F && (i & 3) == 1) bf16sig = true;
    }
    if (big) return bf16sig ? 3 : 2;
    return (ones > 96) ? 0 : 1;
}

__global__ void detect_kernel(const unsigned char* gm, const unsigned char* cm) {
    if (threadIdx.x == 0) {
        g_mtype[0] = classify_bytes(gm);
        g_mtype[1] = classify_bytes(cm);
    }
}

__global__ void convert_mask_kernel(const void* src, unsigned char* dst, int n, int which) {
    int i = blockIdx.x * blockDim.x + threadIdx.x;
    if (i >= n) return;
    int t = g_mtype[which];
    unsigned char v;
    if (t == 0)      v = ((const unsigned char*)src)[i] != 0;
    else if (t == 1) v = ((const int*)src)[i] != 0;
    else if (t == 3) v = ((const unsigned short*)src)[i] != 0;
    else             v = ((const float*)src)[i] != 0.0f;
    dst[i] = v;
}

// ---------------- instance norm over D=512, one block per token ----------------
__global__ void inorm_kernel(const float* __restrict__ x, float* __restrict__ y) {
    const size_t base = (size_t)blockIdx.x * 512;
    const int tid = threadIdx.x;   // 128 threads
    float v[4];
    float s = 0.f, s2 = 0.f;
#pragma unroll
    for (int i = 0; i < 4; i++) {
        float a = x[base + tid + i * 128];
        v[i] = a; s += a; s2 += a * a;
    }
#pragma unroll
    for (int o = 16; o > 0; o >>= 1) {
        s  += __shfl_xor_sync(0xffffffffu, s,  o);
        s2 += __shfl_xor_sync(0xffffffffu, s2, o);
    }
    __shared__ float sh[8];
    int w = tid >> 5;
    if ((tid & 31) == 0) { sh[w] = s; sh[4 + w] = s2; }
    __syncthreads();
    s  = sh[0] + sh[1] + sh[2] + sh[3];
    s2 = sh[4] + sh[5] + sh[6] + sh[7];
    float mean = s * (1.f / 512.f);
    float var  = s2 * (1.f / 512.f) - mean * mean;
    float inv  = rsqrtf(var + 1e-5f);
#pragma unroll
    for (int i = 0; i < 4; i++)
        y[base + tid + i * 128] = (v[i] - mean) * inv;
}

// ================= TF32 GEMM-NT, cp.async 3-stage, ldmatrix fragments ============
// C = [res +] A(MxK) * W(NxK)^T + bias [, relu].  Block 128x128x32, 256 thr,
// 8 warps (2m x 4n), warp tile 64x32. Smem rows [128][36] raw f32 bits.
// Dynamic smem: 6 * 4608 words = 110592 B (3 A stages + 3 B stages).
#define AST 4608   // words per 128x36 stage

template<int RELU, int HASRES>
__global__ void __launch_bounds__(256) gemm_tf32_nt(
    const float* __restrict__ A, int lda,
    const float* __restrict__ W, int ldw,
    const float* __restrict__ bias,
    const float* __restrict__ res,
    float* __restrict__ C, int ldc, int K)
{
    extern __shared__ unsigned smbuf[];
    const unsigned a_smem = (unsigned)__cvta_generic_to_shared(smbuf);
    const unsigned b_smem = a_smem + 3 * AST * 4;
    const int tid = threadIdx.x, lane = tid & 31, wid = tid >> 5;
    const int wm = (wid & 1) * 64, wn = (wid >> 1) * 32;
    const int m0 = blockIdx.y * 128, n0 = blockIdx.x * 128;

    // ldmatrix lane geometry
    const int t8 = lane >> 3, l8 = lane & 7;
    const int ra = l8 + (t8 & 1) * 8, ca = (t8 >> 1) * 4;   // A tiles
    const int rb = l8 + (t8 >> 1) * 8, cb = (t8 & 1) * 4;   // B tiles
    unsigned aBase[4], bBase[2];
#pragma unroll
    for (int mi = 0; mi < 4; mi++)
        aBase[mi] = a_smem + (unsigned)(((wm + mi * 16 + ra) * 36 + ca) * 4);
#pragma unroll
    for (int p = 0; p < 2; p++)
        bBase[p] = b_smem + (unsigned)(((wn + p * 16 + rb) * 36 + cb) * 4);

    const int nt = K >> 5;   // 32-wide k chunks

    auto load_tile = [&](int s, int kt) {
        const int k0 = kt * 32;
#pragma unroll
        for (int i = 0; i < 4; i++) {
            int id = tid + i * 256;
            int row = id >> 3, c4 = (id & 7) * 4;
            unsigned da = a_smem + (unsigned)((s * AST + row * 36 + c4) * 4);
            unsigned db = b_smem + (unsigned)((s * AST + row * 36 + c4) * 4);
            CPA(da, A + (size_t)(m0 + row) * lda + k0 + c4);
            CPA(db, W + (size_t)(n0 + row) * ldw + k0 + c4);
        }
    };

    load_tile(0, 0); CPC();
    load_tile(1, 1); CPC();

    float acc[4][4][4] = {};
    for (int kt = 0; kt < nt; kt++) {
        CPW(1);
        __syncthreads();
        if (kt + 2 < nt) load_tile((kt + 2) % 3, kt + 2);
        CPC();
        const int cur = kt % 3;
        const unsigned stg = (unsigned)(cur * AST * 4);
#pragma unroll
        for (int ks = 0; ks < 32; ks += 8) {
            unsigned af[4][4], bf[4][2];
#pragma unroll
            for (int mi = 0; mi < 4; mi++)
                LDM4(af[mi][0], af[mi][1], af[mi][2], af[mi][3],
                     aBase[mi] + stg + ks * 4);
#pragma unroll
            for (int p = 0; p < 2; p++)
                LDM4(bf[2 * p][0], bf[2 * p][1], bf[2 * p + 1][0], bf[2 * p + 1][1],
                     bBase[p] + stg + ks * 4);
#pragma unroll
            for (int mi = 0; mi < 4; mi++)
#pragma unroll
                for (int ni = 0; ni < 4; ni++)
                    mma8(acc[mi][ni], af[mi], bf[ni]);
        }
        __syncthreads();
    }

#pragma unroll
    for (int mi = 0; mi < 4; mi++)
#pragma unroll
        for (int ni = 0; ni < 4; ni++) {
            int row = m0 + wm + mi * 16 + (lane >> 2);
            int col = n0 + wn + ni * 8 + 2 * (lane & 3);
            float b0v = bias[col], b1v = bias[col + 1];
            float v0 = acc[mi][ni][0] + b0v, v1 = acc[mi][ni][1] + b1v;
            float v2 = acc[mi][ni][2] + b0v, v3 = acc[mi][ni][3] + b1v;
            if (HASRES) {
                float2 r0 = *(const float2*)&res[(size_t)row * ldc + col];
                float2 r1 = *(const float2*)&res[(size_t)(row + 8) * ldc + col];
                v0 += r0.x; v1 += r0.y; v2 += r1.x; v3 += r1.y;
            }
            if (RELU) {
                v0 = fmaxf(v0, 0.f); v1 = fmaxf(v1, 0.f);
                v2 = fmaxf(v2, 0.f); v3 = fmaxf(v3, 0.f);
            }
            float2 o0 = {v0, v1}, o1 = {v2, v3};
            *(float2*)&C[(size_t)row * ldc + col]       = o0;
            *(float2*)&C[(size_t)(row + 8) * ldc + col] = o1;
        }
}

// ================= TF32 attention scores, cp.async + ldmatrix ====================
// S = mask ? (Qh Kh^T)/sqrt(128) : -1e9.  d=128 -> 4 k-chunks of 32.
// grid: (Lk/128, 8, B*H). MODE 0: global outer-product mask, MODE 1: cross.
template<int MODE>
__global__ void __launch_bounds__(256) scores_tf32(
    const float* __restrict__ Q, const float* __restrict__ Km,
    const unsigned char* __restrict__ mask,
    float* __restrict__ Sout, int Lk, int kbstride)
{
    extern __shared__ unsigned smbuf[];
    const unsigned a_smem = (unsigned)__cvta_generic_to_shared(smbuf);
    const unsigned b_smem = a_smem + 3 * AST * 4;
    const int tid = threadIdx.x, lane = tid & 31, wid = tid >> 5;
    const int wm = (wid & 1) * 64, wn = (wid >> 1) * 32;
    const int b = blockIdx.z >> 2, h = blockIdx.z & 3;
    const int m0 = blockIdx.y * 128, n0 = blockIdx.x * 128;
    const float* Ap = Q  + (size_t)b * 524288  + h * 128;
    const float* Bp = Km + (size_t)b * kbstride + h * 128;

    const int t8 = lane >> 3, l8 = lane & 7;
    const int ra = l8 + (t8 & 1) * 8, ca = (t8 >> 1) * 4;
    const int rb = l8 + (t8 >> 1) * 8, cb = (t8 & 1) * 4;
    unsigned aBase[4], bBase[2];
#pragma unroll
    for (int mi = 0; mi < 4; mi++)
        aBase[mi] = a_smem + (unsigned)(((wm + mi * 16 + ra) * 36 + ca) * 4);
#pragma unroll
    for (int p = 0; p < 2; p++)
        bBase[p] = b_smem + (unsigned)(((wn + p * 16 + rb) * 36 + cb) * 4);

    auto load_tile = [&](int s, int kt) {
        const int k0 = kt * 32;
#pragma unroll
        for (int i = 0; i < 4; i++) {
            int id = tid + i * 256;
            int row = id >> 3, c4 = (id & 7) * 4;
            unsigned da = a_smem + (unsigned)((s * AST + row * 36 + c4) * 4);
            unsigned db = b_smem + (unsigned)((s * AST + row * 36 + c4) * 4);
            CPA(da, Ap + (size_t)(m0 + row) * 512 + k0 + c4);
            CPA(db, Bp + (size_t)(n0 + row) * 512 + k0 + c4);
        }
    };

    load_tile(0, 0); CPC();
    load_tile(1, 1); CPC();

    float acc[4][4][4] = {};
    for (int kt = 0; kt < 4; kt++) {
        CPW(1);
        __syncthreads();
        if (kt + 2 < 4) load_tile((kt + 2) % 3, kt + 2);
        CPC();
        const int cur = kt % 3;
        const unsigned stg = (unsigned)(cur * AST * 4);
#pragma unroll
        for (int ks = 0; ks < 32; ks += 8) {
            unsigned af[4][4], bf[4][2];
#pragma unroll
            for (int mi = 0; mi < 4; mi++)
                LDM4(af[mi][0], af[mi][1], af[mi][2], af[mi][3],
                     aBase[mi] + stg + ks * 4);
#pragma unroll
            for (int p = 0; p < 2; p++)
                LDM4(bf[2 * p][0], bf[2 * p][1], bf[2 * p + 1][0], bf[2 * p + 1][1],
                     bBase[p] + stg + ks * 4);
#pragma unroll
            for (int mi = 0; mi < 4; mi++)
#pragma unroll
                for (int ni = 0; ni < 4; ni++)
                    mma8(acc[mi][ni], af[mi], bf[ni]);
        }
        __syncthreads();
    }

    const float scale = 0.08838834764831845f;   // 1/sqrt(128)
    float* Sb = Sout + (size_t)blockIdx.z * 1024 * Lk;
#pragma unroll
    for (int mi = 0; mi < 4; mi++)
#pragma unroll
        for (int ni = 0; ni < 4; ni++) {
            int q0 = m0 + wm + mi * 16 + (lane >> 2);
            int col = n0 + wn + ni * 8 + 2 * (lane & 3);
            bool ok00, ok01, ok10, ok11;
            if (MODE == 0) {
                bool qa = mask[b * 1024 + q0] != 0;
                bool qb = mask[b * 1024 + q0 + 8] != 0;
                bool ka = mask[b * 1024 + col] != 0;
                bool kb = mask[b * 1024 + col + 1] != 0;
                ok00 = qa && ka; ok01 = qa && kb; ok10 = qb && ka; ok11 = qb && kb;
            } else {
                const unsigned char* mrow0 = mask + ((size_t)(b * 1024 + q0)) * 256;
                const unsigned char* mrow1 = mrow0 + 8 * 256;
                ok00 = mrow0[col] != 0; ok01 = mrow0[col + 1] != 0;
                ok10 = mrow1[col] != 0; ok11 = mrow1[col + 1] != 0;
            }
            float2 o0 = {ok00 ? acc[mi][ni][0] * scale : -1e9f,
                         ok01 ? acc[mi][ni][1] * scale : -1e9f};
            float2 o1 = {ok10 ? acc[mi][ni][2] * scale : -1e9f,
                         ok11 ? acc[mi][ni][3] * scale : -1e9f};
            *(float2*)&Sb[(size_t)q0 * Lk + col]       = o0;
            *(float2*)&Sb[(size_t)(q0 + 8) * Lk + col] = o1;
        }
}

// ---------------- row softmax, one block (128 thr) per row; PT = Lk/128 ----------
template<int PT>
__global__ void softmax_kernel(float* __restrict__ Sc) {
    float* p = Sc + (size_t)blockIdx.x * (PT * 128);
    const int tid = threadIdx.x;
    float v[PT];
    float mx = -3.4e38f;
#pragma unroll
    for (int i = 0; i < PT; i++) { v[i] = p[tid + i * 128]; mx = fmaxf(mx, v[i]); }
#pragma unroll
    for (int o = 16; o > 0; o >>= 1) mx = fmaxf(mx, __shfl_xor_sync(0xffffffffu, mx, o));
    __shared__ float shm[4], shs[4];
    if ((tid & 31) == 0) shm[tid >> 5] = mx;
    __syncthreads();
    mx = fmaxf(fmaxf(shm[0], shm[1]), fmaxf(shm[2], shm[3]));
    float s = 0.f;
#pragma unroll
    for (int i = 0; i < PT; i++) { v[i] = __expf(v[i] - mx); s += v[i]; }
#pragma unroll
    for (int o = 16; o > 0; o >>= 1) s += __shfl_xor_sync(0xffffffffu, s, o);
    if ((tid & 31) == 0) shs[tid >> 5] = s;
    __syncthreads();
    s = shs[0] + shs[1] + shs[2] + shs[3];
    float inv = 1.f / s;
#pragma unroll
    for (int i = 0; i < PT; i++) p[tid + i * 128] = v[i] * inv;
}

// ================= TF32 AV, cp.async + ldmatrix(A) ===============================
// O[b,q,h*128+n] = sum_k P[bh,q,k] * V[b,k,h*128+n].
// grid: (8, B*H). Block tile 128(m) x 128(n=head dim) x 32(kv).
// A stages 128x36 (P), B stages 32x132 (V, k-major).
#define BVT 4224   // words per 32x132 V stage

__global__ void __launch_bounds__(256) av_tf32(
    const float* __restrict__ P, const float* __restrict__ V,
    float* __restrict__ O, int Lk, int vbstride)
{
    extern __shared__ unsigned smbuf[];
    unsigned* Bw = smbuf + 3 * AST;          // generic-space view for scalar loads
    const unsigned a_smem = (unsigned)__cvta_generic_to_shared(smbuf);
    const unsigned b_smem = a_smem + 3 * AST * 4;
    const int tid = threadIdx.x, lane = tid & 31, wid = tid >> 5;
    const int wm = (wid & 1) * 64, wn = (wid >> 1) * 32;
    const int b = blockIdx.y >> 2, h = blockIdx.y & 3;
    const int m0 = blockIdx.x * 128;
    const float* Pp = P + ((size_t)blockIdx.y * 1024 + m0) * Lk;
    const float* Vp = V + (size_t)b * vbstride + h * 128;

    const int t8 = lane >> 3, l8 = lane & 7;
    const int ra = l8 + (t8 & 1) * 8, ca = (t8 >> 1) * 4;
    unsigned aBase[4];
#pragma unroll
    for (int mi = 0; mi < 4; mi++)
        aBase[mi] = a_smem + (unsigned)(((wm + mi * 16 + ra) * 36 + ca) * 4);

    auto load_tile = [&](int s, int kt) {
        const int k0 = kt * 32;
#pragma unroll
        for (int i = 0; i < 4; i++) {        // P: 128 rows x 32 words
            int id = tid + i * 256;
            int row = id >> 3, c4 = (id & 7) * 4;
            unsigned da = a_smem + (unsigned)((s * AST + row * 36 + c4) * 4);
            CPA(da, Pp + (size_t)row * Lk + k0 + c4);
        }
#pragma unroll
        for (int i = 0; i < 4; i++) {        // V: 32 rows x 128 words (FIXED: full coverage)
            int id = tid + i * 256;
            int row = id >> 5, c4 = (id & 31) * 4;
            unsigned db = b_smem + (unsigned)((s * BVT + row * 132 + c4) * 4);
            CPA(db, Vp + (size_t)(k0 + row) * 512 + c4);
        }
    };

    load_tile(0, 0); CPC();
    load_tile(1, 1); CPC();

    float acc[4][4][4] = {};
    const int nt = Lk >> 5;
    for (int kt = 0; kt < nt; kt++) {
        CPW(1);
        __syncthreads();
        if (kt + 2 < nt) load_tile((kt + 2) % 3, kt + 2);
        CPC();
        const int cur = kt % 3;
        const unsigned stg = (unsigned)(cur * AST * 4);
        const unsigned* Bcur = Bw + cur * BVT;
#pragma unroll
        for (int ks = 0; ks < 32; ks += 8) {
            unsigned af[4][4], bf[4][2];
#pragma unroll
            for (int mi = 0; mi < 4; mi++)
                LDM4(af[mi][0], af[mi][1], af[mi][2], af[mi][3],
                     aBase[mi] + stg + ks * 4);
            const int kk = ks + (lane & 3);
#pragma unroll
            for (int ni = 0; ni < 4; ni++) {
                int n = wn + ni * 8 + (lane >> 2);
                bf[ni][0] = Bcur[kk * 132 + n];
                bf[ni][1] = Bcur[(kk + 4) * 132 + n];
            }
#pragma unroll
            for (int mi = 0; mi < 4; mi++)
#pragma unroll
                for (int ni = 0; ni < 4; ni++)
                    mma8(acc[mi][ni], af[mi], bf[ni]);
        }
        __syncthreads();
    }

#pragma unroll
    for (int mi = 0; mi < 4; mi++)
#pragma unroll
        for (int ni = 0; ni < 4; ni++) {
            int row = m0 + wm + mi * 16 + (lane >> 2);
            int col = h * 128 + wn + ni * 8 + 2 * (lane & 3);
            float2 o0 = {acc[mi][ni][0], acc[mi][ni][1]};
            float2 o1 = {acc[mi][ni][2], acc[mi][ni][3]};
            *(float2*)&O[(size_t)b * 524288 + (size_t)row * 512 + col]       = o0;
            *(float2*)&O[(size_t)b * 524288 + (size_t)(row + 8) * 512 + col] = o1;
        }
}

// ---------------- launch ----------------
static const int SMEM_GEMM = 6 * AST * 4;             // 110592
static const int SMEM_AV   = (3 * AST + 3 * BVT) * 4; // 105984

extern "C" void kernel_launch(void* const* d_in, const int* in_sizes, int n_in,
                              void* d_out, int out_size) {
    const float* edges = (const float*)d_in[0];
    const float* bbse  = (const float*)d_in[1];
    const void*  gm    = d_in[2];
    const void*  cm    = d_in[3];
    const float* gWq = (const float*)d_in[4];  const float* gbq = (const float*)d_in[5];
    const float* gWk = (const float*)d_in[6];  const float* gbk = (const float*)d_in[7];
    const float* gWv = (const float*)d_in[8];  const float* gbv = (const float*)d_in[9];
    const float* gWo = (const float*)d_in[10]; const float* gbo = (const float*)d_in[11];
    const float* cWq = (const float*)d_in[12]; const float* cbq = (const float*)d_in[13];
    const float* cWk = (const float*)d_in[14]; const float* cbk = (const float*)d_in[15];
    const float* cWv = (const float*)d_in[16]; const float* cbv = (const float*)d_in[17];
    const float* cWo = (const float*)d_in[18]; const float* cbo = (const float*)d_in[19];
    const float* fW1 = (const float*)d_in[20]; const float* fb1 = (const float*)d_in[21];
    const float* fW2 = (const float*)d_in[22]; const float* fb2 = (const float*)d_in[23];
    float* out = (float*)d_out;

    float *X, *Q, *Kb, *V, *AO, *Sc;
    unsigned char *m8g, *m8c;
    cudaGetSymbolAddress((void**)&X,  g_X);
    cudaGetSymbolAddress((void**)&Q,  g_Q);
    cudaGetSymbolAddress((void**)&Kb, g_K);
    cudaGetSymbolAddress((void**)&V,  g_V);
    cudaGetSymbolAddress((void**)&AO, g_AO);
    cudaGetSymbolAddress((void**)&Sc, g_S);
    cudaGetSymbolAddress((void**)&m8g, g_m8g);
    cudaGetSymbolAddress((void**)&m8c, g_m8c);

    // raise dynamic smem limits (host-side, idempotent, capture-safe)
    cudaFuncSetAttribute(gemm_tf32_nt<0,0>, cudaFuncAttributeMaxDynamicSharedMemorySize, SMEM_GEMM);
    cudaFuncSetAttribute(gemm_tf32_nt<0,1>, cudaFuncAttributeMaxDynamicSharedMemorySize, SMEM_GEMM);
    cudaFuncSetAttribute(gemm_tf32_nt<1,0>, cudaFuncAttributeMaxDynamicSharedMemorySize, SMEM_GEMM);
    cudaFuncSetAttribute(scores_tf32<0>,    cudaFuncAttributeMaxDynamicSharedMemorySize, SMEM_GEMM);
    cudaFuncSetAttribute(scores_tf32<1>,    cudaFuncAttributeMaxDynamicSharedMemorySize, SMEM_GEMM);
    cudaFuncSetAttribute(av_tf32,           cudaFuncAttributeMaxDynamicSharedMemorySize, SMEM_AV);

    // masks -> canonical uint8
    detect_kernel<<<1, 32>>>((const unsigned char*)gm, (const unsigned char*)cm);
    convert_mask_kernel<<<64, 256>>>(gm, m8g, 16384, 0);
    convert_mask_kernel<<<16384, 256>>>(cm, m8c, 4194304, 1);

    const int M = 16384;  // B*S tokens

    // ---- 1. global edge-edge self-attention ----
    inorm_kernel<<<M, 128>>>(edges, X);
    gemm_tf32_nt<0, 0><<<dim3(4, 128), 256, SMEM_GEMM>>>(X, 512, gWq, 512, gbq, nullptr, Q,  512, 512);
    gemm_tf32_nt<0, 0><<<dim3(4, 128), 256, SMEM_GEMM>>>(X, 512, gWk, 512, gbk, nullptr, Kb, 512, 512);
    gemm_tf32_nt<0, 0><<<dim3(4, 128), 256, SMEM_GEMM>>>(X, 512, gWv, 512, gbv, nullptr, V,  512, 512);
    scores_tf32<0><<<dim3(8, 8, 64), 256, SMEM_GEMM>>>(Q, Kb, m8g, Sc, 1024, 524288);
    softmax_kernel<8><<<65536, 128>>>(Sc);
    av_tf32<<<dim3(8, 64), 256, SMEM_AV>>>(Sc, V, AO, 1024, 524288);
    gemm_tf32_nt<0, 1><<<dim3(4, 128), 256, SMEM_GEMM>>>(AO, 512, gWo, 512, gbo, edges, out, 512, 512);

    // ---- 2. cross-attention from bb semantics ----
    inorm_kernel<<<M, 128>>>(out, X);
    gemm_tf32_nt<0, 0><<<dim3(4, 128), 256, SMEM_GEMM>>>(X,    512, cWq, 512, cbq, nullptr, Q,  512, 512);
    gemm_tf32_nt<0, 0><<<dim3(4, 32),  256, SMEM_GEMM>>>(bbse, 512, cWk, 512, cbk, nullptr, Kb, 512, 512);
    gemm_tf32_nt<0, 0><<<dim3(4, 32),  256, SMEM_GEMM>>>(bbse, 512, cWv, 512, cbv, nullptr, V,  512, 512);
    scores_tf32<1><<<dim3(2, 8, 64), 256, SMEM_GEMM>>>(Q, Kb, m8c, Sc, 256, 131072);
    softmax_kernel<2><<<65536, 128>>>(Sc);
    av_tf32<<<dim3(8, 64), 256, SMEM_AV>>>(Sc, V, AO, 256, 131072);
    gemm_tf32_nt<0, 1><<<dim3(4, 128), 256, SMEM_GEMM>>>(AO, 512, cWo, 512, cbo, out, out, 512, 512);

    // ---- 3. FFN ----
    inorm_kernel<<<M, 128>>>(out, X);
    gemm_tf32_nt<1, 0><<<dim3(16, 128), 256, SMEM_GEMM>>>(X,  512,  fW1, 512,  fb1, nullptr, Sc,  2048, 512);
    gemm_tf32_nt<0, 1><<<dim3(4, 128),  256, SMEM_GEMM>>>(Sc, 2048, fW2, 2048, fb2, out,     out, 512,  2048);
}

// round 9
// speedup vs baseline: 3.7631x; 1.1001x over previous
#include <cuda_runtime.h>
#include <cuda_bf16.h>

// Problem constants
//   B=16, N=32, D=512, H=4, SB=256, S=N*N=1024, DS=128
// Output: edges (16,1024,512) f32

// ---------------- static scratch (no allocations allowed) ----------------
__device__ float g_X [8388608];    // inorm output (B,S,D)
__device__ float g_Q [8388608];    // Q (B,S,D)
__device__ float g_K [8388608];    // K (B,S,D) or (B,SB,D)
__device__ float g_V [8388608];    // V
__device__ float g_AO[8388608];    // attention output pre-O-proj (B,S,D)
__device__ float g_S [67108864];   // FFN hidden
__device__ unsigned char g_m8g[16384];    // global mask, flattened g (B,S)
__device__ unsigned char g_m8c[4194304];  // cross mask (B,S,SB)
__device__ int g_mtype[2];

// ---------------- cp.async / ldmatrix helpers ----------------
#define CPA(dst, src) asm volatile("cp.async.cg.shared.global [%0], [%1], 16;" :: "r"(dst), "l"(src))
#define CPC()         asm volatile("cp.async.commit_group;")
#define CPW(n)        asm volatile("cp.async.wait_group %0;" :: "n"(n))
#define LDM4(r0, r1, r2, r3, addr) \
    asm volatile("ldmatrix.sync.aligned.m8n8.x4.shared.b16 {%0,%1,%2,%3}, [%4];" \
        : "=r"(r0), "=r"(r1), "=r"(r2), "=r"(r3) : "r"(addr))

__device__ __forceinline__ void mma8(float* c, const unsigned* a, const unsigned* b) {
    asm volatile(
        "mma.sync.aligned.m16n8k8.row.col.f32.tf32.tf32.f32 "
        "{%0,%1,%2,%3}, {%4,%5,%6,%7}, {%8,%9}, {%0,%1,%2,%3};"
        : "+f"(c[0]), "+f"(c[1]), "+f"(c[2]), "+f"(c[3])
        : "r"(a[0]), "r"(a[1]), "r"(a[2]), "r"(a[3]), "r"(b[0]), "r"(b[1]));
}

// ---------------- mask dtype detection + conversion ----------------
// 0 = uint8 bool, 1 = int32, 2 = float32, 3 = bfloat16
__device__ int classify_bytes(const unsigned char* p) {
    bool big = false, bf16sig = false;
    int ones = 0;
    for (int i = 0; i < 256; i++) {
        unsigned char v = p[i];
        if (v > 1) big = true;
        if (v == 1) ones++;
        if (v == 0x3F && (i & 3) == 1) bf16sig = true;
    }
    if (big) return bf16sig ? 3 : 2;
    return (ones > 96) ? 0 : 1;
}

__global__ void detect_kernel(const unsigned char* gm, const unsigned char* cm) {
    if (threadIdx.x == 0) {
        g_mtype[0] = classify_bytes(gm);
        g_mtype[1] = classify_bytes(cm);
    }
}

__global__ void convert_mask_kernel(const void* src, unsigned char* dst, int n, int which) {
    int i = blockIdx.x * blockDim.x + threadIdx.x;
    if (i >= n) return;
    int t = g_mtype[which];
    unsigned char v;
    if (t == 0)      v = ((const unsigned char*)src)[i] != 0;
    else if (t == 1) v = ((const int*)src)[i] != 0;
    else if (t == 3) v = ((const unsigned short*)src)[i] != 0;
    else             v = ((const float*)src)[i] != 0.0f;
    dst[i] = v;
}

// ---------------- instance norm over D=512, one block per token ----------------
__global__ void inorm_kernel(const float* __restrict__ x, float* __restrict__ y) {
    const size_t base = (size_t)blockIdx.x * 512;
    const int tid = threadIdx.x;   // 128 threads
    float v[4];
    float s = 0.f, s2 = 0.f;
#pragma unroll
    for (int i = 0; i < 4; i++) {
        float a = x[base + tid + i * 128];
        v[i] = a; s += a; s2 += a * a;
    }
#pragma unroll
    for (int o = 16; o > 0; o >>= 1) {
        s  += __shfl_xor_sync(0xffffffffu, s,  o);
        s2 += __shfl_xor_sync(0xffffffffu, s2, o);
    }
    __shared__ float sh[8];
    int w = tid >> 5;
    if ((tid & 31) == 0) { sh[w] = s; sh[4 + w] = s2; }
    __syncthreads();
    s  = sh[0] + sh[1] + sh[2] + sh[3];
    s2 = sh[4] + sh[5] + sh[6] + sh[7];
    float mean = s * (1.f / 512.f);
    float var  = s2 * (1.f / 512.f) - mean * mean;
    float inv  = rsqrtf(var + 1e-5f);
#pragma unroll
    for (int i = 0; i < 4; i++)
        y[base + tid + i * 128] = (v[i] - mean) * inv;
}

// ================= TF32 GEMM-NT, cp.async 3-stage, ldmatrix fragments ============
#define AST 4608   // words per 128x36 stage

template<int RELU, int HASRES>
__global__ void __launch_bounds__(256) gemm_tf32_nt(
    const float* __restrict__ A, int lda,
    const float* __restrict__ W, int ldw,
    const float* __restrict__ bias,
    const float* __restrict__ res,
    float* __restrict__ C, int ldc, int K)
{
    extern __shared__ unsigned smbuf[];
    const unsigned a_smem = (unsigned)__cvta_generic_to_shared(smbuf);
    const unsigned b_smem = a_smem + 3 * AST * 4;
    const int tid = threadIdx.x, lane = tid & 31, wid = tid >> 5;
    const int wm = (wid & 1) * 64, wn = (wid >> 1) * 32;
    const int m0 = blockIdx.y * 128, n0 = blockIdx.x * 128;

    const int t8 = lane >> 3, l8 = lane & 7;
    const int ra = l8 + (t8 & 1) * 8, ca = (t8 >> 1) * 4;   // A tiles
    const int rb = l8 + (t8 >> 1) * 8, cb = (t8 & 1) * 4;   // B tiles
    unsigned aBase[4], bBase[2];
#pragma unroll
    for (int mi = 0; mi < 4; mi++)
        aBase[mi] = a_smem + (unsigned)(((wm + mi * 16 + ra) * 36 + ca) * 4);
#pragma unroll
    for (int p = 0; p < 2; p++)
        bBase[p] = b_smem + (unsigned)(((wn + p * 16 + rb) * 36 + cb) * 4);

    const int nt = K >> 5;

    auto load_tile = [&](int s, int kt) {
        const int k0 = kt * 32;
#pragma unroll
        for (int i = 0; i < 4; i++) {
            int id = tid + i * 256;
            int row = id >> 3, c4 = (id & 7) * 4;
            unsigned da = a_smem + (unsigned)((s * AST + row * 36 + c4) * 4);
            unsigned db = b_smem + (unsigned)((s * AST + row * 36 + c4) * 4);
            CPA(da, A + (size_t)(m0 + row) * lda + k0 + c4);
            CPA(db, W + (size_t)(n0 + row) * ldw + k0 + c4);
        }
    };

    load_tile(0, 0); CPC();
    load_tile(1, 1); CPC();

    float acc[4][4][4] = {};
    for (int kt = 0; kt < nt; kt++) {
        CPW(1);
        __syncthreads();
        if (kt + 2 < nt) load_tile((kt + 2) % 3, kt + 2);
        CPC();
        const int cur = kt % 3;
        const unsigned stg = (unsigned)(cur * AST * 4);
#pragma unroll
        for (int ks = 0; ks < 32; ks += 8) {
            unsigned af[4][4], bf[4][2];
#pragma unroll
            for (int mi = 0; mi < 4; mi++)
                LDM4(af[mi][0], af[mi][1], af[mi][2], af[mi][3],
                     aBase[mi] + stg + ks * 4);
#pragma unroll
            for (int p = 0; p < 2; p++)
                LDM4(bf[2 * p][0], bf[2 * p][1], bf[2 * p + 1][0], bf[2 * p + 1][1],
                     bBase[p] + stg + ks * 4);
#pragma unroll
            for (int mi = 0; mi < 4; mi++)
#pragma unroll
                for (int ni = 0; ni < 4; ni++)
                    mma8(acc[mi][ni], af[mi], bf[ni]);
        }
        __syncthreads();
    }

#pragma unroll
    for (int mi = 0; mi < 4; mi++)
#pragma unroll
        for (int ni = 0; ni < 4; ni++) {
            int row = m0 + wm + mi * 16 + (lane >> 2);
            int col = n0 + wn + ni * 8 + 2 * (lane & 3);
            float b0v = bias[col], b1v = bias[col + 1];
            float v0 = acc[mi][ni][0] + b0v, v1 = acc[mi][ni][1] + b1v;
            float v2 = acc[mi][ni][2] + b0v, v3 = acc[mi][ni][3] + b1v;
            if (HASRES) {
                float2 r0 = *(const float2*)&res[(size_t)row * ldc + col];
                float2 r1 = *(const float2*)&res[(size_t)(row + 8) * ldc + col];
                v0 += r0.x; v1 += r0.y; v2 += r1.x; v3 += r1.y;
            }
            if (RELU) {
                v0 = fmaxf(v0, 0.f); v1 = fmaxf(v1, 0.f);
                v2 = fmaxf(v2, 0.f); v3 = fmaxf(v3, 0.f);
            }
            float2 o0 = {v0, v1}, o1 = {v2, v3};
            *(float2*)&C[(size_t)row * ldc + col]       = o0;
            *(float2*)&C[(size_t)(row + 8) * ldc + col] = o1;
        }
}

// ================= Fused flash attention (TF32 MMA, online softmax) ==============
// One block = (128 q-rows, one b*h). 8 warps, warp owns 16 q-rows x full KV sweep.
// KV tiles of 64, double-buffered cp.async. Q resident in smem + register frags.
// P stays in registers (shfl permute acc-frag -> A-frag).
// smem: Q 128x132 | K 2x64x132 | V 2x64x136  = 204800 B.
#define QW (128 * 132)
#define KW (64 * 132)
#define VW (64 * 136)

template<int MODE>   // 0: global outer-product mask, 1: cross mask
__global__ void __launch_bounds__(256) flash_tf32(
    const float* __restrict__ Qg, const float* __restrict__ Kg,
    const float* __restrict__ Vg, const unsigned char* __restrict__ mask,
    float* __restrict__ O, int Lk, int kvstride)
{
    extern __shared__ unsigned smbuf[];
    unsigned* Vw = smbuf + QW + 2 * KW;          // generic view for scalar V loads
    const unsigned q_sm = (unsigned)__cvta_generic_to_shared(smbuf);
    const unsigned k_sm = q_sm + QW * 4;
    const unsigned v_sm = k_sm + 2 * KW * 4;
    const int tid = threadIdx.x, lane = tid & 31, wid = tid >> 5;
    const int l = lane & 3, r4 = lane >> 2;
    const int b = blockIdx.y >> 2, h = blockIdx.y & 3;
    const int q0 = blockIdx.x * 128;
    const float* Qp = Qg + (size_t)b * 524288 + (size_t)q0 * 512 + h * 128;
    const float* Kp = Kg + (size_t)b * kvstride + h * 128;
    const float* Vp = Vg + (size_t)b * kvstride + h * 128;

    // ldmatrix geometry (validated in gemm_tf32_nt)
    const int t8 = lane >> 3, l8 = lane & 7;
    const int ra = l8 + (t8 & 1) * 8, ca = (t8 >> 1) * 4;
    const int rb = l8 + (t8 >> 1) * 8, cb = (t8 & 1) * 4;
    const unsigned aBase = q_sm + (unsigned)(((wid * 16 + ra) * 132 + ca) * 4);
    unsigned kBase[4];
#pragma unroll
    for (int p = 0; p < 4; p++)
        kBase[p] = k_sm + (unsigned)(((p * 16 + rb) * 132 + cb) * 4);

    // ---- load Q tile (128x128) ----
#pragma unroll
    for (int i = 0; i < 16; i++) {
        int id = tid + i * 256;
        int row = id >> 5, c4 = (id & 31) * 4;
        CPA(q_sm + (unsigned)((row * 132 + c4) * 4), Qp + (size_t)row * 512 + c4);
    }
    auto loadKV = [&](int st, int t) {
        const int kv0 = t * 64;
#pragma unroll
        for (int i = 0; i < 8; i++) {
            int id = tid + i * 256;
            int row = id >> 5, c4 = (id & 31) * 4;
            CPA(k_sm + (unsigned)((st * KW + row * 132 + c4) * 4),
                Kp + (size_t)(kv0 + row) * 512 + c4);
        }
#pragma unroll
        for (int i = 0; i < 8; i++) {
            int id = tid + i * 256;
            int row = id >> 5, c4 = (id & 31) * 4;
            CPA(v_sm + (unsigned)((st * VW + row * 136 + c4) * 4),
                Vp + (size_t)(kv0 + row) * 512 + c4);
        }
    };
    const int nt = Lk >> 6;
    loadKV(0, 0); CPC();          // group0 = Q + KV0
    loadKV(1, 1); CPC();          // group1 = KV1

    // per-warp row info
    const int rowg0 = q0 + wid * 16 + r4;      // global q row
    const int rowg1 = rowg0 + 8;
    unsigned char qok0 = 1, qok1 = 1;
    if (MODE == 0) { qok0 = mask[b * 1024 + rowg0]; qok1 = mask[b * 1024 + rowg1]; }
    const unsigned char* mrow0 = mask + ((size_t)(b * 1024 + rowg0)) * 256;
    const unsigned char* mrow1 = mask + ((size_t)(b * 1024 + rowg1)) * 256;

    CPW(1);
    __syncthreads();              // Q + KV0 ready

    // preload Q fragments (16 k8-chunks)
    unsigned qf[16][4];
#pragma unroll
    for (int kc = 0; kc < 16; kc++)
        LDM4(qf[kc][0], qf[kc][1], qf[kc][2], qf[kc][3], aBase + kc * 32);

    float oacc[16][4] = {};
    float m0 = -INFINITY, m1 = -INFINITY, l0 = 0.f, l1 = 0.f;
    const float scale = 0.08838834764831845f;   // 1/sqrt(128)

    for (int t = 0; t < nt; t++) {
        if (t > 0) { CPW(1); __syncthreads(); }
        const int st = t & 1;
        const unsigned kstg = (unsigned)(st * KW * 4);
        const int kv0 = t * 64;

        // ---- S = Q K^T (16 rows x 64 cols per warp) ----
        float sacc[8][4] = {};
#pragma unroll
        for (int kc = 0; kc < 16; kc++) {
            unsigned bf[8][2];
#pragma unroll
            for (int p = 0; p < 4; p++)
                LDM4(bf[2 * p][0], bf[2 * p][1], bf[2 * p + 1][0], bf[2 * p + 1][1],
                     kBase[p] + kstg + kc * 32);
#pragma unroll
            for (int nn = 0; nn < 8; nn++)
                mma8(sacc[nn], qf[kc], bf[nn]);
        }

        // ---- mask + scale + online softmax ----
        float tmax0 = -INFINITY, tmax1 = -INFINITY;
#pragma unroll
        for (int nn = 0; nn < 8; nn++) {
            int col = kv0 + nn * 8 + 2 * l;
            bool ok00, ok01, ok10, ok11;
            if (MODE == 0) {
                bool ka = mask[b * 1024 + col] != 0;
                bool kb = mask[b * 1024 + col + 1] != 0;
                ok00 = qok0 && ka; ok01 = qok0 && kb;
                ok10 = qok1 && ka; ok11 = qok1 && kb;
            } else {
                ok00 = mrow0[col] != 0; ok01 = mrow0[col + 1] != 0;
                ok10 = mrow1[col] != 0; ok11 = mrow1[col + 1] != 0;
            }
            sacc[nn][0] = ok00 ? sacc[nn][0] * scale : -1e9f;
            sacc[nn][1] = ok01 ? sacc[nn][1] * scale : -1e9f;
            sacc[nn][2] = ok10 ? sacc[nn][2] * scale : -1e9f;
            sacc[nn][3] = ok11 ? sacc[nn][3] * scale : -1e9f;
            tmax0 = fmaxf(tmax0, fmaxf(sacc[nn][0], sacc[nn][1]));
            tmax1 = fmaxf(tmax1, fmaxf(sacc[nn][2], sacc[nn][3]));
        }
        tmax0 = fmaxf(tmax0, __shfl_xor_sync(0xffffffffu, tmax0, 1));
        tmax0 = fmaxf(tmax0, __shfl_xor_sync(0xffffffffu, tmax0, 2));
        tmax1 = fmaxf(tmax1, __shfl_xor_sync(0xffffffffu, tmax1, 1));
        tmax1 = fmaxf(tmax1, __shfl_xor_sync(0xffffffffu, tmax1, 2));
        float mn0 = fmaxf(m0, tmax0), mn1 = fmaxf(m1, tmax1);
        float al0 = __expf(m0 - mn0), al1 = __expf(m1 - mn1);
        float rs0 = 0.f, rs1 = 0.f;
#pragma unroll
        for (int nn = 0; nn < 8; nn++) {
            sacc[nn][0] = __expf(sacc[nn][0] - mn0);
            sacc[nn][1] = __expf(sacc[nn][1] - mn0);
            sacc[nn][2] = __expf(sacc[nn][2] - mn1);
            sacc[nn][3] = __expf(sacc[nn][3] - mn1);
            rs0 += sacc[nn][0] + sacc[nn][1];
            rs1 += sacc[nn][2] + sacc[nn][3];
        }
        rs0 += __shfl_xor_sync(0xffffffffu, rs0, 1);
        rs0 += __shfl_xor_sync(0xffffffffu, rs0, 2);
        rs1 += __shfl_xor_sync(0xffffffffu, rs1, 1);
        rs1 += __shfl_xor_sync(0xffffffffu, rs1, 2);
        l0 = l0 * al0 + rs0; l1 = l1 * al1 + rs1;
        m0 = mn0; m1 = mn1;
#pragma unroll
        for (int nn = 0; nn < 16; nn++) {
            oacc[nn][0] *= al0; oacc[nn][1] *= al0;
            oacc[nn][2] *= al1; oacc[nn][3] *= al1;
        }

        // ---- O += P V  (k = 64 kv, n = 128 head dim) ----
        const int src0 = (lane & ~3) | (l >> 1);
        const int src1 = src0 + 2;
        const bool odd = l & 1;
        const unsigned* Vs = Vw + st * VW;
#pragma unroll
        for (int kc = 0; kc < 8; kc++) {
            float f0 = __shfl_sync(0xffffffffu, sacc[kc][0], src0);
            float f1 = __shfl_sync(0xffffffffu, sacc[kc][1], src0);
            float h0 = __shfl_sync(0xffffffffu, sacc[kc][2], src0);
            float h1 = __shfl_sync(0xffffffffu, sacc[kc][3], src0);
            float g0 = __shfl_sync(0xffffffffu, sacc[kc][0], src1);
            float g1 = __shfl_sync(0xffffffffu, sacc[kc][1], src1);
            float k0 = __shfl_sync(0xffffffffu, sacc[kc][2], src1);
            float k1 = __shfl_sync(0xffffffffu, sacc[kc][3], src1);
            unsigned au[4];
            au[0] = __float_as_uint(odd ? f1 : f0);   // row r,   col l
            au[1] = __float_as_uint(odd ? h1 : h0);   // row r+8, col l
            au[2] = __float_as_uint(odd ? g1 : g0);   // row r,   col l+4
            au[3] = __float_as_uint(odd ? k1 : k0);   // row r+8, col l+4
#pragma unroll
            for (int nn = 0; nn < 16; nn++) {
                unsigned bb[2];
                bb[0] = Vs[(kc * 8 + l) * 136 + nn * 8 + r4];
                bb[1] = Vs[(kc * 8 + l + 4) * 136 + nn * 8 + r4];
                mma8(oacc[nn], au, bb);
            }
        }

        __syncthreads();                          // all warps done with stage st
        if (t + 2 < nt) loadKV(st, t + 2);
        CPC();
    }

    // ---- epilogue: O /= l, write to AO ----
    float inv0 = 1.f / l0, inv1 = 1.f / l1;
#pragma unroll
    for (int nn = 0; nn < 16; nn++) {
        int col = h * 128 + nn * 8 + 2 * l;
        float2 o0 = {oacc[nn][0] * inv0, oacc[nn][1] * inv0};
        float2 o1 = {oacc[nn][2] * inv1, oacc[nn][3] * inv1};
        *(float2*)&O[(size_t)b * 524288 + (size_t)rowg0 * 512 + col] = o0;
        *(float2*)&O[(size_t)b * 524288 + (size_t)rowg1 * 512 + col] = o1;
    }
}

// ---------------- launch ----------------
static const int SMEM_GEMM  = 6 * AST * 4;              // 110592
static const int SMEM_FLASH = (QW + 2 * KW + 2 * VW) * 4; // 204800

extern "C" void kernel_launch(void* const* d_in, const int* in_sizes, int n_in,
                              void* d_out, int out_size) {
    const float* edges = (const float*)d_in[0];
    const float* bbse  = (const float*)d_in[1];
    const void*  gm    = d_in[2];
    const void*  cm    = d_in[3];
    const float* gWq = (const float*)d_in[4];  const float* gbq = (const float*)d_in[5];
    const float* gWk = (const float*)d_in[6];  const float* gbk = (const float*)d_in[7];
    const float* gWv = (const float*)d_in[8];  const float* gbv = (const float*)d_in[9];
    const float* gWo = (const float*)d_in[10]; const float* gbo = (const float*)d_in[11];
    const float* cWq = (const float*)d_in[12]; const float* cbq = (const float*)d_in[13];
    const float* cWk = (const float*)d_in[14]; const float* cbk = (const float*)d_in[15];
    const float* cWv = (const float*)d_in[16]; const float* cbv = (const float*)d_in[17];
    const float* cWo = (const float*)d_in[18]; const float* cbo = (const float*)d_in[19];
    const float* fW1 = (const float*)d_in[20]; const float* fb1 = (const float*)d_in[21];
    const float* fW2 = (const float*)d_in[22]; const float* fb2 = (const float*)d_in[23];
    float* out = (float*)d_out;

    float *X, *Q, *Kb, *V, *AO, *Sc;
    unsigned char *m8g, *m8c;
    cudaGetSymbolAddress((void**)&X,  g_X);
    cudaGetSymbolAddress((void**)&Q,  g_Q);
    cudaGetSymbolAddress((void**)&Kb, g_K);
    cudaGetSymbolAddress((void**)&V,  g_V);
    cudaGetSymbolAddress((void**)&AO, g_AO);
    cudaGetSymbolAddress((void**)&Sc, g_S);
    cudaGetSymbolAddress((void**)&m8g, g_m8g);
    cudaGetSymbolAddress((void**)&m8c, g_m8c);

    cudaFuncSetAttribute(gemm_tf32_nt<0,0>, cudaFuncAttributeMaxDynamicSharedMemorySize, SMEM_GEMM);
    cudaFuncSetAttribute(gemm_tf32_nt<0,1>, cudaFuncAttributeMaxDynamicSharedMemorySize, SMEM_GEMM);
    cudaFuncSetAttribute(gemm_tf32_nt<1,0>, cudaFuncAttributeMaxDynamicSharedMemorySize, SMEM_GEMM);
    cudaFuncSetAttribute(flash_tf32<0>,     cudaFuncAttributeMaxDynamicSharedMemorySize, SMEM_FLASH);
    cudaFuncSetAttribute(flash_tf32<1>,     cudaFuncAttributeMaxDynamicSharedMemorySize, SMEM_FLASH);

    // masks -> canonical uint8
    detect_kernel<<<1, 32>>>((const unsigned char*)gm, (const unsigned char*)cm);
    convert_mask_kernel<<<64, 256>>>(gm, m8g, 16384, 0);
    convert_mask_kernel<<<16384, 256>>>(cm, m8c, 4194304, 1);

    const int M = 16384;  // B*S tokens

    // ---- 1. global edge-edge self-attention ----
    inorm_kernel<<<M, 128>>>(edges, X);
    gemm_tf32_nt<0, 0><<<dim3(4, 128), 256, SMEM_GEMM>>>(X, 512, gWq, 512, gbq, nullptr, Q,  512, 512);
    gemm_tf32_nt<0, 0><<<dim3(4, 128), 256, SMEM_GEMM>>>(X, 512, gWk, 512, gbk, nullptr, Kb, 512, 512);
    gemm_tf32_nt<0, 0><<<dim3(4, 128), 256, SMEM_GEMM>>>(X, 512, gWv, 512, gbv, nullptr, V,  512, 512);
    flash_tf32<0><<<dim3(8, 64), 256, SMEM_FLASH>>>(Q, Kb, V, m8g, AO, 1024, 524288);
    gemm_tf32_nt<0, 1><<<dim3(4, 128), 256, SMEM_GEMM>>>(AO, 512, gWo, 512, gbo, edges, out, 512, 512);

    // ---- 2. cross-attention from bb semantics ----
    inorm_kernel<<<M, 128>>>(out, X);
    gemm_tf32_nt<0, 0><<<dim3(4, 128), 256, SMEM_GEMM>>>(X,    512, cWq, 512, cbq, nullptr, Q,  512, 512);
    gemm_tf32_nt<0, 0><<<dim3(4, 32),  256, SMEM_GEMM>>>(bbse, 512, cWk, 512, cbk, nullptr, Kb, 512, 512);
    gemm_tf32_nt<0, 0><<<dim3(4, 32),  256, SMEM_GEMM>>>(bbse, 512, cWv, 512, cbv, nullptr, V,  512, 512);
    flash_tf32<1><<<dim3(8, 64), 256, SMEM_FLASH>>>(Q, Kb, V, m8c, AO, 256, 131072);
    gemm_tf32_nt<0, 1><<<dim3(4, 128), 256, SMEM_GEMM>>>(AO, 512, cWo, 512, cbo, out, out, 512, 512);

    // ---- 3. FFN ----
    inorm_kernel<<<M, 128>>>(out, X);
    gemm_tf32_nt<1, 0><<<dim3(16, 128), 256, SMEM_GEMM>>>(X,  512,  fW1, 512,  fb1, nullptr, Sc,  2048, 512);
    gemm_tf32_nt<0, 1><<<dim3(4, 128),  256, SMEM_GEMM>>>(Sc, 2048, fW2, 2048, fb2, out,     out, 512,  2048);
}

// round 12
// speedup vs baseline: 5.7141x; 1.5185x over previous
#include <cuda_runtime.h>
#include <cuda_fp16.h>

// Problem constants
//   B=16, N=32, D=512, H=4, SB=256, S=N*N=1024, DS=128
// Output: edges (16,1024,512) f32

// ---------------- static scratch (no allocations allowed) ----------------
__device__ float g_X [8388608];    // X16 (fp16 view): inorm output
__device__ float g_Q [8388608];    // Q16
__device__ float g_K [8388608];    // K16
__device__ float g_V [8388608];    // V16
__device__ float g_AO[8388608];    // AO16
__device__ float g_S [67108864];   // hidden16 (FFN)
__device__ __half g_W16[6291456];  // fp16 weights (10 mats) + bbse16
__device__ unsigned char g_m8g[16384];    // global mask, flattened g (B,S)
__device__ unsigned char g_m8c[4194304];  // cross mask (B,S,SB)
__device__ int g_mtype[2];

// W16 offsets (halves)
#define WO_GQ 0
#define WO_GK 262144
#define WO_GV 524288
#define WO_GO 786432
#define WO_CQ 1048576
#define WO_CK 1310720
#define WO_CV 1572864
#define WO_CO 1835008
#define WO_F1 2097152
#define WO_F2 3145728
#define WO_BB 4194304

// ---------------- cp.async / ldmatrix / mma helpers ----------------
#define CPA(dst, src) asm volatile("cp.async.cg.shared.global [%0], [%1], 16;" :: "r"(dst), "l"(src))
#define CPC()         asm volatile("cp.async.commit_group;")
#define CPW(n)        asm volatile("cp.async.wait_group %0;" :: "n"(n))
#define LDM4(r0, r1, r2, r3, addr) \
    asm volatile("ldmatrix.sync.aligned.m8n8.x4.shared.b16 {%0,%1,%2,%3}, [%4];" \
        : "=r"(r0), "=r"(r1), "=r"(r2), "=r"(r3) : "r"(addr))
#define LDM4T(r0, r1, r2, r3, addr) \
    asm volatile("ldmatrix.sync.aligned.m8n8.x4.trans.shared.b16 {%0,%1,%2,%3}, [%4];" \
        : "=r"(r0), "=r"(r1), "=r"(r2), "=r"(r3) : "r"(addr))

__device__ __forceinline__ void mma16(float* c, const unsigned* a, const unsigned* b) {
    asm volatile(
        "mma.sync.aligned.m16n8k16.row.col.f32.f16.f16.f32 "
        "{%0,%1,%2,%3}, {%4,%5,%6,%7}, {%8,%9}, {%0,%1,%2,%3};"
        : "+f"(c[0]), "+f"(c[1]), "+f"(c[2]), "+f"(c[3])
        : "r"(a[0]), "r"(a[1]), "r"(a[2]), "r"(a[3]), "r"(b[0]), "r"(b[1]));
}

__device__ __forceinline__ unsigned packh2(float lo, float hi) {
    __half2 h = __floats2half2_rn(lo, hi);   // .x = lo (low 16 bits)
    return *(unsigned*)&h;
}

// ---------------- mask dtype detection + conversion ----------------
__device__ int classify_bytes(const unsigned char* p) {
    bool big = false, bf16sig = false;
    int ones = 0;
    for (int i = 0; i < 256; i++) {
        unsigned char v = p[i];
        if (v > 1) big = true;
        if (v == 1) ones++;
        if (v == 0x3F && (i & 3) == 1) bf16sig = true;
    }
    if (big) return bf16sig ? 3 : 2;
    return (ones > 96) ? 0 : 1;
}

__global__ void detect_kernel(const unsigned char* gm, const unsigned char* cm) {
    if (threadIdx.x == 0) {
        g_mtype[0] = classify_bytes(gm);
        g_mtype[1] = classify_bytes(cm);
    }
}

__global__ void convert_mask_kernel(const void* src, unsigned char* dst, int n, int which) {
    int i = blockIdx.x * blockDim.x + threadIdx.x;
    if (i >= n) return;
    int t = g_mtype[which];
    unsigned char v;
    if (t == 0)      v = ((const unsigned char*)src)[i] != 0;
    else if (t == 1) v = ((const int*)src)[i] != 0;
    else if (t == 3) v = ((const unsigned short*)src)[i] != 0;
    else             v = ((const float*)src)[i] != 0.0f;
    dst[i] = v;
}

// ---------------- f32 -> fp16 bulk conversion of weights + bbse ----------------
// 24 segments of 262144 elems. grid (256, 24), 256 thr, 4 elems/thread.
__global__ void convert_w_kernel(
    const float* a0, const float* a1, const float* a2, const float* a3,
    const float* a4, const float* a5, const float* a6, const float* a7,
    const float* f1, const float* f2, const float* bb, __half* dst)
{
    const float* tab[8] = {a0, a1, a2, a3, a4, a5, a6, a7};
    int seg = blockIdx.y;
    const float* src;
    if (seg < 8)       src = tab[seg];
    else if (seg < 12) src = f1 + (seg - 8) * 262144;
    else if (seg < 16) src = f2 + (seg - 12) * 262144;
    else               src = bb + (seg - 16) * 262144;
    int idx = (blockIdx.x * 256 + threadIdx.x) * 4;
    float4 v = *(const float4*)(src + idx);
    __half2 h0 = __floats2half2_rn(v.x, v.y);
    __half2 h1 = __floats2half2_rn(v.z, v.w);
    uint2 o = {*(unsigned*)&h0, *(unsigned*)&h1};
    *(uint2*)(dst + (size_t)seg * 262144 + idx) = o;
}

// ---------------- instance norm over D=512, fp16 output ----------------
__global__ void inorm_kernel(const float* __restrict__ x, __half* __restrict__ y) {
    const size_t base = (size_t)blockIdx.x * 512;
    const int tid = threadIdx.x;   // 128 threads
    float v[4];
    float s = 0.f, s2 = 0.f;
#pragma unroll
    for (int i = 0; i < 4; i++) {
        float a = x[base + tid + i * 128];
        v[i] = a; s += a; s2 += a * a;
    }
#pragma unroll
    for (int o = 16; o > 0; o >>= 1) {
        s  += __shfl_xor_sync(0xffffffffu, s,  o);
        s2 += __shfl_xor_sync(0xffffffffu, s2, o);
    }
    __shared__ float sh[8];
    int w = tid >> 5;
    if ((tid & 31) == 0) { sh[w] = s; sh[4 + w] = s2; }
    __syncthreads();
    s  = sh[0] + sh[1] + sh[2] + sh[3];
    s2 = sh[4] + sh[5] + sh[6] + sh[7];
    float mean = s * (1.f / 512.f);
    float var  = s2 * (1.f / 512.f) - mean * mean;
    float inv  = rsqrtf(var + 1e-5f);
#pragma unroll
    for (int i = 0; i < 4; i++)
        y[base + tid + i * 128] = __float2half_rn((v[i] - mean) * inv);
}

// ================= FP16 GEMM-NT, cp.async 3-stage, ldmatrix, m16n8k16 ============
// C = [res +] A(MxK) * W(NxK)^T + bias [, relu].  Block 128x128x32, 256 thr,
// 8 warps (2m x 4n), warp tile 64x32. Smem tiles [128][32+8] halves.
#define ASTB 10240    // bytes per 128x40-half stage

template<int RELU, int HASRES, int OUTF16>
__global__ void __launch_bounds__(256) gemm_fp16_nt(
    const __half* __restrict__ A, int lda,
    const __half* __restrict__ W, int ldw,
    const float* __restrict__ bias,
    const float* __restrict__ res,
    void* __restrict__ Cv, int ldc, int K)
{
    extern __shared__ __half smh[];
    const unsigned a_smem = (unsigned)__cvta_generic_to_shared(smh);
    const unsigned b_smem = a_smem + 3 * ASTB;
    const int tid = threadIdx.x, lane = tid & 31, wid = tid >> 5;
    const int wm = (wid & 1) * 64, wn = (wid >> 1) * 32;
    const int m0 = blockIdx.y * 128, n0 = blockIdx.x * 128;

    // ldmatrix geometry (halves)
    const int t8 = lane >> 3, l8 = lane & 7;
    const int ra = l8 + (t8 & 1) * 8, ca = (t8 >> 1) * 8;   // A: rows split, then k8
    const int rb = l8 + (t8 >> 1) * 8, cb = (t8 & 1) * 8;   // B: k8 split, then n+8
    unsigned aBase[4], bBase[2];
#pragma unroll
    for (int mi = 0; mi < 4; mi++)
        aBase[mi] = a_smem + (unsigned)(((wm + mi * 16 + ra) * 40 + ca) * 2);
#pragma unroll
    for (int p = 0; p < 2; p++)
        bBase[p] = b_smem + (unsigned)(((wn + p * 16 + rb) * 40 + cb) * 2);

    const int nt = K >> 5;   // 32-wide k chunks

    auto load_tile = [&](int s, int kt) {
        const int k0 = kt * 32;
#pragma unroll
        for (int i = 0; i < 2; i++) {
            int id = tid + i * 256;
            int row = id >> 2, c8 = (id & 3) * 8;
            CPA(a_smem + (unsigned)(s * ASTB + (row * 40 + c8) * 2),
                A + (size_t)(m0 + row) * lda + k0 + c8);
            CPA(b_smem + (unsigned)(s * ASTB + (row * 40 + c8) * 2),
                W + (size_t)(n0 + row) * ldw + k0 + c8);
        }
    };

    load_tile(0, 0); CPC();
    load_tile(1, 1); CPC();

    float acc[4][4][4] = {};
    for (int kt = 0; kt < nt; kt++) {
        CPW(1);
        __syncthreads();
        if (kt + 2 < nt) load_tile((kt + 2) % 3, kt + 2);
        CPC();
        const unsigned stg = (unsigned)((kt % 3) * ASTB);
#pragma unroll
        for (int kc = 0; kc < 2; kc++) {      // two k16 slices
            unsigned af[4][4], bf[4][2];
#pragma unroll
            for (int mi = 0; mi < 4; mi++)
                LDM4(af[mi][0], af[mi][1], af[mi][2], af[mi][3],
                     aBase[mi] + stg + kc * 32);
#pragma unroll
            for (int p = 0; p < 2; p++)
                LDM4(bf[2 * p][0], bf[2 * p][1], bf[2 * p + 1][0], bf[2 * p + 1][1],
                     bBase[p] + stg + kc * 32);
#pragma unroll
            for (int mi = 0; mi < 4; mi++)
#pragma unroll
                for (int ni = 0; ni < 4; ni++)
                    mma16(acc[mi][ni], af[mi], bf[ni]);
        }
        __syncthreads();
    }

#pragma unroll
    for (int mi = 0; mi < 4; mi++)
#pragma unroll
        for (int ni = 0; ni < 4; ni++) {
            int row = m0 + wm + mi * 16 + (lane >> 2);
            int col = n0 + wn + ni * 8 + 2 * (lane & 3);
            float b0v = bias[col], b1v = bias[col + 1];
            float v0 = acc[mi][ni][0] + b0v, v1 = acc[mi][ni][1] + b1v;
            float v2 = acc[mi][ni][2] + b0v, v3 = acc[mi][ni][3] + b1v;
            if (HASRES) {
                float2 r0 = *(const float2*)&res[(size_t)row * ldc + col];
                float2 r1 = *(const float2*)&res[(size_t)(row + 8) * ldc + col];
                v0 += r0.x; v1 += r0.y; v2 += r1.x; v3 += r1.y;
            }
            if (RELU) {
                v0 = fmaxf(v0, 0.f); v1 = fmaxf(v1, 0.f);
                v2 = fmaxf(v2, 0.f); v3 = fmaxf(v3, 0.f);
            }
            if (OUTF16) {
                __half* C = (__half*)Cv;
                __half2 h0 = __floats2half2_rn(v0, v1);
                __half2 h1 = __floats2half2_rn(v2, v3);
                *(__half2*)&C[(size_t)row * ldc + col]       = h0;
                *(__half2*)&C[(size_t)(row + 8) * ldc + col] = h1;
            } else {
                float* C = (float*)Cv;
                float2 o0 = {v0, v1}, o1 = {v2, v3};
                *(float2*)&C[(size_t)row * ldc + col]       = o0;
                *(float2*)&C[(size_t)(row + 8) * ldc + col] = o1;
            }
        }
}

// ================= Fused flash attention (fp16 MMA, online softmax) ==============
// One block = (128 q-rows, one b*h). 8 warps, warp owns 16 q-rows x full KV sweep.
// KV tiles of 64, double-buffered cp.async. Q resident in smem + register frags.
// P packs straight from the S accumulator (no shuffles); V via ldmatrix.trans.
// smem: Q 128x136h | K 2x64x136h | V 2x64x136h  = 104448 B.
#define QB 34816
#define KB 17408

template<int MODE>   // 0: global outer-product mask, 1: cross mask
__global__ void __launch_bounds__(256) flash_fp16(
    const __half* __restrict__ Qg, const __half* __restrict__ Kg,
    const __half* __restrict__ Vg, const unsigned char* __restrict__ mask,
    __half* __restrict__ O, int Lk, int kvstride)
{
    extern __shared__ __half smh[];
    const unsigned q_sm = (unsigned)__cvta_generic_to_shared(smh);
    const unsigned k_sm = q_sm + QB;
    const unsigned v_sm = k_sm + 2 * KB;
    const int tid = threadIdx.x, lane = tid & 31, wid = tid >> 5;
    const int l = lane & 3, r4 = lane >> 2;
    const int b = blockIdx.y >> 2, h = blockIdx.y & 3;
    const int q0 = blockIdx.x * 128;
    const __half* Qp = Qg + (size_t)b * 524288 + (size_t)q0 * 512 + h * 128;
    const __half* Kp = Kg + (size_t)b * kvstride + h * 128;
    const __half* Vp = Vg + (size_t)b * kvstride + h * 128;

    // ldmatrix geometry
    const int t8 = lane >> 3, l8 = lane & 7;
    const int ra = l8 + (t8 & 1) * 8, ca = (t8 >> 1) * 8;    // Q (A-type)
    const int rb = l8 + (t8 >> 1) * 8, cb = (t8 & 1) * 8;    // K (B-type)
    const int vr = l8 + (t8 & 1) * 8, vc = (t8 >> 1) * 8;    // V (trans B-type)
    const unsigned qBase = q_sm + (unsigned)(((wid * 16 + ra) * 136 + ca) * 2);
    unsigned kBase[4];
#pragma unroll
    for (int p = 0; p < 4; p++)
        kBase[p] = k_sm + (unsigned)(((p * 16 + rb) * 136 + cb) * 2);
    const unsigned vBase0 = v_sm + (unsigned)((vr * 136 + vc) * 2);

    // ---- load Q tile (128x128 halves) ----
#pragma unroll
    for (int i = 0; i < 8; i++) {
        int id = tid + i * 256;
        int row = id >> 4, c8 = (id & 15) * 8;
        CPA(q_sm + (unsigned)((row * 136 + c8) * 2), Qp + (size_t)row * 512 + c8);
    }
    auto loadKV = [&](int st, int t) {
        const int kv0 = t * 64;
#pragma unroll
        for (int i = 0; i < 4; i++) {
            int id = tid + i * 256;
            int row = id >> 4, c8 = (id & 15) * 8;
            CPA(k_sm + (unsigned)(st * KB + (row * 136 + c8) * 2),
                Kp + (size_t)(kv0 + row) * 512 + c8);
            CPA(v_sm + (unsigned)(st * KB + (row * 136 + c8) * 2),
                Vp + (size_t)(kv0 + row) * 512 + c8);
        }
    };
    const int nt = Lk >> 6;
    loadKV(0, 0); CPC();          // group0 = Q + KV0
    loadKV(1, 1); CPC();          // group1 = KV1

    // per-warp row info
    const int rowg0 = q0 + wid * 16 + r4;
    const int rowg1 = rowg0 + 8;
    unsigned char qok0 = 1, qok1 = 1;
    if (MODE == 0) { qok0 = mask[b * 1024 + rowg0]; qok1 = mask[b * 1024 + rowg1]; }
    const unsigned char* mrow0 = mask + ((size_t)(b * 1024 + rowg0)) * 256;
    const unsigned char* mrow1 = mask + ((size_t)(b * 1024 + rowg1)) * 256;

    CPW(1);
    __syncthreads();              // Q + KV0 ready

    // preload Q fragments (8 k16-chunks)
    unsigned qf[8][4];
#pragma unroll
    for (int kc = 0; kc < 8; kc++)
        LDM4(qf[kc][0], qf[kc][1], qf[kc][2], qf[kc][3], qBase + kc * 32);

    float oacc[16][4] = {};
    float m0 = -INFINITY, m1 = -INFINITY, l0 = 0.f, l1 = 0.f;
    const float scale = 0.08838834764831845f;   // 1/sqrt(128)

    for (int t = 0; t < nt; t++) {
        if (t > 0) { CPW(1); __syncthreads(); }
        const int st = t & 1;
        const unsigned kstg = (unsigned)(st * KB);
        const int kv0 = t * 64;

        // ---- S = Q K^T (16 rows x 64 kv cols per warp) ----
        float sacc[8][4] = {};
#pragma unroll
        for (int kc = 0; kc < 8; kc++) {
            unsigned bf[8][2];
#pragma unroll
            for (int p = 0; p < 4; p++)
                LDM4(bf[2 * p][0], bf[2 * p][1], bf[2 * p + 1][0], bf[2 * p + 1][1],
                     kBase[p] + kstg + kc * 32);
#pragma unroll
            for (int nn = 0; nn < 8; nn++)
                mma16(sacc[nn], qf[kc], bf[nn]);
        }

        // ---- mask + scale + online softmax ----
        float tmax0 = -INFINITY, tmax1 = -INFINITY;
#pragma unroll
        for (int nn = 0; nn < 8; nn++) {
            int col = kv0 + nn * 8 + 2 * l;
            bool ok00, ok01, ok10, ok11;
            if (MODE == 0) {
                bool ka = mask[b * 1024 + col] != 0;
                bool kb = mask[b * 1024 + col + 1] != 0;
                ok00 = qok0 && ka; ok01 = qok0 && kb;
                ok10 = qok1 && ka; ok11 = qok1 && kb;
            } else {
                ok00 = mrow0[col] != 0; ok01 = mrow0[col + 1] != 0;
                ok10 = mrow1[col] != 0; ok11 = mrow1[col + 1] != 0;
            }
            sacc[nn][0] = ok00 ? sacc[nn][0] * scale : -1e9f;
            sacc[nn][1] = ok01 ? sacc[nn][1] * scale : -1e9f;
            sacc[nn][2] = ok10 ? sacc[nn][2] * scale : -1e9f;
            sacc[nn][3] = ok11 ? sacc[nn][3] * scale : -1e9f;
            tmax0 = fmaxf(tmax0, fmaxf(sacc[nn][0], sacc[nn][1]));
            tmax1 = fmaxf(tmax1, fmaxf(sacc[nn][2], sacc[nn][3]));
        }
        tmax0 = fmaxf(tmax0, __shfl_xor_sync(0xffffffffu, tmax0, 1));
        tmax0 = fmaxf(tmax0, __shfl_xor_sync(0xffffffffu, tmax0, 2));
        tmax1 = fmaxf(tmax1, __shfl_xor_sync(0xffffffffu, tmax1, 1));
        tmax1 = fmaxf(tmax1, __shfl_xor_sync(0xffffffffu, tmax1, 2));
        float mn0 = fmaxf(m0, tmax0), mn1 = fmaxf(m1, tmax1);
        float al0 = __expf(m0 - mn0), al1 = __expf(m1 - mn1);
        float rs0 = 0.f, rs1 = 0.f;
#pragma unroll
        for (int nn = 0; nn < 8; nn++) {
            sacc[nn][0] = __expf(sacc[nn][0] - mn0);
            sacc[nn][1] = __expf(sacc[nn][1] - mn0);
            sacc[nn][2] = __expf(sacc[nn][2] - mn1);
            sacc[nn][3] = __expf(sacc[nn][3] - mn1);
            rs0 += sacc[nn][0] + sacc[nn][1];
            rs1 += sacc[nn][2] + sacc[nn][3];
        }
        rs0 += __shfl_xor_sync(0xffffffffu, rs0, 1);
        rs0 += __shfl_xor_sync(0xffffffffu, rs0, 2);
        rs1 += __shfl_xor_sync(0xffffffffu, rs1, 1);
        rs1 += __shfl_xor_sync(0xffffffffu, rs1, 2);
        l0 = l0 * al0 + rs0; l1 = l1 * al1 + rs1;
        m0 = mn0; m1 = mn1;
#pragma unroll
        for (int nn = 0; nn < 16; nn++) {
            oacc[nn][0] *= al0; oacc[nn][1] *= al0;
            oacc[nn][2] *= al1; oacc[nn][3] *= al1;
        }

        // ---- O += P V   (P fragments packed in-lane; V via ldmatrix.trans) ----
        const unsigned vst = (unsigned)(st * KB);
#pragma unroll
        for (int kc2 = 0; kc2 < 4; kc2++) {   // kv k16 chunks
            unsigned au[4];
            au[0] = packh2(sacc[2 * kc2][0],     sacc[2 * kc2][1]);
            au[1] = packh2(sacc[2 * kc2][2],     sacc[2 * kc2][3]);
            au[2] = packh2(sacc[2 * kc2 + 1][0], sacc[2 * kc2 + 1][1]);
            au[3] = packh2(sacc[2 * kc2 + 1][2], sacc[2 * kc2 + 1][3]);
#pragma unroll
            for (int g = 0; g < 8; g++) {     // n16 groups over head dim 128
                unsigned r0, r1, r2, r3;
                LDM4T(r0, r1, r2, r3, vBase0 + vst + kc2 * 4352 + g * 32);
                unsigned b0[2] = {r0, r1}, b1[2] = {r2, r3};
                mma16(oacc[2 * g],     au, b0);
                mma16(oacc[2 * g + 1], au, b1);
            }
        }

        __syncthreads();                      // all warps done with stage st
        if (t + 2 < nt) loadKV(st, t + 2);
        CPC();
    }

    // ---- epilogue: O /= l, write fp16 ----
    float inv0 = 1.f / l0, inv1 = 1.f / l1;
#pragma unroll
    for (int nn = 0; nn < 16; nn++) {
        int col = h * 128 + nn * 8 + 2 * l;
        __half2 h0 = __floats2half2_rn(oacc[nn][0] * inv0, oacc[nn][1] * inv0);
        __half2 h1 = __floats2half2_rn(oacc[nn][2] * inv1, oacc[nn][3] * inv1);
        *(__half2*)&O[(size_t)b * 524288 + (size_t)rowg0 * 512 + col] = h0;
        *(__half2*)&O[(size_t)b * 524288 + (size_t)rowg1 * 512 + col] = h1;
    }
}

// ---------------- launch ----------------
static const int SMEM_GEMM  = 6 * ASTB;          // 61440
static const int SMEM_FLASH = QB + 4 * KB;       // 104448

extern "C" void kernel_launch(void* const* d_in, const int* in_sizes, int n_in,
                              void* d_out, int out_size) {
    const float* edges = (const float*)d_in[0];
    const float* bbse  = (const float*)d_in[1];
    const void*  gm    = d_in[2];
    const void*  cm    = d_in[3];
    const float* gWq = (const float*)d_in[4];  const float* gbq = (const float*)d_in[5];
    const float* gWk = (const float*)d_in[6];  const float* gbk = (const float*)d_in[7];
    const float* gWv = (const float*)d_in[8];  const float* gbv = (const float*)d_in[9];
    const float* gWo = (const float*)d_in[10]; const float* gbo = (const float*)d_in[11];
    const float* cWq = (const float*)d_in[12]; const float* cbq = (const float*)d_in[13];
    const float* cWk = (const float*)d_in[14]; const float* cbk = (const float*)d_in[15];
    const float* cWv = (const float*)d_in[16]; const float* cbv = (const float*)d_in[17];
    const float* cWo = (const float*)d_in[18]; const float* cbo = (const float*)d_in[19];
    const float* fW1 = (const float*)d_in[20]; const float* fb1 = (const float*)d_in[21];
    const float* fW2 = (const float*)d_in[22]; const float* fb2 = (const float*)d_in[23];
    float* out = (float*)d_out;

    void *Xa, *Qa, *Ka, *Va, *AOa, *Sa, *Wa;
    unsigned char *m8g, *m8c;
    cudaGetSymbolAddress(&Xa,  g_X);
    cudaGetSymbolAddress(&Qa,  g_Q);
    cudaGetSymbolAddress(&Ka,  g_K);
    cudaGetSymbolAddress(&Va,  g_V);
    cudaGetSymbolAddress(&AOa, g_AO);
    cudaGetSymbolAddress(&Sa,  g_S);
    cudaGetSymbolAddress(&Wa,  g_W16);
    cudaGetSymbolAddress((void**)&m8g, g_m8g);
    cudaGetSymbolAddress((void**)&m8c, g_m8c);
    __half* X16  = (__half*)Xa;
    __half* Q16  = (__half*)Qa;
    __half* K16  = (__half*)Ka;
    __half* V16  = (__half*)Va;
    __half* AO16 = (__half*)AOa;
    __half* H16  = (__half*)Sa;
    __half* W16  = (__half*)Wa;

    cudaFuncSetAttribute(gemm_fp16_nt<0,0,1>, cudaFuncAttributeMaxDynamicSharedMemorySize, SMEM_GEMM);
    cudaFuncSetAttribute(gemm_fp16_nt<0,1,0>, cudaFuncAttributeMaxDynamicSharedMemorySize, SMEM_GEMM);
    cudaFuncSetAttribute(gemm_fp16_nt<1,0,1>, cudaFuncAttributeMaxDynamicSharedMemorySize, SMEM_GEMM);
    cudaFuncSetAttribute(flash_fp16<0>,       cudaFuncAttributeMaxDynamicSharedMemorySize, SMEM_FLASH);
    cudaFuncSetAttribute(flash_fp16<1>,       cudaFuncAttributeMaxDynamicSharedMemorySize, SMEM_FLASH);

    // masks -> canonical uint8; weights/bbse -> fp16
    detect_kernel<<<1, 32>>>((const unsigned char*)gm, (const unsigned char*)cm);
    convert_mask_kernel<<<64, 256>>>(gm, m8g, 16384, 0);
    convert_mask_kernel<<<16384, 256>>>(cm, m8c, 4194304, 1);
    convert_w_kernel<<<dim3(256, 24), 256>>>(gWq, gWk, gWv, gWo, cWq, cWk, cWv, cWo,
                                             fW1, fW2, bbse, W16);

    const int M = 16384;  // B*S tokens
    const __half* B16 = W16 + WO_BB;

    // ---- 1. global edge-edge self-attention ----
    inorm_kernel<<<M, 128>>>(edges, X16);
    gemm_fp16_nt<0,0,1><<<dim3(4, 128), 256, SMEM_GEMM>>>(X16, 512, W16 + WO_GQ, 512, gbq, nullptr, Q16, 512, 512);
    gemm_fp16_nt<0,0,1><<<dim3(4, 128), 256, SMEM_GEMM>>>(X16, 512, W16 + WO_GK, 512, gbk, nullptr, K16, 512, 512);
    gemm_fp16_nt<0,0,1><<<dim3(4, 128), 256, SMEM_GEMM>>>(X16, 512, W16 + WO_GV, 512, gbv, nullptr, V16, 512, 512);
    flash_fp16<0><<<dim3(8, 64), 256, SMEM_FLASH>>>(Q16, K16, V16, m8g, AO16, 1024, 524288);
    gemm_fp16_nt<0,1,0><<<dim3(4, 128), 256, SMEM_GEMM>>>(AO16, 512, W16 + WO_GO, 512, gbo, edges, out, 512, 512);

    // ---- 2. cross-attention from bb semantics ----
    inorm_kernel<<<M, 128>>>(out, X16);
    gemm_fp16_nt<0,0,1><<<dim3(4, 128), 256, SMEM_GEMM>>>(X16, 512, W16 + WO_CQ, 512, cbq, nullptr, Q16, 512, 512);
    gemm_fp16_nt<0,0,1><<<dim3(4, 32),  256, SMEM_GEMM>>>(B16, 512, W16 + WO_CK, 512, cbk, nullptr, K16, 512, 512);
    gemm_fp16_nt<0,0,1><<<dim3(4, 32),  256, SMEM_GEMM>>>(B16, 512, W16 + WO_CV, 512, cbv, nullptr, V16, 512, 512);
    flash_fp16<1><<<dim3(8, 64), 256, SMEM_FLASH>>>(Q16, K16, V16, m8c, AO16, 256, 131072);
    gemm_fp16_nt<0,1,0><<<dim3(4, 128), 256, SMEM_GEMM>>>(AO16, 512, W16 + WO_CO, 512, cbo, out, out, 512, 512);

    // ---- 3. FFN ----
    inorm_kernel<<<M, 128>>>(out, X16);
    gemm_fp16_nt<1,0,1><<<dim3(16, 128), 256, SMEM_GEMM>>>(X16, 512,  W16 + WO_F1, 512,  fb1, nullptr, H16, 2048, 512);
    gemm_fp16_nt<0,1,0><<<dim3(4, 128),  256, SMEM_GEMM>>>(H16, 2048, W16 + WO_F2, 2048, fb2, out,     out, 512,  2048);
}

// round 14
// speedup vs baseline: 5.7807x; 1.0117x over previous
#include <cuda_runtime.h>
#include <cuda_fp16.h>

// Problem constants
//   B=16, N=32, D=512, H=4, SB=256, S=N*N=1024, DS=128
// Output: edges (16,1024,512) f32

// ---------------- static scratch (no allocations allowed) ----------------
__device__ float g_X [8388608];    // X16 (fp16 view): inorm output
__device__ float g_Q [8388608];    // cross-Q16
__device__ float g_K [8388608];    // cross-KV16 (4096 x 1024)
__device__ float g_AO[8388608];    // AO16
__device__ float g_S [67108864];   // QKV16 (16384x1536) / FFN hidden16
__device__ __half g_W16[6291456];  // fp16 weights (10 mats) + bbse16
__device__ float g_bcat[4096];     // concat biases: [0..1536) g qkv, [2048..3072) c kv
__device__ unsigned char g_m8g[16384];    // global mask, flattened g (B,S)
__device__ unsigned char g_m8c[4194304];  // cross mask (B,S,SB)
__device__ int g_mtype[2];

// W16 offsets (halves)
#define WO_GQ 0
#define WO_GK 262144
#define WO_GV 524288
#define WO_GO 786432
#define WO_CQ 1048576
#define WO_CK 1310720
#define WO_CV 1572864
#define WO_CO 1835008
#define WO_F1 2097152
#define WO_F2 3145728
#define WO_BB 4194304

// ---------------- cp.async / ldmatrix / mma helpers ----------------
#define CPA(dst, src) asm volatile("cp.async.cg.shared.global [%0], [%1], 16;" :: "r"(dst), "l"(src))
#define CPC()         asm volatile("cp.async.commit_group;")
#define CPW(n)        asm volatile("cp.async.wait_group %0;" :: "n"(n))
#define LDM4(r0, r1, r2, r3, addr) \
    asm volatile("ldmatrix.sync.aligned.m8n8.x4.shared.b16 {%0,%1,%2,%3}, [%4];" \
        : "=r"(r0), "=r"(r1), "=r"(r2), "=r"(r3) : "r"(addr))
#define LDM4T(r0, r1, r2, r3, addr) \
    asm volatile("ldmatrix.sync.aligned.m8n8.x4.trans.shared.b16 {%0,%1,%2,%3}, [%4];" \
        : "=r"(r0), "=r"(r1), "=r"(r2), "=r"(r3) : "r"(addr))

__device__ __forceinline__ void mma16(float* c, const unsigned* a, const unsigned* b) {
    asm volatile(
        "mma.sync.aligned.m16n8k16.row.col.f32.f16.f16.f32 "
        "{%0,%1,%2,%3}, {%4,%5,%6,%7}, {%8,%9}, {%0,%1,%2,%3};"
        : "+f"(c[0]), "+f"(c[1]), "+f"(c[2]), "+f"(c[3])
        : "r"(a[0]), "r"(a[1]), "r"(a[2]), "r"(a[3]), "r"(b[0]), "r"(b[1]));
}

__device__ __forceinline__ unsigned packh2(float lo, float hi) {
    __half2 h = __floats2half2_rn(lo, hi);
    return *(unsigned*)&h;
}

// ---------------- mask dtype detection + conversion ----------------
__device__ int classify_bytes(const unsigned char* p) {
    bool big = false, bf16sig = false;
    int ones = 0;
    for (int i = 0; i < 256; i++) {
        unsigned char v = p[i];
        if (v > 1) big = true;
        if (v == 1) ones++;
        if (v == 0x3F && (i & 3) == 1) bf16sig = true;
    }
    if (big) return bf16sig ? 3 : 2;
    return (ones > 96) ? 0 : 1;
}

__global__ void detect_kernel(const unsigned char* gm, const unsigned char* cm) {
    if (threadIdx.x == 0) {
        g_mtype[0] = classify_bytes(gm);
        g_mtype[1] = classify_bytes(cm);
    }
}

__global__ void convert_mask_kernel(const void* src, unsigned char* dst, int n, int which) {
    int i = blockIdx.x * blockDim.x + threadIdx.x;
    if (i >= n) return;
    int t = g_mtype[which];
    unsigned char v;
    if (t == 0)      v = ((const unsigned char*)src)[i] != 0;
    else if (t == 1) v = ((const int*)src)[i] != 0;
    else if (t == 3) v = ((const unsigned short*)src)[i] != 0;
    else             v = ((const float*)src)[i] != 0.0f;
    dst[i] = v;
}

// ---------------- f32 -> fp16 bulk conversion of weights + bbse ----------------
__global__ void convert_w_kernel(
    const float* a0, const float* a1, const float* a2, const float* a3,
    const float* a4, const float* a5, const float* a6, const float* a7,
    const float* f1, const float* f2, const float* bb, __half* dst)
{
    const float* tab[8] = {a0, a1, a2, a3, a4, a5, a6, a7};
    int seg = blockIdx.y;
    const float* src;
    if (seg < 8)       src = tab[seg];
    else if (seg < 12) src = f1 + (seg - 8) * 262144;
    else if (seg < 16) src = f2 + (seg - 12) * 262144;
    else               src = bb + (seg - 16) * 262144;
    int idx = (blockIdx.x * 256 + threadIdx.x) * 4;
    float4 v = *(const float4*)(src + idx);
    __half2 h0 = __floats2half2_rn(v.x, v.y);
    __half2 h1 = __floats2half2_rn(v.z, v.w);
    uint2 o = {*(unsigned*)&h0, *(unsigned*)&h1};
    *(uint2*)(dst + (size_t)seg * 262144 + idx) = o;
}

// ---------------- bias concat: [gbq|gbk|gbv] at 0, [cbk|cbv] at 2048 ----------
__global__ void concat_bias_kernel(
    const float* q, const float* k, const float* v,
    const float* ck, const float* cv, float* dst)
{
    int i = blockIdx.x * 256 + threadIdx.x;   // 0..2047
    if (i < 1536)
        dst[i] = (i < 512) ? q[i] : (i < 1024 ? k[i - 512] : v[i - 1024]);
    if (i < 1024)
        dst[2048 + i] = (i < 512) ? ck[i] : cv[i - 512];
}

// ---------------- instance norm over D=512, fp16 output ----------------
__global__ void inorm_kernel(const float* __restrict__ x, __half* __restrict__ y) {
    const size_t base = (size_t)blockIdx.x * 512;
    const int tid = threadIdx.x;   // 128 threads
    float v[4];
    float s = 0.f, s2 = 0.f;
#pragma unroll
    for (int i = 0; i < 4; i++) {
        float a = x[base + tid + i * 128];
        v[i] = a; s += a; s2 += a * a;
    }
#pragma unroll
    for (int o = 16; o > 0; o >>= 1) {
        s  += __shfl_xor_sync(0xffffffffu, s,  o);
        s2 += __shfl_xor_sync(0xffffffffu, s2, o);
    }
    __shared__ float sh[8];
    int w = tid >> 5;
    if ((tid & 31) == 0) { sh[w] = s; sh[4 + w] = s2; }
    __syncthreads();
    s  = sh[0] + sh[1] + sh[2] + sh[3];
    s2 = sh[4] + sh[5] + sh[6] + sh[7];
    float mean = s * (1.f / 512.f);
    float var  = s2 * (1.f / 512.f) - mean * mean;
    float inv  = rsqrtf(var + 1e-5f);
#pragma unroll
    for (int i = 0; i < 4; i++)
        y[base + tid + i * 128] = __float2half_rn((v[i] - mean) * inv);
}

// ================= FP16 GEMM-NT, cp.async 3-stage, ldmatrix, m16n8k16 ============
// C = [res +] A(MxK) * W(NxK)^T + bias [, relu].  Block 128 x BN x 32, 256 thr,
// 8 warps (2m x 4n). BN=128: warp tile 64x32. BN=64: warp tile 64x16.
#define ASTB 10240    // bytes per 128x40-half A stage

template<int RELU, int HASRES, int OUTF16, int BN>
__global__ void __launch_bounds__(256) gemm_fp16_nt(
    const __half* __restrict__ A, int lda,
    const __half* __restrict__ W, int ldw,
    const float* __restrict__ bias,
    const float* __restrict__ res,
    void* __restrict__ Cv, int ldc, int K)
{
    constexpr int NI  = BN / 32;     // n8-frag pairs per warp (4 or 2)
    constexpr int NP  = BN / 64;     // B ldmatrix groups per warp (2 or 1)
    constexpr int BSTB = BN * 80;    // bytes per BNx40-half B stage
    extern __shared__ __half smh[];
    const unsigned a_smem = (unsigned)__cvta_generic_to_shared(smh);
    const unsigned b_smem = a_smem + 3 * ASTB;
    const int tid = threadIdx.x, lane = tid & 31, wid = tid >> 5;
    const int wm = (wid & 1) * 64, wn = (wid >> 1) * (NI * 8);
    const int m0 = blockIdx.y * 128, n0 = blockIdx.x * BN;

    const int t8 = lane >> 3, l8 = lane & 7;
    const int ra = l8 + (t8 & 1) * 8, ca = (t8 >> 1) * 8;   // A geometry
    const int rb = l8 + (t8 >> 1) * 8, cb = (t8 & 1) * 8;   // B geometry
    unsigned aBase[4], bBase[NP];
#pragma unroll
    for (int mi = 0; mi < 4; mi++)
        aBase[mi] = a_smem + (unsigned)(((wm + mi * 16 + ra) * 40 + ca) * 2);
#pragma unroll
    for (int p = 0; p < NP; p++)
        bBase[p] = b_smem + (unsigned)(((wn + p * 16 + rb) * 40 + cb) * 2);

    const int nt = K >> 5;

    auto load_tile = [&](int s, int kt) {
        const int k0 = kt * 32;
#pragma unroll
        for (int i = 0; i < 2; i++) {        // A: 128 rows
            int id = tid + i * 256;
            int row = id >> 2, c8 = (id & 3) * 8;
            CPA(a_smem + (unsigned)(s * ASTB + (row * 40 + c8) * 2),
                A + (size_t)(m0 + row) * lda + k0 + c8);
        }
#pragma unroll
        for (int i = 0; i < BN / 64; i++) {  // B: BN rows
            int id = tid + i * 256;
            int row = id >> 2, c8 = (id & 3) * 8;
            CPA(b_smem + (unsigned)(s * BSTB + (row * 40 + c8) * 2),
                W + (size_t)(n0 + row) * ldw + k0 + c8);
        }
    };

    load_tile(0, 0); CPC();
    load_tile(1, 1); CPC();

    float acc[4][NI][4] = {};
    for (int kt = 0; kt < nt; kt++) {
        CPW(1);
        __syncthreads();
        if (kt + 2 < nt) load_tile((kt + 2) % 3, kt + 2);
        CPC();
        const unsigned stgA = (unsigned)((kt % 3) * ASTB);
        const unsigned stgB = (unsigned)((kt % 3) * BSTB);
#pragma unroll
        for (int kc = 0; kc < 2; kc++) {      // two k16 slices
            unsigned af[4][4], bf[NI][2];
#pragma unroll
            for (int mi = 0; mi < 4; mi++)
                LDM4(af[mi][0], af[mi][1], af[mi][2], af[mi][3],
                     aBase[mi] + stgA + kc * 32);
#pragma unroll
            for (int p = 0; p < NP; p++)
                LDM4(bf[2 * p][0], bf[2 * p][1], bf[2 * p + 1][0], bf[2 * p + 1][1],
                     bBase[p] + stgB + kc * 32);
#pragma unroll
            for (int mi = 0; mi < 4; mi++)
#pragma unroll
                for (int ni = 0; ni < NI; ni++)
                    mma16(acc[mi][ni], af[mi], bf[ni]);
        }
        __syncthreads();
    }

#pragma unroll
    for (int mi = 0; mi < 4; mi++)
#pragma unroll
        for (int ni = 0; ni < NI; ni++) {
            int row = m0 + wm + mi * 16 + (lane >> 2);
            int col = n0 + wn + ni * 8 + 2 * (lane & 3);
            float b0v = bias[col], b1v = bias[col + 1];
            float v0 = acc[mi][ni][0] + b0v, v1 = acc[mi][ni][1] + b1v;
            float v2 = acc[mi][ni][2] + b0v, v3 = acc[mi][ni][3] + b1v;
            if (HASRES) {
                float2 r0 = *(const float2*)&res[(size_t)row * ldc + col];
                float2 r1 = *(const float2*)&res[(size_t)(row + 8) * ldc + col];
                v0 += r0.x; v1 += r0.y; v2 += r1.x; v3 += r1.y;
            }
            if (RELU) {
                v0 = fmaxf(v0, 0.f); v1 = fmaxf(v1, 0.f);
                v2 = fmaxf(v2, 0.f); v3 = fmaxf(v3, 0.f);
            }
            if (OUTF16) {
                __half* C = (__half*)Cv;
                __half2 h0 = __floats2half2_rn(v0, v1);
                __half2 h1 = __floats2half2_rn(v2, v3);
                *(__half2*)&C[(size_t)row * ldc + col]       = h0;
                *(__half2*)&C[(size_t)(row + 8) * ldc + col] = h1;
            } else {
                float* C = (float*)Cv;
                float2 o0 = {v0, v1}, o1 = {v2, v3};
                *(float2*)&C[(size_t)row * ldc + col]       = o0;
                *(float2*)&C[(size_t)(row + 8) * ldc + col] = o1;
            }
        }
}

// ================= Fused flash attention (fp16 MMA, online softmax) ==============
// One block = (128 q-rows, one b*h). 8 warps, warp owns 16 q-rows x full KV sweep.
// Q/K/V read from arbitrary-strided fp16 buffers (packed QKV supported).
// smem: Q 128x136h | K 2x64x136h | V 2x64x136h  = 104448 B.
#define QB 34816
#define KB 17408

template<int MODE>   // 0: global outer-product mask, 1: cross mask
__global__ void __launch_bounds__(256) flash_fp16(
    const __half* __restrict__ Qg, int qld, int qbs,
    const __half* __restrict__ Kg, const __half* __restrict__ Vg, int kvld, int kvbs,
    const unsigned char* __restrict__ mask,
    __half* __restrict__ O, int Lk)
{
    extern __shared__ __half smh[];
    const unsigned q_sm = (unsigned)__cvta_generic_to_shared(smh);
    const unsigned k_sm = q_sm + QB;
    const unsigned v_sm = k_sm + 2 * KB;
    const int tid = threadIdx.x, lane = tid & 31, wid = tid >> 5;
    const int l = lane & 3, r4 = lane >> 2;
    const int b = blockIdx.y >> 2, h = blockIdx.y & 3;
    const int q0 = blockIdx.x * 128;
    const __half* Qp = Qg + (size_t)b * qbs + (size_t)q0 * qld + h * 128;
    const __half* Kp = Kg + (size_t)b * kvbs + h * 128;
    const __half* Vp = Vg + (size_t)b * kvbs + h * 128;

    const int t8 = lane >> 3, l8 = lane & 7;
    const int ra = l8 + (t8 & 1) * 8, ca = (t8 >> 1) * 8;    // Q (A-type)
    const int rb = l8 + (t8 >> 1) * 8, cb = (t8 & 1) * 8;    // K (B-type)
    const int vr = l8 + (t8 & 1) * 8, vc = (t8 >> 1) * 8;    // V (trans B-type)
    const unsigned qBase = q_sm + (unsigned)(((wid * 16 + ra) * 136 + ca) * 2);
    unsigned kBase[4];
#pragma unroll
    for (int p = 0; p < 4; p++)
        kBase[p] = k_sm + (unsigned)(((p * 16 + rb) * 136 + cb) * 2);
    const unsigned vBase0 = v_sm + (unsigned)((vr * 136 + vc) * 2);

    // ---- load Q tile (128x128 halves) ----
#pragma unroll
    for (int i = 0; i < 8; i++) {
        int id = tid + i * 256;
        int row = id >> 4, c8 = (id & 15) * 8;
        CPA(q_sm + (unsigned)((row * 136 + c8) * 2), Qp + (size_t)row * qld + c8);
    }
    auto loadKV = [&](int st, int t) {
        const int kv0 = t * 64;
#pragma unroll
        for (int i = 0; i < 4; i++) {
            int id = tid + i * 256;
            int row = id >> 4, c8 = (id & 15) * 8;
            CPA(k_sm + (unsigned)(st * KB + (row * 136 + c8) * 2),
                Kp + (size_t)(kv0 + row) * kvld + c8);
            CPA(v_sm + (unsigned)(st * KB + (row * 136 + c8) * 2),
                Vp + (size_t)(kv0 + row) * kvld + c8);
        }
    };
    const int nt = Lk >> 6;
    loadKV(0, 0); CPC();
    loadKV(1, 1); CPC();

    const int rowg0 = q0 + wid * 16 + r4;
    const int rowg1 = rowg0 + 8;
    unsigned char qok0 = 1, qok1 = 1;
    if (MODE == 0) { qok0 = mask[b * 1024 + rowg0]; qok1 = mask[b * 1024 + rowg1]; }
    const unsigned char* mrow0 = mask + ((size_t)(b * 1024 + rowg0)) * 256;
    const unsigned char* mrow1 = mask + ((size_t)(b * 1024 + rowg1)) * 256;

    CPW(1);
    __syncthreads();

    unsigned qf[8][4];
#pragma unroll
    for (int kc = 0; kc < 8; kc++)
        LDM4(qf[kc][0], qf[kc][1], qf[kc][2], qf[kc][3], qBase + kc * 32);

    float oacc[16][4] = {};
    float m0 = -INFINITY, m1 = -INFINITY, l0 = 0.f, l1 = 0.f;
    const float scale = 0.08838834764831845f;   // 1/sqrt(128)

    for (int t = 0; t < nt; t++) {
        if (t > 0) { CPW(1); __syncthreads(); }
        const int st = t & 1;
        const unsigned kstg = (unsigned)(st * KB);
        const int kv0 = t * 64;

        float sacc[8][4] = {};
#pragma unroll
        for (int kc = 0; kc < 8; kc++) {
            unsigned bf[8][2];
#pragma unroll
            for (int p = 0; p < 4; p++)
                LDM4(bf[2 * p][0], bf[2 * p][1], bf[2 * p + 1][0], bf[2 * p + 1][1],
                     kBase[p] + kstg + kc * 32);
#pragma unroll
            for (int nn = 0; nn < 8; nn++)
                mma16(sacc[nn], qf[kc], bf[nn]);
        }

        float tmax0 = -INFINITY, tmax1 = -INFINITY;
#pragma unroll
        for (int nn = 0; nn < 8; nn++) {
            int col = kv0 + nn * 8 + 2 * l;
            bool ok00, ok01, ok10, ok11;
            if (MODE == 0) {
                bool ka = mask[b * 1024 + col] != 0;
                bool kb = mask[b * 1024 + col + 1] != 0;
                ok00 = qok0 && ka; ok01 = qok0 && kb;
                ok10 = qok1 && ka; ok11 = qok1 && kb;
            } else {
                ok00 = mrow0[col] != 0; ok01 = mrow0[col + 1] != 0;
                ok10 = mrow1[col] != 0; ok11 = mrow1[col + 1] != 0;
            }
            sacc[nn][0] = ok00 ? sacc[nn][0] * scale : -1e9f;
            sacc[nn][1] = ok01 ? sacc[nn][1] * scale : -1e9f;
            sacc[nn][2] = ok10 ? sacc[nn][2] * scale : -1e9f;
            sacc[nn][3] = ok11 ? sacc[nn][3] * scale : -1e9f;
            tmax0 = fmaxf(tmax0, fmaxf(sacc[nn][0], sacc[nn][1]));
            tmax1 = fmaxf(tmax1, fmaxf(sacc[nn][2], sacc[nn][3]));
        }
        tmax0 = fmaxf(tmax0, __shfl_xor_sync(0xffffffffu, tmax0, 1));
        tmax0 = fmaxf(tmax0, __shfl_xor_sync(0xffffffffu, tmax0, 2));
        tmax1 = fmaxf(tmax1, __shfl_xor_sync(0xffffffffu, tmax1, 1));
        tmax1 = fmaxf(tmax1, __shfl_xor_sync(0xffffffffu, tmax1, 2));
        float mn0 = fmaxf(m0, tmax0), mn1 = fmaxf(m1, tmax1);
        float al0 = __expf(m0 - mn0), al1 = __expf(m1 - mn1);
        float rs0 = 0.f, rs1 = 0.f;
#pragma unroll
        for (int nn = 0; nn < 8; nn++) {
            sacc[nn][0] = __expf(sacc[nn][0] - mn0);
            sacc[nn][1] = __expf(sacc[nn][1] - mn0);
            sacc[nn][2] = __expf(sacc[nn][2] - mn1);
            sacc[nn][3] = __expf(sacc[nn][3] - mn1);
            rs0 += sacc[nn][0] + sacc[nn][1];
            rs1 += sacc[nn][2] + sacc[nn][3];
        }
        rs0 += __shfl_xor_sync(0xffffffffu, rs0, 1);
        rs0 += __shfl_xor_sync(0xffffffffu, rs0, 2);
        rs1 += __shfl_xor_sync(0xffffffffu, rs1, 1);
        rs1 += __shfl_xor_sync(0xffffffffu, rs1, 2);
        l0 = l0 * al0 + rs0; l1 = l1 * al1 + rs1;
        m0 = mn0; m1 = mn1;
#pragma unroll
        for (int nn = 0; nn < 16; nn++) {
            oacc[nn][0] *= al0; oacc[nn][1] *= al0;
            oacc[nn][2] *= al1; oacc[nn][3] *= al1;
        }

        const unsigned vst = (unsigned)(st * KB);
#pragma unroll
        for (int kc2 = 0; kc2 < 4; kc2++) {
            unsigned au[4];
            au[0] = packh2(sacc[2 * kc2][0],     sacc[2 * kc2][1]);
            au[1] = packh2(sacc[2 * kc2][2],     sacc[2 * kc2][3]);
            au[2] = packh2(sacc[2 * kc2 + 1][0], sacc[2 * kc2 + 1][1]);
            au[3] = packh2(sacc[2 * kc2 + 1][2], sacc[2 * kc2 + 1][3]);
#pragma unroll
            for (int g = 0; g < 8; g++) {
                unsigned r0, r1, r2, r3;
                LDM4T(r0, r1, r2, r3, vBase0 + vst + kc2 * 4352 + g * 32);
                unsigned b0[2] = {r0, r1}, b1[2] = {r2, r3};
                mma16(oacc[2 * g],     au, b0);
                mma16(oacc[2 * g + 1], au, b1);
            }
        }

        __syncthreads();
        if (t + 2 < nt) loadKV(st, t + 2);
        CPC();
    }

    float inv0 = 1.f / l0, inv1 = 1.f / l1;
#pragma unroll
    for (int nn = 0; nn < 16; nn++) {
        int col = h * 128 + nn * 8 + 2 * l;
        __half2 h0 = __floats2half2_rn(oacc[nn][0] * inv0, oacc[nn][1] * inv0);
        __half2 h1 = __floats2half2_rn(oacc[nn][2] * inv1, oacc[nn][3] * inv1);
        *(__half2*)&O[(size_t)b * 524288 + (size_t)rowg0 * 512 + col] = h0;
        *(__half2*)&O[(size_t)b * 524288 + (size_t)rowg1 * 512 + col] = h1;
    }
}

// ---------------- launch ----------------
static const int SMEM_G128  = 3 * ASTB + 3 * 128 * 80;   // 61440
static const int SMEM_G64   = 3 * ASTB + 3 * 64 * 80;    // 46080
static const int SMEM_FLASH = QB + 4 * KB;               // 104448

extern "C" void kernel_launch(void* const* d_in, const int* in_sizes, int n_in,
                              void* d_out, int out_size) {
    const float* edges = (const float*)d_in[0];
    const float* bbse  = (const float*)d_in[1];
    const void*  gm    = d_in[2];
    const void*  cm    = d_in[3];
    const float* gWq = (const float*)d_in[4];  const float* gbq = (const float*)d_in[5];
    const float* gWk = (const float*)d_in[6];  const float* gbk = (const float*)d_in[7];
    const float* gWv = (const float*)d_in[8];  const float* gbv = (const float*)d_in[9];
    const float* gWo = (const float*)d_in[10]; const float* gbo = (const float*)d_in[11];
    const float* cWq = (const float*)d_in[12]; const float* cbq = (const float*)d_in[13];
    const float* cWk = (const float*)d_in[14]; const float* cbk = (const float*)d_in[15];
    const float* cWv = (const float*)d_in[16]; const float* cbv = (const float*)d_in[17];
    const float* cWo = (const float*)d_in[18]; const float* cbo = (const float*)d_in[19];
    const float* fW1 = (const float*)d_in[20]; const float* fb1 = (const float*)d_in[21];
    const float* fW2 = (const float*)d_in[22]; const float* fb2 = (const float*)d_in[23];
    float* out = (float*)d_out;

    void *Xa, *Qa, *Ka, *AOa, *Sa, *Wa, *Ba;
    unsigned char *m8g, *m8c;
    cudaGetSymbolAddress(&Xa,  g_X);
    cudaGetSymbolAddress(&Qa,  g_Q);
    cudaGetSymbolAddress(&Ka,  g_K);
    cudaGetSymbolAddress(&AOa, g_AO);
    cudaGetSymbolAddress(&Sa,  g_S);
    cudaGetSymbolAddress(&Wa,  g_W16);
    cudaGetSymbolAddress(&Ba,  g_bcat);
    cudaGetSymbolAddress((void**)&m8g, g_m8g);
    cudaGetSymbolAddress((void**)&m8c, g_m8c);
    __half* X16   = (__half*)Xa;
    __half* Q16   = (__half*)Qa;     // cross-Q (16384 x 512)
    __half* KV16  = (__half*)Ka;     // cross-KV (4096 x 1024)
    __half* AO16  = (__half*)AOa;
    __half* QKV16 = (__half*)Sa;     // packed QKV (16384 x 1536); later FFN hidden
    __half* H16   = (__half*)Sa;
    __half* W16   = (__half*)Wa;
    float*  bcat  = (float*)Ba;

    cudaFuncSetAttribute(gemm_fp16_nt<0,0,1,128>, cudaFuncAttributeMaxDynamicSharedMemorySize, SMEM_G128);
    cudaFuncSetAttribute(gemm_fp16_nt<1,0,1,128>, cudaFuncAttributeMaxDynamicSharedMemorySize, SMEM_G128);
    cudaFuncSetAttribute(gemm_fp16_nt<0,0,1,64>,  cudaFuncAttributeMaxDynamicSharedMemorySize, SMEM_G64);
    cudaFuncSetAttribute(gemm_fp16_nt<0,1,0,64>,  cudaFuncAttributeMaxDynamicSharedMemorySize, SMEM_G64);
    cudaFuncSetAttribute(flash_fp16<0>,           cudaFuncAttributeMaxDynamicSharedMemorySize, SMEM_FLASH);
    cudaFuncSetAttribute(flash_fp16<1>,           cudaFuncAttributeMaxDynamicSharedMemorySize, SMEM_FLASH);

    // masks -> canonical uint8; weights/bbse -> fp16; bias concat
    detect_kernel<<<1, 32>>>((const unsigned char*)gm, (const unsigned char*)cm);
    convert_mask_kernel<<<64, 256>>>(gm, m8g, 16384, 0);
    convert_mask_kernel<<<16384, 256>>>(cm, m8c, 4194304, 1);
    convert_w_kernel<<<dim3(256, 24), 256>>>(gWq, gWk, gWv, gWo, cWq, cWk, cWv, cWo,
                                             fW1, fW2, bbse, W16);
    concat_bias_kernel<<<8, 256>>>(gbq, gbk, gbv, cbk, cbv, bcat);

    const int M = 16384;  // B*S tokens
    const __half* B16 = W16 + WO_BB;

    // ---- 1. global edge-edge self-attention ----
    inorm_kernel<<<M, 128>>>(edges, X16);
    // fused QKV: N=1536 (weights gWq|gWk|gWv contiguous)
    gemm_fp16_nt<0,0,1,128><<<dim3(12, 128), 256, SMEM_G128>>>(
        X16, 512, W16 + WO_GQ, 512, bcat, nullptr, QKV16, 1536, 512);
    flash_fp16<0><<<dim3(8, 64), 256, SMEM_FLASH>>>(
        QKV16, 1536, 1572864, QKV16 + 512, QKV16 + 1024, 1536, 1572864,
        m8g, AO16, 1024);
    gemm_fp16_nt<0,1,0,64><<<dim3(8, 128), 256, SMEM_G64>>>(
        AO16, 512, W16 + WO_GO, 512, gbo, edges, out, 512, 512);

    // ---- 2. cross-attention from bb semantics ----
    inorm_kernel<<<M, 128>>>(out, X16);
    gemm_fp16_nt<0,0,1,64><<<dim3(8, 128), 256, SMEM_G64>>>(
        X16, 512, W16 + WO_CQ, 512, cbq, nullptr, Q16, 512, 512);
    // fused cross-KV: N=1024 (weights cWk|cWv contiguous), M=4096 bbse tokens
    gemm_fp16_nt<0,0,1,128><<<dim3(8, 32), 256, SMEM_G128>>>(
        B16, 512, W16 + WO_CK, 512, bcat + 2048, nullptr, KV16, 1024, 512);
    flash_fp16<1><<<dim3(8, 64), 256, SMEM_FLASH>>>(
        Q16, 512, 524288, KV16, KV16 + 512, 1024, 262144,
        m8c, AO16, 256);
    gemm_fp16_nt<0,1,0,64><<<dim3(8, 128), 256, SMEM_G64>>>(
        AO16, 512, W16 + WO_CO, 512, cbo, out, out, 512, 512);

    // ---- 3. FFN ----
    inorm_kernel<<<M, 128>>>(out, X16);
    gemm_fp16_nt<1,0,1,128><<<dim3(16, 128), 256, SMEM_G128>>>(
        X16, 512, W16 + WO_F1, 512, fb1, nullptr, H16, 2048, 512);
    gemm_fp16_nt<0,1,0,64><<<dim3(8, 128), 256, SMEM_G64>>>(
        H16, 2048, W16 + WO_F2, 2048, fb2, out, out, 512, 2048);
}

// round 16
// speedup vs baseline: 5.8871x; 1.0184x over previous
#include <cuda_runtime.h>
#include <cuda_fp16.h>

// Problem constants
//   B=16, N=32, D=512, H=4, SB=256, S=N*N=1024, DS=128
// Output: edges (16,1024,512) f32

// ---------------- static scratch (no allocations allowed) ----------------
__device__ float g_X [8388608];    // X16 (fp16 view): inorm output
__device__ float g_Q [8388608];    // cross-Q16
__device__ float g_K [8388608];    // cross-KV16 (4096 x 1024)
__device__ float g_AO[8388608];    // AO16
__device__ float g_S [67108864];   // QKV16 (16384x1536) / FFN hidden16
__device__ __half g_W16[6291456];  // fp16 weights (10 mats) + bbse16
__device__ float g_bcat[4096];     // concat biases: [0..1536) g qkv, [2048..3072) c kv
__device__ unsigned char g_m8g[16384];    // global mask, flattened g (B,S)
__device__ unsigned char g_m8c[4194304];  // cross mask (B,S,SB)
__device__ int g_mtype[2];

// W16 offsets (halves)
#define WO_GQ 0
#define WO_GO 786432
#define WO_CQ 1048576
#define WO_CK 1310720
#define WO_CO 1835008
#define WO_F1 2097152
#define WO_F2 3145728
#define WO_BB 4194304

// ---------------- cp.async / ldmatrix / mma helpers ----------------
#define CPA(dst, src) asm volatile("cp.async.cg.shared.global [%0], [%1], 16;" :: "r"(dst), "l"(src))
#define CPC()         asm volatile("cp.async.commit_group;")
#define CPW(n)        asm volatile("cp.async.wait_group %0;" :: "n"(n))
#define LDM4(r0, r1, r2, r3, addr) \
    asm volatile("ldmatrix.sync.aligned.m8n8.x4.shared.b16 {%0,%1,%2,%3}, [%4];" \
        : "=r"(r0), "=r"(r1), "=r"(r2), "=r"(r3) : "r"(addr))
#define LDM4T(r0, r1, r2, r3, addr) \
    asm volatile("ldmatrix.sync.aligned.m8n8.x4.trans.shared.b16 {%0,%1,%2,%3}, [%4];" \
        : "=r"(r0), "=r"(r1), "=r"(r2), "=r"(r3) : "r"(addr))

__device__ __forceinline__ void mma16(float* c, const unsigned* a, const unsigned* b) {
    asm volatile(
        "mma.sync.aligned.m16n8k16.row.col.f32.f16.f16.f32 "
        "{%0,%1,%2,%3}, {%4,%5,%6,%7}, {%8,%9}, {%0,%1,%2,%3};"
        : "+f"(c[0]), "+f"(c[1]), "+f"(c[2]), "+f"(c[3])
        : "r"(a[0]), "r"(a[1]), "r"(a[2]), "r"(a[3]), "r"(b[0]), "r"(b[1]));
}

__device__ __forceinline__ unsigned packh2(float lo, float hi) {
    __half2 h = __floats2half2_rn(lo, hi);
    return *(unsigned*)&h;
}

// ---------------- mask dtype detection + conversion ----------------
__device__ int classify_bytes(const unsigned char* p) {
    bool big = false, bf16sig = false;
    int ones = 0;
    for (int i = 0; i < 256; i++) {
        unsigned char v = p[i];
        if (v > 1) big = true;
        if (v == 1) ones++;
        if (v == 0x3F && (i & 3) == 1) bf16sig = true;
    }
    if (big) return bf16sig ? 3 : 2;
    return (ones > 96) ? 0 : 1;
}

__global__ void detect_kernel(const unsigned char* gm, const unsigned char* cm) {
    if (threadIdx.x == 0) {
        g_mtype[0] = classify_bytes(gm);
        g_mtype[1] = classify_bytes(cm);
    }
}

// 4 consecutive elems per thread, uchar4 stores (n multiple of 4)
__global__ void convert_mask_kernel(const void* src, unsigned char* dst, int n, int which) {
    int i = (blockIdx.x * blockDim.x + threadIdx.x) * 4;
    if (i >= n) return;
    int t = g_mtype[which];
    uchar4 o;
    if (t == 0) {
        uchar4 v = *(const uchar4*)((const unsigned char*)src + i);
        o = make_uchar4(v.x != 0, v.y != 0, v.z != 0, v.w != 0);
    } else if (t == 1) {
        int4 v = *(const int4*)((const int*)src + i);
        o = make_uchar4(v.x != 0, v.y != 0, v.z != 0, v.w != 0);
    } else if (t == 3) {
        ushort4 v = *(const ushort4*)((const unsigned short*)src + i);
        o = make_uchar4(v.x != 0, v.y != 0, v.z != 0, v.w != 0);
    } else {
        float4 v = *(const float4*)((const float*)src + i);
        o = make_uchar4(v.x != 0.f, v.y != 0.f, v.z != 0.f, v.w != 0.f);
    }
    *(uchar4*)(dst + i) = o;
}

// ---------------- f32 -> fp16 bulk conversion of weights + bbse ----------------
// 24 segments of 262144 elems. grid (64, 24), 256 thr, 4 float4 per thread (MLP 4).
__global__ void convert_w_kernel(
    const float* a0, const float* a1, const float* a2, const float* a3,
    const float* a4, const float* a5, const float* a6, const float* a7,
    const float* f1, const float* f2, const float* bb, __half* dst)
{
    const float* tab[8] = {a0, a1, a2, a3, a4, a5, a6, a7};
    int seg = blockIdx.y;
    const float* src;
    if (seg < 8)       src = tab[seg];
    else if (seg < 12) src = f1 + (seg - 8) * 262144;
    else if (seg < 16) src = f2 + (seg - 12) * 262144;
    else               src = bb + (seg - 16) * 262144;
    __half* d = dst + (size_t)seg * 262144;
    int base = (blockIdx.x * 256 + threadIdx.x) * 4;   // stride 65536 elems per j
    float4 v0 = *(const float4*)(src + base);
    float4 v1 = *(const float4*)(src + base + 65536);
    float4 v2 = *(const float4*)(src + base + 131072);
    float4 v3 = *(const float4*)(src + base + 196608);
#define CW_STORE(vv, off) { \
        __half2 h0 = __floats2half2_rn((vv).x, (vv).y); \
        __half2 h1 = __floats2half2_rn((vv).z, (vv).w); \
        uint2 o = {*(unsigned*)&h0, *(unsigned*)&h1}; \
        *(uint2*)(d + base + (off)) = o; }
    CW_STORE(v0, 0) CW_STORE(v1, 65536) CW_STORE(v2, 131072) CW_STORE(v3, 196608)
#undef CW_STORE
}

// ---------------- bias concat: [gbq|gbk|gbv] at 0, [cbk|cbv] at 2048 ----------
__global__ void concat_bias_kernel(
    const float* q, const float* k, const float* v,
    const float* ck, const float* cv, float* dst)
{
    int i = blockIdx.x * 256 + threadIdx.x;   // 0..2047
    if (i < 1536)
        dst[i] = (i < 512) ? q[i] : (i < 1024 ? k[i - 512] : v[i - 1024]);
    if (i < 1024)
        dst[2048 + i] = (i < 512) ? ck[i] : cv[i - 512];
}

// ---------------- instance norm over D=512, fp16 output ----------------
// 128 threads/token; one float4 load + one uint2 (4 halves) store per thread.
__global__ void inorm_kernel(const float* __restrict__ x, __half* __restrict__ y) {
    const size_t base = (size_t)blockIdx.x * 512;
    const int tid = threadIdx.x;
    float4 v = *(const float4*)(x + base + tid * 4);
    float s  = v.x + v.y + v.z + v.w;
    float s2 = v.x * v.x + v.y * v.y + v.z * v.z + v.w * v.w;
#pragma unroll
    for (int o = 16; o > 0; o >>= 1) {
        s  += __shfl_xor_sync(0xffffffffu, s,  o);
        s2 += __shfl_xor_sync(0xffffffffu, s2, o);
    }
    __shared__ float sh[8];
    int w = tid >> 5;
    if ((tid & 31) == 0) { sh[w] = s; sh[4 + w] = s2; }
    __syncthreads();
    s  = sh[0] + sh[1] + sh[2] + sh[3];
    s2 = sh[4] + sh[5] + sh[6] + sh[7];
    float mean = s * (1.f / 512.f);
    float var  = s2 * (1.f / 512.f) - mean * mean;
    float inv  = rsqrtf(var + 1e-5f);
    __half2 h0 = __floats2half2_rn((v.x - mean) * inv, (v.y - mean) * inv);
    __half2 h1 = __floats2half2_rn((v.z - mean) * inv, (v.w - mean) * inv);
    uint2 o = {*(unsigned*)&h0, *(unsigned*)&h1};
    *(uint2*)(y + base + tid * 4) = o;
}

// ================= FP16 GEMM-NT, cp.async 3-stage, ldmatrix, m16n8k16 ============
// C = [res +] A(MxK) * W(NxK)^T + bias [, relu].  Block 128 x BN x 32, 256 thr,
// 8 warps (2m x 4n). BN=128: warp tile 64x32. BN=64: warp tile 64x16.
#define ASTB 10240    // bytes per 128x40-half A stage

template<int RELU, int HASRES, int OUTF16, int BN>
__global__ void __launch_bounds__(256) gemm_fp16_nt(
    const __half* __restrict__ A, int lda,
    const __half* __restrict__ W, int ldw,
    const float* __restrict__ bias,
    const float* __restrict__ res,
    void* __restrict__ Cv, int ldc, int K)
{
    constexpr int NI  = BN / 32;     // n8-frag pairs per warp (4 or 2)
    constexpr int NP  = BN / 64;     // B ldmatrix groups per warp (2 or 1)
    constexpr int BSTB = BN * 80;    // bytes per BNx40-half B stage
    extern __shared__ __half smh[];
    const unsigned a_smem = (unsigned)__cvta_generic_to_shared(smh);
    const unsigned b_smem = a_smem + 3 * ASTB;
    const int tid = threadIdx.x, lane = tid & 31, wid = tid >> 5;
    const int wm = (wid & 1) * 64, wn = (wid >> 1) * (NI * 8);
    const int m0 = blockIdx.y * 128, n0 = blockIdx.x * BN;

    const int t8 = lane >> 3, l8 = lane & 7;
    const int ra = l8 + (t8 & 1) * 8, ca = (t8 >> 1) * 8;   // A geometry
    const int rb = l8 + (t8 >> 1) * 8, cb = (t8 & 1) * 8;   // B geometry
    unsigned aBase[4], bBase[NP];
#pragma unroll
    for (int mi = 0; mi < 4; mi++)
        aBase[mi] = a_smem + (unsigned)(((wm + mi * 16 + ra) * 40 + ca) * 2);
#pragma unroll
    for (int p = 0; p < NP; p++)
        bBase[p] = b_smem + (unsigned)(((wn + p * 16 + rb) * 40 + cb) * 2);

    const int nt = K >> 5;

    auto load_tile = [&](int s, int kt) {
        const int k0 = kt * 32;
#pragma unroll
        for (int i = 0; i < 2; i++) {        // A: 128 rows
            int id = tid + i * 256;
            int row = id >> 2, c8 = (id & 3) * 8;
            CPA(a_smem + (unsigned)(s * ASTB + (row * 40 + c8) * 2),
                A + (size_t)(m0 + row) * lda + k0 + c8);
        }
#pragma unroll
        for (int i = 0; i < BN / 64; i++) {  // B: BN rows
            int id = tid + i * 256;
            int row = id >> 2, c8 = (id & 3) * 8;
            CPA(b_smem + (unsigned)(s * BSTB + (row * 40 + c8) * 2),
                W + (size_t)(n0 + row) * ldw + k0 + c8);
        }
    };

    load_tile(0, 0); CPC();
    load_tile(1, 1); CPC();

    float acc[4][NI][4] = {};
    for (int kt = 0; kt < nt; kt++) {
        CPW(1);
        __syncthreads();
        if (kt + 2 < nt) load_tile((kt + 2) % 3, kt + 2);
        CPC();
        const unsigned stgA = (unsigned)((kt % 3) * ASTB);
        const unsigned stgB = (unsigned)((kt % 3) * BSTB);
#pragma unroll
        for (int kc = 0; kc < 2; kc++) {      // two k16 slices
            unsigned af[4][4], bf[NI][2];
#pragma unroll
            for (int mi = 0; mi < 4; mi++)
                LDM4(af[mi][0], af[mi][1], af[mi][2], af[mi][3],
                     aBase[mi] + stgA + kc * 32);
#pragma unroll
            for (int p = 0; p < NP; p++)
                LDM4(bf[2 * p][0], bf[2 * p][1], bf[2 * p + 1][0], bf[2 * p + 1][1],
                     bBase[p] + stgB + kc * 32);
#pragma unroll
            for (int mi = 0; mi < 4; mi++)
#pragma unroll
                for (int ni = 0; ni < NI; ni++)
                    mma16(acc[mi][ni], af[mi], bf[ni]);
        }
        __syncthreads();
    }

#pragma unroll
    for (int mi = 0; mi < 4; mi++)
#pragma unroll
        for (int ni = 0; ni < NI; ni++) {
            int row = m0 + wm + mi * 16 + (lane >> 2);
            int col = n0 + wn + ni * 8 + 2 * (lane & 3);
            float b0v = bias[col], b1v = bias[col + 1];
            float v0 = acc[mi][ni][0] + b0v, v1 = acc[mi][ni][1] + b1v;
            float v2 = acc[mi][ni][2] + b0v, v3 = acc[mi][ni][3] + b1v;
            if (HASRES) {
                float2 r0 = *(const float2*)&res[(size_t)row * ldc + col];
                float2 r1 = *(const float2*)&res[(size_t)(row + 8) * ldc + col];
                v0 += r0.x; v1 += r0.y; v2 += r1.x; v3 += r1.y;
            }
            if (RELU) {
                v0 = fmaxf(v0, 0.f); v1 = fmaxf(v1, 0.f);
                v2 = fmaxf(v2, 0.f); v3 = fmaxf(v3, 0.f);
            }
            if (OUTF16) {
                __half* C = (__half*)Cv;
                __half2 h0 = __floats2half2_rn(v0, v1);
                __half2 h1 = __floats2half2_rn(v2, v3);
                *(__half2*)&C[(size_t)row * ldc + col]       = h0;
                *(__half2*)&C[(size_t)(row + 8) * ldc + col] = h1;
            } else {
                float* C = (float*)Cv;
                float2 o0 = {v0, v1}, o1 = {v2, v3};
                *(float2*)&C[(size_t)row * ldc + col]       = o0;
                *(float2*)&C[(size_t)(row + 8) * ldc + col] = o1;
            }
        }
}

// ================= Fused flash attention (fp16 MMA, online softmax) ==============
// One block = (128 q-rows, one b*h). 8 warps, warp owns 16 q-rows x full KV sweep.
// Q/K/V read from arbitrary-strided fp16 buffers (packed QKV supported).
// smem: Q 128x136h | K 2x64x136h | V 2x64x136h  = 104448 B.
#define QB 34816
#define KB 17408

template<int MODE>   // 0: global outer-product mask, 1: cross mask
__global__ void __launch_bounds__(256) flash_fp16(
    const __half* __restrict__ Qg, int qld, int qbs,
    const __half* __restrict__ Kg, const __half* __restrict__ Vg, int kvld, int kvbs,
    const unsigned char* __restrict__ mask,
    __half* __restrict__ O, int Lk)
{
    extern __shared__ __half smh[];
    const unsigned q_sm = (unsigned)__cvta_generic_to_shared(smh);
    const unsigned k_sm = q_sm + QB;
    const unsigned v_sm = k_sm + 2 * KB;
    const int tid = threadIdx.x, lane = tid & 31, wid = tid >> 5;
    const int l = lane & 3, r4 = lane >> 2;
    const int b = blockIdx.y >> 2, h = blockIdx.y & 3;
    const int q0 = blockIdx.x * 128;
    const __half* Qp = Qg + (size_t)b * qbs + (size_t)q0 * qld + h * 128;
    const __half* Kp = Kg + (size_t)b * kvbs + h * 128;
    const __half* Vp = Vg + (size_t)b * kvbs + h * 128;

    const int t8 = lane >> 3, l8 = lane & 7;
    const int ra = l8 + (t8 & 1) * 8, ca = (t8 >> 1) * 8;    // Q (A-type)
    const int rb = l8 + (t8 >> 1) * 8, cb = (t8 & 1) * 8;    // K (B-type)
    const int vr = l8 + (t8 & 1) * 8, vc = (t8 >> 1) * 8;    // V (trans B-type)
    const unsigned qBase = q_sm + (unsigned)(((wid * 16 + ra) * 136 + ca) * 2);
    unsigned kBase[4];
#pragma unroll
    for (int p = 0; p < 4; p++)
        kBase[p] = k_sm + (unsigned)(((p * 16 + rb) * 136 + cb) * 2);
    const unsigned vBase0 = v_sm + (unsigned)((vr * 136 + vc) * 2);

#pragma unroll
    for (int i = 0; i < 8; i++) {
        int id = tid + i * 256;
        int row = id >> 4, c8 = (id & 15) * 8;
        CPA(q_sm + (unsigned)((row * 136 + c8) * 2), Qp + (size_t)row * qld + c8);
    }
    auto loadKV = [&](int st, int t) {
        const int kv0 = t * 64;
#pragma unroll
        for (int i = 0; i < 4; i++) {
            int id = tid + i * 256;
            int row = id >> 4, c8 = (id & 15) * 8;
            CPA(k_sm + (unsigned)(st * KB + (row * 136 + c8) * 2),
                Kp + (size_t)(kv0 + row) * kvld + c8);
            CPA(v_sm + (unsigned)(st * KB + (row * 136 + c8) * 2),
                Vp + (size_t)(kv0 + row) * kvld + c8);
        }
    };
    const int nt = Lk >> 6;
    loadKV(0, 0); CPC();
    loadKV(1, 1); CPC();

    const int rowg0 = q0 + wid * 16 + r4;
    const int rowg1 = rowg0 + 8;
    unsigned char qok0 = 1, qok1 = 1;
    if (MODE == 0) { qok0 = mask[b * 1024 + rowg0]; qok1 = mask[b * 1024 + rowg1]; }
    const unsigned char* mrow0 = mask + ((size_t)(b * 1024 + rowg0)) * 256;
    const unsigned char* mrow1 = mask + ((size_t)(b * 1024 + rowg1)) * 256;

    CPW(1);
    __syncthreads();

    unsigned qf[8][4];
#pragma unroll
    for (int kc = 0; kc < 8; kc++)
        LDM4(qf[kc][0], qf[kc][1], qf[kc][2], qf[kc][3], qBase + kc * 32);

    float oacc[16][4] = {};
    float m0 = -INFINITY, m1 = -INFINITY, l0 = 0.f, l1 = 0.f;
    const float scale = 0.08838834764831845f;   // 1/sqrt(128)

    for (int t = 0; t < nt; t++) {
        if (t > 0) { CPW(1); __syncthreads(); }
        const int st = t & 1;
        const unsigned kstg = (unsigned)(st * KB);
        const int kv0 = t * 64;

        float sacc[8][4] = {};
#pragma unroll
        for (int kc = 0; kc < 8; kc++) {
            unsigned bf[8][2];
#pragma unroll
            for (int p = 0; p < 4; p++)
                LDM4(bf[2 * p][0], bf[2 * p][1], bf[2 * p + 1][0], bf[2 * p + 1][1],
                     kBase[p] + kstg + kc * 32);
#pragma unroll
            for (int nn = 0; nn < 8; nn++)
                mma16(sacc[nn], qf[kc], bf[nn]);
        }

        float tmax0 = -INFINITY, tmax1 = -INFINITY;
#pragma unroll
        for (int nn = 0; nn < 8; nn++) {
            int col = kv0 + nn * 8 + 2 * l;
            bool ok00, ok01, ok10, ok11;
            if (MODE == 0) {
                bool ka = mask[b * 1024 + col] != 0;
                bool kb = mask[b * 1024 + col + 1] != 0;
                ok00 = qok0 && ka; ok01 = qok0 && kb;
                ok10 = qok1 && ka; ok11 = qok1 && kb;
            } else {
                ok00 = mrow0[col] != 0; ok01 = mrow0[col + 1] != 0;
                ok10 = mrow1[col] != 0; ok11 = mrow1[col + 1] != 0;
            }
            sacc[nn][0] = ok00 ? sacc[nn][0] * scale : -1e9f;
            sacc[nn][1] = ok01 ? sacc[nn][1] * scale : -1e9f;
            sacc[nn][2] = ok10 ? sacc[nn][2] * scale : -1e9f;
            sacc[nn][3] = ok11 ? sacc[nn][3] * scale : -1e9f;
            tmax0 = fmaxf(tmax0, fmaxf(sacc[nn][0], sacc[nn][1]));
            tmax1 = fmaxf(tmax1, fmaxf(sacc[nn][2], sacc[nn][3]));
        }
        tmax0 = fmaxf(tmax0, __shfl_xor_sync(0xffffffffu, tmax0, 1));
        tmax0 = fmaxf(tmax0, __shfl_xor_sync(0xffffffffu, tmax0, 2));
        tmax1 = fmaxf(tmax1, __shfl_xor_sync(0xffffffffu, tmax1, 1));
        tmax1 = fmaxf(tmax1, __shfl_xor_sync(0xffffffffu, tmax1, 2));
        float mn0 = fmaxf(m0, tmax0), mn1 = fmaxf(m1, tmax1);
        float al0 = __expf(m0 - mn0), al1 = __expf(m1 - mn1);
        float rs0 = 0.f, rs1 = 0.f;
#pragma unroll
        for (int nn = 0; nn < 8; nn++) {
            sacc[nn][0] = __expf(sacc[nn][0] - mn0);
            sacc[nn][1] = __expf(sacc[nn][1] - mn0);
            sacc[nn][2] = __expf(sacc[nn][2] - mn1);
            sacc[nn][3] = __expf(sacc[nn][3] - mn1);
            rs0 += sacc[nn][0] + sacc[nn][1];
            rs1 += sacc[nn][2] + sacc[nn][3];
        }
        rs0 += __shfl_xor_sync(0xffffffffu, rs0, 1);
        rs0 += __shfl_xor_sync(0xffffffffu, rs0, 2);
        rs1 += __shfl_xor_sync(0xffffffffu, rs1, 1);
        rs1 += __shfl_xor_sync(0xffffffffu, rs1, 2);
        l0 = l0 * al0 + rs0; l1 = l1 * al1 + rs1;
        m0 = mn0; m1 = mn1;
#pragma unroll
        for (int nn = 0; nn < 16; nn++) {
            oacc[nn][0] *= al0; oacc[nn][1] *= al0;
            oacc[nn][2] *= al1; oacc[nn][3] *= al1;
        }

        const unsigned vst = (unsigned)(st * KB);
#pragma unroll
        for (int kc2 = 0; kc2 < 4; kc2++) {
            unsigned au[4];
            au[0] = packh2(sacc[2 * kc2][0],     sacc[2 * kc2][1]);
            au[1] = packh2(sacc[2 * kc2][2],     sacc[2 * kc2][3]);
            au[2] = packh2(sacc[2 * kc2 + 1][0], sacc[2 * kc2 + 1][1]);
            au[3] = packh2(sacc[2 * kc2 + 1][2], sacc[2 * kc2 + 1][3]);
#pragma unroll
            for (int g = 0; g < 8; g++) {
                unsigned r0, r1, r2, r3;
                LDM4T(r0, r1, r2, r3, vBase0 + vst + kc2 * 4352 + g * 32);
                unsigned b0[2] = {r0, r1}, b1[2] = {r2, r3};
                mma16(oacc[2 * g],     au, b0);
                mma16(oacc[2 * g + 1], au, b1);
            }
        }

        __syncthreads();
        if (t + 2 < nt) loadKV(st, t + 2);
        CPC();
    }

    float inv0 = 1.f / l0, inv1 = 1.f / l1;
#pragma unroll
    for (int nn = 0; nn < 16; nn++) {
        int col = h * 128 + nn * 8 + 2 * l;
        __half2 h0 = __floats2half2_rn(oacc[nn][0] * inv0, oacc[nn][1] * inv0);
        __half2 h1 = __floats2half2_rn(oacc[nn][2] * inv1, oacc[nn][3] * inv1);
        *(__half2*)&O[(size_t)b * 524288 + (size_t)rowg0 * 512 + col] = h0;
        *(__half2*)&O[(size_t)b * 524288 + (size_t)rowg1 * 512 + col] = h1;
    }
}

// ---------------- launch ----------------
static const int SMEM_G128  = 3 * ASTB + 3 * 128 * 80;   // 61440
static const int SMEM_G64   = 3 * ASTB + 3 * 64 * 80;    // 46080
static const int SMEM_FLASH = QB + 4 * KB;               // 104448

extern "C" void kernel_launch(void* const* d_in, const int* in_sizes, int n_in,
                              void* d_out, int out_size) {
    const float* edges = (const float*)d_in[0];
    const float* bbse  = (const float*)d_in[1];
    const void*  gm    = d_in[2];
    const void*  cm    = d_in[3];
    const float* gWq = (const float*)d_in[4];  const float* gbq = (const float*)d_in[5];
    const float* gWk = (const float*)d_in[6];  const float* gbk = (const float*)d_in[7];
    const float* gWv = (const float*)d_in[8];  const float* gbv = (const float*)d_in[9];
    const float* gWo = (const float*)d_in[10]; const float* gbo = (const float*)d_in[11];
    const float* cWq = (const float*)d_in[12]; const float* cbq = (const float*)d_in[13];
    const float* cWk = (const float*)d_in[14]; const float* cbk = (const float*)d_in[15];
    const float* cWv = (const float*)d_in[16]; const float* cbv = (const float*)d_in[17];
    const float* cWo = (const float*)d_in[18]; const float* cbo = (const float*)d_in[19];
    const float* fW1 = (const float*)d_in[20]; const float* fb1 = (const float*)d_in[21];
    const float* fW2 = (const float*)d_in[22]; const float* fb2 = (const float*)d_in[23];
    float* out = (float*)d_out;

    void *Xa, *Qa, *Ka, *AOa, *Sa, *Wa, *Ba;
    unsigned char *m8g, *m8c;
    cudaGetSymbolAddress(&Xa,  g_X);
    cudaGetSymbolAddress(&Qa,  g_Q);
    cudaGetSymbolAddress(&Ka,  g_K);
    cudaGetSymbolAddress(&AOa, g_AO);
    cudaGetSymbolAddress(&Sa,  g_S);
    cudaGetSymbolAddress(&Wa,  g_W16);
    cudaGetSymbolAddress(&Ba,  g_bcat);
    cudaGetSymbolAddress((void**)&m8g, g_m8g);
    cudaGetSymbolAddress((void**)&m8c, g_m8c);
    __half* X16   = (__half*)Xa;
    __half* Q16   = (__half*)Qa;     // cross-Q (16384 x 512)
    __half* KV16  = (__half*)Ka;     // cross-KV (4096 x 1024)
    __half* AO16  = (__half*)AOa;
    __half* QKV16 = (__half*)Sa;     // packed QKV (16384 x 1536); later FFN hidden
    __half* H16   = (__half*)Sa;
    __half* W16   = (__half*)Wa;
    float*  bcat  = (float*)Ba;

    cudaFuncSetAttribute(gemm_fp16_nt<0,0,1,128>, cudaFuncAttributeMaxDynamicSharedMemorySize, SMEM_G128);
    cudaFuncSetAttribute(gemm_fp16_nt<1,0,1,128>, cudaFuncAttributeMaxDynamicSharedMemorySize, SMEM_G128);
    cudaFuncSetAttribute(gemm_fp16_nt<0,0,1,64>,  cudaFuncAttributeMaxDynamicSharedMemorySize, SMEM_G64);
    cudaFuncSetAttribute(gemm_fp16_nt<0,1,0,64>,  cudaFuncAttributeMaxDynamicSharedMemorySize, SMEM_G64);
    cudaFuncSetAttribute(flash_fp16<0>,           cudaFuncAttributeMaxDynamicSharedMemorySize, SMEM_FLASH);
    cudaFuncSetAttribute(flash_fp16<1>,           cudaFuncAttributeMaxDynamicSharedMemorySize, SMEM_FLASH);

    // masks -> canonical uint8; weights/bbse -> fp16; bias concat
    detect_kernel<<<1, 32>>>((const unsigned char*)gm, (const unsigned char*)cm);
    convert_mask_kernel<<<16, 256>>>(gm, m8g, 16384, 0);
    convert_mask_kernel<<<4096, 256>>>(cm, m8c, 4194304, 1);
    convert_w_kernel<<<dim3(64, 24), 256>>>(gWq, gWk, gWv, gWo, cWq, cWk, cWv, cWo,
                                            fW1, fW2, bbse, W16);
    concat_bias_kernel<<<8, 256>>>(gbq, gbk, gbv, cbk, cbv, bcat);

    const int M = 16384;  // B*S tokens
    const __half* B16 = W16 + WO_BB;

    // ---- 1. global edge-edge self-attention ----
    inorm_kernel<<<M, 128>>>(edges, X16);
    // fused QKV: N=1536 (weights gWq|gWk|gWv contiguous)
    gemm_fp16_nt<0,0,1,128><<<dim3(12, 128), 256, SMEM_G128>>>(
        X16, 512, W16 + WO_GQ, 512, bcat, nullptr, QKV16, 1536, 512);
    flash_fp16<0><<<dim3(8, 64), 256, SMEM_FLASH>>>(
        QKV16, 1536, 1572864, QKV16 + 512, QKV16 + 1024, 1536, 1572864,
        m8g, AO16, 1024);
    gemm_fp16_nt<0,1,0,64><<<dim3(8, 128), 256, SMEM_G64>>>(
        AO16, 512, W16 + WO_GO, 512, gbo, edges, out, 512, 512);

    // ---- 2. cross-attention from bb semantics ----
    inorm_kernel<<<M, 128>>>(out, X16);
    gemm_fp16_nt<0,0,1,64><<<dim3(8, 128), 256, SMEM_G64>>>(
        X16, 512, W16 + WO_CQ, 512, cbq, nullptr, Q16, 512, 512);
    // fused cross-KV: N=1024 (weights cWk|cWv contiguous), M=4096 bbse tokens
    gemm_fp16_nt<0,0,1,128><<<dim3(8, 32), 256, SMEM_G128>>>(
        B16, 512, W16 + WO_CK, 512, bcat + 2048, nullptr, KV16, 1024, 512);
    flash_fp16<1><<<dim3(8, 64), 256, SMEM_FLASH>>>(
        Q16, 512, 524288, KV16, KV16 + 512, 1024, 262144,
        m8c, AO16, 256);
    gemm_fp16_nt<0,1,0,64><<<dim3(8, 128), 256, SMEM_G64>>>(
        AO16, 512, W16 + WO_CO, 512, cbo, out, out, 512, 512);

    // ---- 3. FFN ----
    inorm_kernel<<<M, 128>>>(out, X16);
    gemm_fp16_nt<1,0,1,128><<<dim3(16, 128), 256, SMEM_G128>>>(
        X16, 512, W16 + WO_F1, 512, fb1, nullptr, H16, 2048, 512);
    gemm_fp16_nt<0,1,0,64><<<dim3(8, 128), 256, SMEM_G64>>>(
        H16, 2048, W16 + WO_F2, 2048, fb2, out, out, 512, 2048);
}

// round 17
// speedup vs baseline: 6.0339x; 1.0249x over previous
#include <cuda_runtime.h>
#include <cuda_fp16.h>

// Problem constants
//   B=16, N=32, D=512, H=4, SB=256, S=N*N=1024, DS=128
// Output: edges (16,1024,512) f32

// ---------------- static scratch (no allocations allowed) ----------------
__device__ float g_X [8388608];    // X16 (fp16 view): inorm output
__device__ float g_Q [8388608];    // cross-Q16
__device__ float g_K [8388608];    // cross-KV16 (4096 x 1024)
__device__ float g_AO[8388608];    // AO16
__device__ float g_S [67108864];   // QKV16 (16384x1536) / FFN hidden16
__device__ __half g_W16[6291456];  // fp16 weights (10 mats) + bbse16
__device__ float g_bcat[4096];     // concat biases: [0..1536) g qkv, [2048..3072) c kv
__device__ unsigned char g_m8g[16384];    // global mask, flattened g (B,S)
__device__ unsigned char g_m8c[4194304];  // cross mask (B,S,SB)
__device__ int g_mtype[2];

// W16 offsets (halves)
#define WO_GQ 0
#define WO_GO 786432
#define WO_CQ 1048576
#define WO_CK 1310720
#define WO_CO 1835008
#define WO_F1 2097152
#define WO_F2 3145728
#define WO_BB 4194304

// ---------------- cp.async / ldmatrix / mma helpers ----------------
#define CPA(dst, src) asm volatile("cp.async.cg.shared.global [%0], [%1], 16;" :: "r"(dst), "l"(src))
#define CPC()         asm volatile("cp.async.commit_group;")
#define CPW(n)        asm volatile("cp.async.wait_group %0;" :: "n"(n))
#define LDM4(r0, r1, r2, r3, addr) \
    asm volatile("ldmatrix.sync.aligned.m8n8.x4.shared.b16 {%0,%1,%2,%3}, [%4];" \
        : "=r"(r0), "=r"(r1), "=r"(r2), "=r"(r3) : "r"(addr))
#define LDM4T(r0, r1, r2, r3, addr) \
    asm volatile("ldmatrix.sync.aligned.m8n8.x4.trans.shared.b16 {%0,%1,%2,%3}, [%4];" \
        : "=r"(r0), "=r"(r1), "=r"(r2), "=r"(r3) : "r"(addr))

__device__ __forceinline__ void mma16(float* c, const unsigned* a, const unsigned* b) {
    asm volatile(
        "mma.sync.aligned.m16n8k16.row.col.f32.f16.f16.f32 "
        "{%0,%1,%2,%3}, {%4,%5,%6,%7}, {%8,%9}, {%0,%1,%2,%3};"
        : "+f"(c[0]), "+f"(c[1]), "+f"(c[2]), "+f"(c[3])
        : "r"(a[0]), "r"(a[1]), "r"(a[2]), "r"(a[3]), "r"(b[0]), "r"(b[1]));
}

__device__ __forceinline__ unsigned packh2(float lo, float hi) {
    __half2 h = __floats2half2_rn(lo, hi);
    return *(unsigned*)&h;
}

// ---------------- mask dtype detection + conversion ----------------
__device__ int classify_bytes(const unsigned char* p) {
    bool big = false, bf16sig = false;
    int ones = 0;
    for (int i = 0; i < 256; i++) {
        unsigned char v = p[i];
        if (v > 1) big = true;
        if (v == 1) ones++;
        if (v == 0x3F && (i & 3) == 1) bf16sig = true;
    }
    if (big) return bf16sig ? 3 : 2;
    return (ones > 96) ? 0 : 1;
}

__global__ void detect_kernel(const unsigned char* gm, const unsigned char* cm) {
    if (threadIdx.x == 0) {
        g_mtype[0] = classify_bytes(gm);
        g_mtype[1] = classify_bytes(cm);
    }
}

// 4 consecutive elems per thread, uchar4 stores (n multiple of 4)
__global__ void convert_mask_kernel(const void* src, unsigned char* dst, int n, int which) {
    int i = (blockIdx.x * blockDim.x + threadIdx.x) * 4;
    if (i >= n) return;
    int t = g_mtype[which];
    uchar4 o;
    if (t == 0) {
        uchar4 v = *(const uchar4*)((const unsigned char*)src + i);
        o = make_uchar4(v.x != 0, v.y != 0, v.z != 0, v.w != 0);
    } else if (t == 1) {
        int4 v = *(const int4*)((const int*)src + i);
        o = make_uchar4(v.x != 0, v.y != 0, v.z != 0, v.w != 0);
    } else if (t == 3) {
        ushort4 v = *(const ushort4*)((const unsigned short*)src + i);
        o = make_uchar4(v.x != 0, v.y != 0, v.z != 0, v.w != 0);
    } else {
        float4 v = *(const float4*)((const float*)src + i);
        o = make_uchar4(v.x != 0.f, v.y != 0.f, v.z != 0.f, v.w != 0.f);
    }
    *(uchar4*)(dst + i) = o;
}

// ---------------- f32 -> fp16 bulk conversion of weights + bbse ----------------
// 24 segments of 262144 elems. grid (64, 24), 256 thr, 4 float4 per thread (MLP 4).
__global__ void convert_w_kernel(
    const float* a0, const float* a1, const float* a2, const float* a3,
    const float* a4, const float* a5, const float* a6, const float* a7,
    const float* f1, const float* f2, const float* bb, __half* dst)
{
    const float* tab[8] = {a0, a1, a2, a3, a4, a5, a6, a7};
    int seg = blockIdx.y;
    const float* src;
    if (seg < 8)       src = tab[seg];
    else if (seg < 12) src = f1 + (seg - 8) * 262144;
    else if (seg < 16) src = f2 + (seg - 12) * 262144;
    else               src = bb + (seg - 16) * 262144;
    __half* d = dst + (size_t)seg * 262144;
    int base = (blockIdx.x * 256 + threadIdx.x) * 4;   // stride 65536 elems per j
    float4 v0 = *(const float4*)(src + base);
    float4 v1 = *(const float4*)(src + base + 65536);
    float4 v2 = *(const float4*)(src + base + 131072);
    float4 v3 = *(const float4*)(src + base + 196608);
#define CW_STORE(vv, off) { \
        __half2 h0 = __floats2half2_rn((vv).x, (vv).y); \
        __half2 h1 = __floats2half2_rn((vv).z, (vv).w); \
        uint2 o = {*(unsigned*)&h0, *(unsigned*)&h1}; \
        *(uint2*)(d + base + (off)) = o; }
    CW_STORE(v0, 0) CW_STORE(v1, 65536) CW_STORE(v2, 131072) CW_STORE(v3, 196608)
#undef CW_STORE
}

// ---------------- bias concat: [gbq|gbk|gbv] at 0, [cbk|cbv] at 2048 ----------
__global__ void concat_bias_kernel(
    const float* q, const float* k, const float* v,
    const float* ck, const float* cv, float* dst)
{
    int i = blockIdx.x * 256 + threadIdx.x;   // 0..2047
    if (i < 1536)
        dst[i] = (i < 512) ? q[i] : (i < 1024 ? k[i - 512] : v[i - 1024]);
    if (i < 1024)
        dst[2048 + i] = (i < 512) ? ck[i] : cv[i - 512];
}

// ---------------- instance norm over D=512, fp16 output ----------------
// 256 threads = 2 tokens per block; 128 threads/token, float4 load + uint2 store.
__global__ void inorm_kernel(const float* __restrict__ x, __half* __restrict__ y) {
    const int tok = threadIdx.x >> 7;              // 0 or 1
    const int tid = threadIdx.x & 127;
    const size_t base = ((size_t)blockIdx.x * 2 + tok) * 512;
    float4 v = *(const float4*)(x + base + tid * 4);
    float s  = v.x + v.y + v.z + v.w;
    float s2 = v.x * v.x + v.y * v.y + v.z * v.z + v.w * v.w;
#pragma unroll
    for (int o = 16; o > 0; o >>= 1) {
        s  += __shfl_xor_sync(0xffffffffu, s,  o);
        s2 += __shfl_xor_sync(0xffffffffu, s2, o);
    }
    __shared__ float sh[2][8];
    int w = tid >> 5;
    if ((tid & 31) == 0) { sh[tok][w] = s; sh[tok][4 + w] = s2; }
    __syncthreads();
    s  = sh[tok][0] + sh[tok][1] + sh[tok][2] + sh[tok][3];
    s2 = sh[tok][4] + sh[tok][5] + sh[tok][6] + sh[tok][7];
    float mean = s * (1.f / 512.f);
    float var  = s2 * (1.f / 512.f) - mean * mean;
    float inv  = rsqrtf(var + 1e-5f);
    __half2 h0 = __floats2half2_rn((v.x - mean) * inv, (v.y - mean) * inv);
    __half2 h1 = __floats2half2_rn((v.z - mean) * inv, (v.w - mean) * inv);
    uint2 o = {*(unsigned*)&h0, *(unsigned*)&h1};
    *(uint2*)(y + base + tid * 4) = o;
}

// ================= FP16 GEMM-NT, cp.async 3-stage, ldmatrix, m16n8k16 ============
// C = [res +] A(MxK) * W(NxK)^T + bias [, relu].  Block 128 x BN x 64(k), 256 thr,
// 8 warps (2m x 4n). BN=128: warp tile 64x32. BN=64: warp tile 64x16.
// Stage rows: 64 k-halves + 8 pad = 72 halves (144 B; ldmatrix rows spread 4 banks).
#define ASTB 18432    // bytes per 128x72-half A stage

template<int RELU, int HASRES, int OUTF16, int BN>
__global__ void __launch_bounds__(256) gemm_fp16_nt(
    const __half* __restrict__ A, int lda,
    const __half* __restrict__ W, int ldw,
    const float* __restrict__ bias,
    const float* __restrict__ res,
    void* __restrict__ Cv, int ldc, int K)
{
    constexpr int NI  = BN / 32;      // n8-frag pairs per warp (4 or 2)
    constexpr int NP  = BN / 64;      // B ldmatrix groups per warp (2 or 1)
    constexpr int BSTB = BN * 144;    // bytes per BNx72-half B stage
    extern __shared__ __half smh[];
    const unsigned a_smem = (unsigned)__cvta_generic_to_shared(smh);
    const unsigned b_smem = a_smem + 3 * ASTB;
    const int tid = threadIdx.x, lane = tid & 31, wid = tid >> 5;
    const int wm = (wid & 1) * 64, wn = (wid >> 1) * (NI * 8);
    const int m0 = blockIdx.y * 128, n0 = blockIdx.x * BN;

    const int t8 = lane >> 3, l8 = lane & 7;
    const int ra = l8 + (t8 & 1) * 8, ca = (t8 >> 1) * 8;   // A geometry
    const int rb = l8 + (t8 >> 1) * 8, cb = (t8 & 1) * 8;   // B geometry
    unsigned aBase[4], bBase[NP];
#pragma unroll
    for (int mi = 0; mi < 4; mi++)
        aBase[mi] = a_smem + (unsigned)(((wm + mi * 16 + ra) * 72 + ca) * 2);
#pragma unroll
    for (int p = 0; p < NP; p++)
        bBase[p] = b_smem + (unsigned)(((wn + p * 16 + rb) * 72 + cb) * 2);

    const int nt = K >> 6;   // 64-wide k chunks

    auto load_tile = [&](int s, int kt) {
        const int k0 = kt * 64;
#pragma unroll
        for (int i = 0; i < 4; i++) {           // A: 128 rows x 64 halves
            int id = tid + i * 256;
            int row = id >> 3, c8 = (id & 7) * 8;
            CPA(a_smem + (unsigned)(s * ASTB + (row * 72 + c8) * 2),
                A + (size_t)(m0 + row) * lda + k0 + c8);
        }
#pragma unroll
        for (int i = 0; i < BN / 32; i++) {     // B: BN rows x 64 halves
            int id = tid + i * 256;
            int row = id >> 3, c8 = (id & 7) * 8;
            CPA(b_smem + (unsigned)(s * BSTB + (row * 72 + c8) * 2),
                W + (size_t)(n0 + row) * ldw + k0 + c8);
        }
    };

    load_tile(0, 0); CPC();
    load_tile(1, 1); CPC();

    float acc[4][NI][4] = {};
    for (int kt = 0; kt < nt; kt++) {
        CPW(1);
        __syncthreads();
        if (kt + 2 < nt) load_tile((kt + 2) % 3, kt + 2);
        CPC();
        const unsigned stgA = (unsigned)((kt % 3) * ASTB);
        const unsigned stgB = (unsigned)((kt % 3) * BSTB);
#pragma unroll
        for (int kc = 0; kc < 4; kc++) {      // four k16 slices
            unsigned af[4][4], bf[NI][2];
#pragma unroll
            for (int mi = 0; mi < 4; mi++)
                LDM4(af[mi][0], af[mi][1], af[mi][2], af[mi][3],
                     aBase[mi] + stgA + kc * 32);
#pragma unroll
            for (int p = 0; p < NP; p++)
                LDM4(bf[2 * p][0], bf[2 * p][1], bf[2 * p + 1][0], bf[2 * p + 1][1],
                     bBase[p] + stgB + kc * 32);
#pragma unroll
            for (int mi = 0; mi < 4; mi++)
#pragma unroll
                for (int ni = 0; ni < NI; ni++)
                    mma16(acc[mi][ni], af[mi], bf[ni]);
        }
        __syncthreads();
    }

#pragma unroll
    for (int mi = 0; mi < 4; mi++)
#pragma unroll
        for (int ni = 0; ni < NI; ni++) {
            int row = m0 + wm + mi * 16 + (lane >> 2);
            int col = n0 + wn + ni * 8 + 2 * (lane & 3);
            float b0v = bias[col], b1v = bias[col + 1];
            float v0 = acc[mi][ni][0] + b0v, v1 = acc[mi][ni][1] + b1v;
            float v2 = acc[mi][ni][2] + b0v, v3 = acc[mi][ni][3] + b1v;
            if (HASRES) {
                float2 r0 = *(const float2*)&res[(size_t)row * ldc + col];
                float2 r1 = *(const float2*)&res[(size_t)(row + 8) * ldc + col];
                v0 += r0.x; v1 += r0.y; v2 += r1.x; v3 += r1.y;
            }
            if (RELU) {
                v0 = fmaxf(v0, 0.f); v1 = fmaxf(v1, 0.f);
                v2 = fmaxf(v2, 0.f); v3 = fmaxf(v3, 0.f);
            }
            if (OUTF16) {
                __half* C = (__half*)Cv;
                __half2 h0 = __floats2half2_rn(v0, v1);
                __half2 h1 = __floats2half2_rn(v2, v3);
                *(__half2*)&C[(size_t)row * ldc + col]       = h0;
                *(__half2*)&C[(size_t)(row + 8) * ldc + col] = h1;
            } else {
                float* C = (float*)Cv;
                float2 o0 = {v0, v1}, o1 = {v2, v3};
                *(float2*)&C[(size_t)row * ldc + col]       = o0;
                *(float2*)&C[(size_t)(row + 8) * ldc + col] = o1;
            }
        }
}

// ================= Fused flash attention (fp16 MMA, online softmax) ==============
// One block = (128 q-rows, one b*h). 8 warps, warp owns 16 q-rows x full KV sweep.
// Q/K/V read from arbitrary-strided fp16 buffers (packed QKV supported).
// smem: Q 128x136h | K 2x64x136h | V 2x64x136h  = 104448 B.
#define QB 34816
#define KB 17408

template<int MODE>   // 0: global outer-product mask, 1: cross mask
__global__ void __launch_bounds__(256) flash_fp16(
    const __half* __restrict__ Qg, int qld, int qbs,
    const __half* __restrict__ Kg, const __half* __restrict__ Vg, int kvld, int kvbs,
    const unsigned char* __restrict__ mask,
    __half* __restrict__ O, int Lk)
{
    extern __shared__ __half smh[];
    const unsigned q_sm = (unsigned)__cvta_generic_to_shared(smh);
    const unsigned k_sm = q_sm + QB;
    const unsigned v_sm = k_sm + 2 * KB;
    const int tid = threadIdx.x, lane = tid & 31, wid = tid >> 5;
    const int l = lane & 3, r4 = lane >> 2;
    const int b = blockIdx.y >> 2, h = blockIdx.y & 3;
    const int q0 = blockIdx.x * 128;
    const __half* Qp = Qg + (size_t)b * qbs + (size_t)q0 * qld + h * 128;
    const __half* Kp = Kg + (size_t)b * kvbs + h * 128;
    const __half* Vp = Vg + (size_t)b * kvbs + h * 128;

    const int t8 = lane >> 3, l8 = lane & 7;
    const int ra = l8 + (t8 & 1) * 8, ca = (t8 >> 1) * 8;    // Q (A-type)
    const int rb = l8 + (t8 >> 1) * 8, cb = (t8 & 1) * 8;    // K (B-type)
    const int vr = l8 + (t8 & 1) * 8, vc = (t8 >> 1) * 8;    // V (trans B-type)
    const unsigned qBase = q_sm + (unsigned)(((wid * 16 + ra) * 136 + ca) * 2);
    unsigned kBase[4];
#pragma unroll
    for (int p = 0; p < 4; p++)
        kBase[p] = k_sm + (unsigned)(((p * 16 + rb) * 136 + cb) * 2);
    const unsigned vBase0 = v_sm + (unsigned)((vr * 136 + vc) * 2);

#pragma unroll
    for (int i = 0; i < 8; i++) {
        int id = tid + i * 256;
        int row = id >> 4, c8 = (id & 15) * 8;
        CPA(q_sm + (unsigned)((row * 136 + c8) * 2), Qp + (size_t)row * qld + c8);
    }
    auto loadKV = [&](int st, int t) {
        const int kv0 = t * 64;
#pragma unroll
        for (int i = 0; i < 4; i++) {
            int id = tid + i * 256;
            int row = id >> 4, c8 = (id & 15) * 8;
            CPA(k_sm + (unsigned)(st * KB + (row * 136 + c8) * 2),
                Kp + (size_t)(kv0 + row) * kvld + c8);
            CPA(v_sm + (unsigned)(st * KB + (row * 136 + c8) * 2),
                Vp + (size_t)(kv0 + row) * kvld + c8);
        }
    };
    const int nt = Lk >> 6;
    loadKV(0, 0); CPC();
    loadKV(1, 1); CPC();

    const int rowg0 = q0 + wid * 16 + r4;
    const int rowg1 = rowg0 + 8;
    unsigned char qok0 = 1, qok1 = 1;
    if (MODE == 0) { qok0 = mask[b * 1024 + rowg0]; qok1 = mask[b * 1024 + rowg1]; }
    const unsigned char* mrow0 = mask + ((size_t)(b * 1024 + rowg0)) * 256;
    const unsigned char* mrow1 = mask + ((size_t)(b * 1024 + rowg1)) * 256;

    CPW(1);
    __syncthreads();

    unsigned qf[8][4];
#pragma unroll
    for (int kc = 0; kc < 8; kc++)
        LDM4(qf[kc][0], qf[kc][1], qf[kc][2], qf[kc][3], qBase + kc * 32);

    float oacc[16][4] = {};
    float m0 = -INFINITY, m1 = -INFINITY, l0 = 0.f, l1 = 0.f;
    const float scale = 0.08838834764831845f;   // 1/sqrt(128)

    for (int t = 0; t < nt; t++) {
        if (t > 0) { CPW(1); __syncthreads(); }
        const int st = t & 1;
        const unsigned kstg = (unsigned)(st * KB);
        const int kv0 = t * 64;

        float sacc[8][4] = {};
#pragma unroll
        for (int kc = 0; kc < 8; kc++) {
            unsigned bf[8][2];
#pragma unroll
            for (int p = 0; p < 4; p++)
                LDM4(bf[2 * p][0], bf[2 * p][1], bf[2 * p + 1][0], bf[2 * p + 1][1],
                     kBase[p] + kstg + kc * 32);
#pragma unroll
            for (int nn = 0; nn < 8; nn++)
                mma16(sacc[nn], qf[kc], bf[nn]);
        }

        float tmax0 = -INFINITY, tmax1 = -INFINITY;
#pragma unroll
        for (int nn = 0; nn < 8; nn++) {
            int col = kv0 + nn * 8 + 2 * l;
            bool ok00, ok01, ok10, ok11;
            if (MODE == 0) {
                bool ka = mask[b * 1024 + col] != 0;
                bool kb = mask[b * 1024 + col + 1] != 0;
                ok00 = qok0 && ka; ok01 = qok0 && kb;
                ok10 = qok1 && ka; ok11 = qok1 && kb;
            } else {
                ok00 = mrow0[col] != 0; ok01 = mrow0[col + 1] != 0;
                ok10 = mrow1[col] != 0; ok11 = mrow1[col + 1] != 0;
            }
            sacc[nn][0] = ok00 ? sacc[nn][0] * scale : -1e9f;
            sacc[nn][1] = ok01 ? sacc[nn][1] * scale : -1e9f;
            sacc[nn][2] = ok10 ? sacc[nn][2] * scale : -1e9f;
            sacc[nn][3] = ok11 ? sacc[nn][3] * scale : -1e9f;
            tmax0 = fmaxf(tmax0, fmaxf(sacc[nn][0], sacc[nn][1]));
            tmax1 = fmaxf(tmax1, fmaxf(sacc[nn][2], sacc[nn][3]));
        }
        tmax0 = fmaxf(tmax0, __shfl_xor_sync(0xffffffffu, tmax0, 1));
        tmax0 = fmaxf(tmax0, __shfl_xor_sync(0xffffffffu, tmax0, 2));
        tmax1 = fmaxf(tmax1, __shfl_xor_sync(0xffffffffu, tmax1, 1));
        tmax1 = fmaxf(tmax1, __shfl_xor_sync(0xffffffffu, tmax1, 2));
        float mn0 = fmaxf(m0, tmax0), mn1 = fmaxf(m1, tmax1);
        float al0 = __expf(m0 - mn0), al1 = __expf(m1 - mn1);
        float rs0 = 0.f, rs1 = 0.f;
#pragma unroll
        for (int nn = 0; nn < 8; nn++) {
            sacc[nn][0] = __expf(sacc[nn][0] - mn0);
            sacc[nn][1] = __expf(sacc[nn][1] - mn0);
            sacc[nn][2] = __expf(sacc[nn][2] - mn1);
            sacc[nn][3] = __expf(sacc[nn][3] - mn1);
            rs0 += sacc[nn][0] + sacc[nn][1];
            rs1 += sacc[nn][2] + sacc[nn][3];
        }
        rs0 += __shfl_xor_sync(0xffffffffu, rs0, 1);
        rs0 += __shfl_xor_sync(0xffffffffu, rs0, 2);
        rs1 += __shfl_xor_sync(0xffffffffu, rs1, 1);
        rs1 += __shfl_xor_sync(0xffffffffu, rs1, 2);
        l0 = l0 * al0 + rs0; l1 = l1 * al1 + rs1;
        m0 = mn0; m1 = mn1;
#pragma unroll
        for (int nn = 0; nn < 16; nn++) {
            oacc[nn][0] *= al0; oacc[nn][1] *= al0;
            oacc[nn][2] *= al1; oacc[nn][3] *= al1;
        }

        const unsigned vst = (unsigned)(st * KB);
#pragma unroll
        for (int kc2 = 0; kc2 < 4; kc2++) {
            unsigned au[4];
            au[0] = packh2(sacc[2 * kc2][0],     sacc[2 * kc2][1]);
            au[1] = packh2(sacc[2 * kc2][2],     sacc[2 * kc2][3]);
            au[2] = packh2(sacc[2 * kc2 + 1][0], sacc[2 * kc2 + 1][1]);
            au[3] = packh2(sacc[2 * kc2 + 1][2], sacc[2 * kc2 + 1][3]);
#pragma unroll
            for (int g = 0; g < 8; g++) {
                unsigned r0, r1, r2, r3;
                LDM4T(r0, r1, r2, r3, vBase0 + vst + kc2 * 4352 + g * 32);
                unsigned b0[2] = {r0, r1}, b1[2] = {r2, r3};
                mma16(oacc[2 * g],     au, b0);
                mma16(oacc[2 * g + 1], au, b1);
            }
        }

        __syncthreads();
        if (t + 2 < nt) loadKV(st, t + 2);
        CPC();
    }

    float inv0 = 1.f / l0, inv1 = 1.f / l1;
#pragma unroll
    for (int nn = 0; nn < 16; nn++) {
        int col = h * 128 + nn * 8 + 2 * l;
        __half2 h0 = __floats2half2_rn(oacc[nn][0] * inv0, oacc[nn][1] * inv0);
        __half2 h1 = __floats2half2_rn(oacc[nn][2] * inv1, oacc[nn][3] * inv1);
        *(__half2*)&O[(size_t)b * 524288 + (size_t)rowg0 * 512 + col] = h0;
        *(__half2*)&O[(size_t)b * 524288 + (size_t)rowg1 * 512 + col] = h1;
    }
}

// ---------------- launch ----------------
static const int SMEM_G128  = 3 * ASTB + 3 * 128 * 144;  // 110592
static const int SMEM_G64   = 3 * ASTB + 3 * 64 * 144;   // 82944
static const int SMEM_FLASH = QB + 4 * KB;               // 104448

extern "C" void kernel_launch(void* const* d_in, const int* in_sizes, int n_in,
                              void* d_out, int out_size) {
    const float* edges = (const float*)d_in[0];
    const float* bbse  = (const float*)d_in[1];
    const void*  gm    = d_in[2];
    const void*  cm    = d_in[3];
    const float* gWq = (const float*)d_in[4];  const float* gbq = (const float*)d_in[5];
    const float* gWk = (const float*)d_in[6];  const float* gbk = (const float*)d_in[7];
    const float* gWv = (const float*)d_in[8];  const float* gbv = (const float*)d_in[9];
    const float* gWo = (const float*)d_in[10]; const float* gbo = (const float*)d_in[11];
    const float* cWq = (const float*)d_in[12]; const float* cbq = (const float*)d_in[13];
    const float* cWk = (const float*)d_in[14]; const float* cbk = (const float*)d_in[15];
    const float* cWv = (const float*)d_in[16]; const float* cbv = (const float*)d_in[17];
    const float* cWo = (const float*)d_in[18]; const float* cbo = (const float*)d_in[19];
    const float* fW1 = (const float*)d_in[20]; const float* fb1 = (const float*)d_in[21];
    const float* fW2 = (const float*)d_in[22]; const float* fb2 = (const float*)d_in[23];
    float* out = (float*)d_out;

    void *Xa, *Qa, *Ka, *AOa, *Sa, *Wa, *Ba;
    unsigned char *m8g, *m8c;
    cudaGetSymbolAddress(&Xa,  g_X);
    cudaGetSymbolAddress(&Qa,  g_Q);
    cudaGetSymbolAddress(&Ka,  g_K);
    cudaGetSymbolAddress(&AOa, g_AO);
    cudaGetSymbolAddress(&Sa,  g_S);
    cudaGetSymbolAddress(&Wa,  g_W16);
    cudaGetSymbolAddress(&Ba,  g_bcat);
    cudaGetSymbolAddress((void**)&m8g, g_m8g);
    cudaGetSymbolAddress((void**)&m8c, g_m8c);
    __half* X16   = (__half*)Xa;
    __half* Q16   = (__half*)Qa;     // cross-Q (16384 x 512)
    __half* KV16  = (__half*)Ka;     // cross-KV (4096 x 1024)
    __half* AO16  = (__half*)AOa;
    __half* QKV16 = (__half*)Sa;     // packed QKV (16384 x 1536); later FFN hidden
    __half* H16   = (__half*)Sa;
    __half* W16   = (__half*)Wa;
    float*  bcat  = (float*)Ba;

    cudaFuncSetAttribute(gemm_fp16_nt<0,0,1,128>, cudaFuncAttributeMaxDynamicSharedMemorySize, SMEM_G128);
    cudaFuncSetAttribute(gemm_fp16_nt<1,0,1,128>, cudaFuncAttributeMaxDynamicSharedMemorySize, SMEM_G128);
    cudaFuncSetAttribute(gemm_fp16_nt<0,0,1,64>,  cudaFuncAttributeMaxDynamicSharedMemorySize, SMEM_G64);
    cudaFuncSetAttribute(gemm_fp16_nt<0,1,0,64>,  cudaFuncAttributeMaxDynamicSharedMemorySize, SMEM_G64);
    cudaFuncSetAttribute(flash_fp16<0>,           cudaFuncAttributeMaxDynamicSharedMemorySize, SMEM_FLASH);
    cudaFuncSetAttribute(flash_fp16<1>,           cudaFuncAttributeMaxDynamicSharedMemorySize, SMEM_FLASH);

    // masks -> canonical uint8; weights/bbse -> fp16; bias concat
    detect_kernel<<<1, 32>>>((const unsigned char*)gm, (const unsigned char*)cm);
    convert_mask_kernel<<<16, 256>>>(gm, m8g, 16384, 0);
    convert_mask_kernel<<<4096, 256>>>(cm, m8c, 4194304, 1);
    convert_w_kernel<<<dim3(64, 24), 256>>>(gWq, gWk, gWv, gWo, cWq, cWk, cWv, cWo,
                                            fW1, fW2, bbse, W16);
    concat_bias_kernel<<<8, 256>>>(gbq, gbk, gbv, cbk, cbv, bcat);

    const __half* B16 = W16 + WO_BB;

    // ---- 1. global edge-edge self-attention ----
    inorm_kernel<<<8192, 256>>>(edges, X16);
    // fused QKV: N=1536 (weights gWq|gWk|gWv contiguous)
    gemm_fp16_nt<0,0,1,128><<<dim3(12, 128), 256, SMEM_G128>>>(
        X16, 512, W16 + WO_GQ, 512, bcat, nullptr, QKV16, 1536, 512);
    flash_fp16<0><<<dim3(8, 64), 256, SMEM_FLASH>>>(
        QKV16, 1536, 1572864, QKV16 + 512, QKV16 + 1024, 1536, 1572864,
        m8g, AO16, 1024);
    gemm_fp16_nt<0,1,0,64><<<dim3(8, 128), 256, SMEM_G64>>>(
        AO16, 512, W16 + WO_GO, 512, gbo, edges, out, 512, 512);

    // ---- 2. cross-attention from bb semantics ----
    inorm_kernel<<<8192, 256>>>(out, X16);
    gemm_fp16_nt<0,0,1,64><<<dim3(8, 128), 256, SMEM_G64>>>(
        X16, 512, W16 + WO_CQ, 512, cbq, nullptr, Q16, 512, 512);
    // fused cross-KV: N=1024 (weights cWk|cWv contiguous), M=4096 bbse tokens
    gemm_fp16_nt<0,0,1,128><<<dim3(8, 32), 256, SMEM_G128>>>(
        B16, 512, W16 + WO_CK, 512, bcat + 2048, nullptr, KV16, 1024, 512);
    flash_fp16<1><<<dim3(8, 64), 256, SMEM_FLASH>>>(
        Q16, 512, 524288, KV16, KV16 + 512, 1024, 262144,
        m8c, AO16, 256);
    gemm_fp16_nt<0,1,0,64><<<dim3(8, 128), 256, SMEM_G64>>>(
        AO16, 512, W16 + WO_CO, 512, cbo, out, out, 512, 512);

    // ---- 3. FFN ----
    inorm_kernel<<<8192, 256>>>(out, X16);
    gemm_fp16_nt<1,0,1,128><<<dim3(16, 128), 256, SMEM_G128>>>(
        X16, 512, W16 + WO_F1, 512, fb1, nullptr, H16, 2048, 512);
    gemm_fp16_nt<0,1,0,64><<<dim3(8, 128), 256, SMEM_G64>>>(
        H16, 2048, W16 + WO_F2, 2048, fb2, out, out, 512, 2048);
}